// round 2
// baseline (speedup 1.0000x reference)
#include <cuda_runtime.h>
#include <math.h>

#define Dd 1024
#define MAXN 1024
#define MAXE 32768

// ---------------- static scratch (single struct, one symbol lookup) ----------------
struct Scratch {
    float X4[MAXN * 4 * Dd];      // [A | B' | C | G] per row, ld=4096
    float Wcat[Dd * 4 * Dd];      // [Wr_s | Wr_o | Ws_v | Wo_v], ld=4096
    float biascat[4 * Dd];        // [0 | b_rel | b_sbj | b_obj]
    float M[Dd * Dd];             // Ws_r @ Wo_r^T
    float Msym[Dd * Dd];          // M + M^T
    float T1[Dd * Dd];            // Wr_r @ M
    float Kq[Dd * Dd];            // Wr_r @ M @ Wr_r^T
    float CW[MAXN * Dd];          // C @ Wo_r^T
    float GW[MAXN * Dd];          // G @ Ws_r^T
    float U1[MAXN * Dd];          // A @ Msym + CW
    float U2[MAXN * Dd];          // B' @ Msym + GW
    float V1[MAXN * Dd];          // U1 @ Wr_r^T
    float V2[MAXN * Dd];          // U2 @ Wr_r^T
    float P[MAXN * MAXN];         // pair scalar matrix
    float S1[MAXN];
    float S2[MAXN];
    float quadP[(size_t)MAXE * 16];
    float logits[MAXE];
    float maxs[MAXN], sums[MAXN], maxo[MAXN], sumo[MAXN];
    float Wmat[MAXN * MAXN];
    float ctx[MAXN * Dd];
    float ctxW[MAXN * Dd];
};
static __device__ Scratch g_s;

// ---------------- generic fp32 SGEMM: C = A@B (+addsrc) (+bias row) -------------
// BM=BN=64, BK=16, 256 threads, 4x4 micro-tile. All dims must be multiples of 64/16.
__global__ __launch_bounds__(256)
void sgemm64(const float* __restrict__ A, int lda,
             const float* __restrict__ B, int ldb,
             float* __restrict__ C, int ldc,
             const float* __restrict__ addsrc,
             const float* __restrict__ bias,
             int K, int transB)
{
    __shared__ float As[16][64];
    __shared__ float Bs[16][64];
    const int tid = threadIdx.x;
    const int tx = tid & 15, ty = tid >> 4;
    const int m0 = blockIdx.y * 64, n0 = blockIdx.x * 64;

    float acc[4][4] = {};

    for (int k0 = 0; k0 < K; k0 += 16) {
        {
            int r  = tid >> 2;
            int kg = (tid & 3) << 2;
            float4 av = *(const float4*)(A + (size_t)(m0 + r) * lda + k0 + kg);
            As[kg + 0][r] = av.x; As[kg + 1][r] = av.y;
            As[kg + 2][r] = av.z; As[kg + 3][r] = av.w;
        }
        if (!transB) {
            int kr = tid >> 4;
            int ng = (tid & 15) << 2;
            *(float4*)&Bs[kr][ng] = *(const float4*)(B + (size_t)(k0 + kr) * ldb + n0 + ng);
        } else {
            int nr = tid >> 2;
            int kg = (tid & 3) << 2;
            float4 bv = *(const float4*)(B + (size_t)(n0 + nr) * ldb + k0 + kg);
            Bs[kg + 0][nr] = bv.x; Bs[kg + 1][nr] = bv.y;
            Bs[kg + 2][nr] = bv.z; Bs[kg + 3][nr] = bv.w;
        }
        __syncthreads();
#pragma unroll
        for (int k = 0; k < 16; k++) {
            float4 a4 = *(float4*)&As[k][ty * 4];
            float4 b4 = *(float4*)&Bs[k][tx * 4];
            float av[4] = {a4.x, a4.y, a4.z, a4.w};
            float bv[4] = {b4.x, b4.y, b4.z, b4.w};
#pragma unroll
            for (int i = 0; i < 4; i++)
#pragma unroll
                for (int j = 0; j < 4; j++)
                    acc[i][j] += av[i] * bv[j];
        }
        __syncthreads();
    }

#pragma unroll
    for (int i = 0; i < 4; i++) {
        int row = m0 + ty * 4 + i;
        float4 v = make_float4(acc[i][0], acc[i][1], acc[i][2], acc[i][3]);
        if (addsrc) {
            float4 s = *(const float4*)(addsrc + (size_t)row * ldc + n0 + tx * 4);
            v.x += s.x; v.y += s.y; v.z += s.z; v.w += s.w;
        }
        if (bias) {
            float4 b = *(const float4*)(bias + n0 + tx * 4);
            v.x += b.x; v.y += b.y; v.z += b.z; v.w += b.w;
        }
        *(float4*)(C + (size_t)row * ldc + n0 + tx * 4) = v;
    }
}

// ---------------- fused quad kernel: per edge partials of x·(x@Kq + V1[s] + V2[o]) ----
__global__ __launch_bounds__(256)
void quadk(const float* __restrict__ X, const float* __restrict__ Kq,
           const float* __restrict__ V1, const float* __restrict__ V2,
           const int* __restrict__ sbj, const int* __restrict__ obj,
           float* __restrict__ quadP, int E)
{
    __shared__ float As[16][64];
    __shared__ float Bs[16][64];
    const int tid = threadIdx.x;
    const int tx = tid & 15, ty = tid >> 4;
    const int m0 = blockIdx.y * 64;   // edge rows
    const int n0 = blockIdx.x * 64;   // feature cols

    float acc[4][4] = {};

    for (int k0 = 0; k0 < Dd; k0 += 16) {
        {
            int r  = tid >> 2;
            int kg = (tid & 3) << 2;
            int rr = m0 + r; if (rr >= E) rr = E - 1;
            float4 av = *(const float4*)(X + (size_t)rr * Dd + k0 + kg);
            As[kg + 0][r] = av.x; As[kg + 1][r] = av.y;
            As[kg + 2][r] = av.z; As[kg + 3][r] = av.w;
        }
        {
            int kr = tid >> 4;
            int ng = (tid & 15) << 2;
            *(float4*)&Bs[kr][ng] = *(const float4*)(Kq + (size_t)(k0 + kr) * Dd + n0 + ng);
        }
        __syncthreads();
#pragma unroll
        for (int k = 0; k < 16; k++) {
            float4 a4 = *(float4*)&As[k][ty * 4];
            float4 b4 = *(float4*)&Bs[k][tx * 4];
            float av[4] = {a4.x, a4.y, a4.z, a4.w};
            float bv[4] = {b4.x, b4.y, b4.z, b4.w};
#pragma unroll
            for (int i = 0; i < 4; i++)
#pragma unroll
                for (int j = 0; j < 4; j++)
                    acc[i][j] += av[i] * bv[j];
        }
        __syncthreads();
    }

    // epilogue: p_row = sum_cols (Y + V1[s] + V2[o]) * x, reduced over the 16 tx lanes
#pragma unroll
    for (int i = 0; i < 4; i++) {
        int r = m0 + ty * 4 + i;
        int rr = (r < E) ? r : (E - 1);
        int s = sbj[rr], o = obj[rr];
        float4 xv = *(const float4*)(X  + (size_t)rr * Dd + n0 + tx * 4);
        float4 a1 = *(const float4*)(V1 + (size_t)s  * Dd + n0 + tx * 4);
        float4 a2 = *(const float4*)(V2 + (size_t)o  * Dd + n0 + tx * 4);
        float p = (acc[i][0] + a1.x + a2.x) * xv.x
                + (acc[i][1] + a1.y + a2.y) * xv.y
                + (acc[i][2] + a1.z + a2.z) * xv.z
                + (acc[i][3] + a1.w + a2.w) * xv.w;
        p += __shfl_xor_sync(0xffffffffu, p, 1);
        p += __shfl_xor_sync(0xffffffffu, p, 2);
        p += __shfl_xor_sync(0xffffffffu, p, 4);
        p += __shfl_xor_sync(0xffffffffu, p, 8);
        if (tx == 0 && r < E) quadP[(size_t)r * 16 + blockIdx.x] = p;
    }
}

// ---------------- small helper kernels ----------------
__global__ void buildcat(const float* __restrict__ Wrel, const float* __restrict__ Wsbj,
                         const float* __restrict__ Wobj, const float* __restrict__ brel,
                         const float* __restrict__ bsbj, const float* __restrict__ bobj)
{
    int idx = blockIdx.x * 256 + threadIdx.x;
    if (idx < Dd * 4 * Dd) {
        int k = idx >> 12;
        int rem = idx & 4095;
        int c = rem >> 10;
        int n = rem & 1023;
        float v;
        if (c == 0)      v = Wrel[k * Dd + n];
        else if (c == 1) v = Wrel[Dd * Dd + k * Dd + n];
        else if (c == 2) v = Wsbj[k * Dd + n];
        else             v = Wobj[k * Dd + n];
        g_s.Wcat[idx] = v;
    }
    if (idx < 4 * Dd) {
        int c = idx >> 10, n = idx & 1023;
        g_s.biascat[idx] = (c == 0) ? 0.f : (c == 1 ? brel[n] : (c == 2 ? bsbj[n] : bobj[n]));
    }
}

__global__ void msymk()
{
    int idx = blockIdx.x * 256 + threadIdx.x;
    if (idx < Dd * Dd) {
        int i = idx >> 10, j = idx & 1023;
        g_s.Msym[idx] = g_s.M[idx] + g_s.M[j * Dd + i];
    }
}

__global__ void zerok(float* p, int n)
{
    int i = blockIdx.x * 256 + threadIdx.x;
    if (i < n) p[i] = 0.f;
}

__global__ void copyk(const float* __restrict__ src, float* __restrict__ dst, long long n4)
{
    long long i = (long long)blockIdx.x * blockDim.x + threadIdx.x;
    if (i < n4) ((float4*)dst)[i] = ((const float4*)src)[i];
}

// S1[n] = 0.5*(rowdot(A,U1)+rowdot(A,CW)); S2[n] = 0.5*(rowdot(B',U2)+rowdot(B',GW))
__global__ void rowdots(float* __restrict__ S1, float* __restrict__ S2)
{
    int n = blockIdx.x, tid = threadIdx.x;
    const float* a  = g_s.X4 + (size_t)n * 4096;
    const float* bp = a + 1024;
    float s1 = 0.f, s2 = 0.f;
    for (int d = tid; d < Dd; d += 256) {
        s1 += a[d]  * (g_s.U1[(size_t)n * Dd + d] + g_s.CW[(size_t)n * Dd + d]);
        s2 += bp[d] * (g_s.U2[(size_t)n * Dd + d] + g_s.GW[(size_t)n * Dd + d]);
    }
    __shared__ float r1[256], r2[256];
    r1[tid] = s1; r2[tid] = s2; __syncthreads();
    for (int st = 128; st > 0; st >>= 1) {
        if (tid < st) { r1[tid] += r1[tid + st]; r2[tid] += r2[tid + st]; }
        __syncthreads();
    }
    if (tid == 0) { S1[n] = 0.5f * r1[0]; S2[n] = 0.5f * r2[0]; }
}

__global__ void logitsk(const int* __restrict__ sbj, const int* __restrict__ obj,
                        int E, int Nn, float scale)
{
    int e = blockIdx.x * 256 + threadIdx.x;
    if (e >= E) return;
    float q = 0.f;
#pragma unroll
    for (int t = 0; t < 16; t++) q += g_s.quadP[(size_t)e * 16 + t];
    int s = sbj[e], o = obj[e];
    g_s.logits[e] = (q + g_s.P[(size_t)s * Nn + o] + g_s.S1[s] + g_s.S2[o]) * scale;
}

// deterministic segment softmax statistics for BOTH segmentations.
// one block per node; blockIdx.y selects sbj (0) or obj (1) indexing.
__global__ void segstats(const int* __restrict__ sbj, const int* __restrict__ obj,
                         int E)
{
    int n = blockIdx.x, tid = threadIdx.x;
    const int* ind = (blockIdx.y == 0) ? sbj : obj;
    __shared__ float red[256];
    float m = -1e30f;
    for (int e = tid; e < E; e += 256)
        if (ind[e] == n) m = fmaxf(m, g_s.logits[e]);
    red[tid] = m; __syncthreads();
    for (int st = 128; st > 0; st >>= 1) {
        if (tid < st) red[tid] = fmaxf(red[tid], red[tid + st]);
        __syncthreads();
    }
    float Mv = red[0]; __syncthreads();
    float s = 0.f;
    for (int e = tid; e < E; e += 256)
        if (ind[e] == n) s += expf(g_s.logits[e] - Mv);
    red[tid] = s; __syncthreads();
    for (int st = 128; st > 0; st >>= 1) {
        if (tid < st) red[tid] += red[tid + st];
        __syncthreads();
    }
    if (tid == 0) {
        if (blockIdx.y == 0) { g_s.maxs[n] = Mv; g_s.sums[n] = red[0]; }
        else                 { g_s.maxo[n] = Mv; g_s.sumo[n] = red[0]; }
    }
}

// scatter softmax weights into dense N x N mixing matrix (<=2 commutative adds per cell)
__global__ void wmatk(const int* __restrict__ sbj, const int* __restrict__ obj,
                      int E, int Nn)
{
    int e = blockIdx.x * 256 + threadIdx.x;
    if (e >= E) return;
    float l = g_s.logits[e];
    int s = sbj[e], o = obj[e];
    float ws = expf(l - g_s.maxs[s]) / g_s.sums[s];
    float wo = expf(l - g_s.maxo[o]) / g_s.sumo[o];
    atomicAdd(&g_s.Wmat[(size_t)s * Nn + o], ws);
    atomicAdd(&g_s.Wmat[(size_t)o * Nn + s], wo);
}

__global__ void finalk(const float* __restrict__ vf, float* __restrict__ out, int total)
{
    int idx = blockIdx.x * 256 + threadIdx.x;
    if (idx >= total) return;
    int n = idx >> 10;
    bool inv = (g_s.sums[n] > 0.f) || (g_s.sumo[n] > 0.f);
    out[idx] = vf[idx] + (inv ? g_s.ctxW[idx] : 0.f);
}

// ---------------- host orchestration ----------------
extern "C" void kernel_launch(void* const* d_in, const int* in_sizes, int n_in,
                              void* d_out, int out_size)
{
    const float* vf   = (const float*)d_in[0];
    const float* rvf  = (const float*)d_in[1];
    const float* Wrel = (const float*)d_in[2];
    const float* brel = (const float*)d_in[3];
    const float* Wsbj = (const float*)d_in[4];
    const float* bsbj = (const float*)d_in[5];
    const float* Wobj = (const float*)d_in[6];
    const float* bobj = (const float*)d_in[7];
    const float* Wctx = (const float*)d_in[8];
    const float* bctx = (const float*)d_in[9];
    const int*   sbj  = (const int*)d_in[10];
    const int*   obj  = (const int*)d_in[11];

    const int Nn = in_sizes[0] / Dd;    // 768
    const int E  = in_sizes[10];        // 24576
    float* out = (float*)d_out;

    Scratch* S = nullptr;
    cudaGetSymbolAddress((void**)&S, g_s);
    float* pX4   = S->X4;    float* pWcat = S->Wcat;  float* pbias = S->biascat;
    float* pM    = S->M;     float* pMsym = S->Msym;  float* pT1   = S->T1;
    float* pKq   = S->Kq;    float* pCW   = S->CW;    float* pGW   = S->GW;
    float* pU1   = S->U1;    float* pU2   = S->U2;    float* pV1   = S->V1;
    float* pV2   = S->V2;    float* pP    = S->P;     float* pS1   = S->S1;
    float* pS2   = S->S2;    float* pquad = S->quadP; float* pWmat = S->Wmat;
    float* pctx  = S->ctx;   float* pctxW = S->ctxW;

    const float* Wr_r = Wrel + 2 * Dd * Dd;
    const float* Ws_r = Wsbj + Dd * Dd;
    const float* Wo_r = Wobj + Dd * Dd;

    // 1. passthrough copy of rel_visual_feat into output
    long long n4 = (long long)E * Dd / 4;
    copyk<<<(unsigned)((n4 + 255) / 256), 256>>>(rvf, out, n4);

    // 2. concat weights + biases; zero Wmat
    buildcat<<<(Dd * 4 * Dd + 255) / 256, 256>>>(Wrel, Wsbj, Wobj, brel, bsbj, bobj);
    zerok<<<(Nn * Nn + 255) / 256, 256>>>(pWmat, Nn * Nn);

    // 3. X4 = vf @ [Wr_s|Wr_o|Ws_v|Wo_v] + [0|b_rel|b_sbj|b_obj]  -> A,B',C,G
    dim3 g1(4096 / 64, Nn / 64);
    sgemm64<<<g1, 256>>>(vf, Dd, pWcat, 4096, pX4, 4096, nullptr, pbias, Dd, 0);

    // 4-7. weight-space chain: M, Msym, T1, Kq
    dim3 gD(Dd / 64, Dd / 64);
    sgemm64<<<gD, 256>>>(Ws_r, Dd, Wo_r, Dd, pM, Dd, nullptr, nullptr, Dd, 1);
    msymk<<<(Dd * Dd + 255) / 256, 256>>>();
    sgemm64<<<gD, 256>>>(Wr_r, Dd, pM, Dd, pT1, Dd, nullptr, nullptr, Dd, 0);
    sgemm64<<<gD, 256>>>(pT1, Dd, Wr_r, Dd, pKq, Dd, nullptr, nullptr, Dd, 1);

    // 8-13. node matrices
    dim3 gN(Dd / 64, Nn / 64);
    sgemm64<<<gN, 256>>>(pX4 + 2048, 4096, Wo_r, Dd, pCW, Dd, nullptr, nullptr, Dd, 1); // CW = C@Wo_r^T
    sgemm64<<<gN, 256>>>(pX4 + 3072, 4096, Ws_r, Dd, pGW, Dd, nullptr, nullptr, Dd, 1); // GW = G@Ws_r^T
    sgemm64<<<gN, 256>>>(pX4,        4096, pMsym, Dd, pU1, Dd, pCW, nullptr, Dd, 0);    // U1 = A@Msym+CW
    sgemm64<<<gN, 256>>>(pX4 + 1024, 4096, pMsym, Dd, pU2, Dd, pGW, nullptr, Dd, 0);    // U2 = B'@Msym+GW
    sgemm64<<<gN, 256>>>(pU1, Dd, Wr_r, Dd, pV1, Dd, nullptr, nullptr, Dd, 1);          // V1 = U1@Wr_r^T
    sgemm64<<<gN, 256>>>(pU2, Dd, Wr_r, Dd, pV2, Dd, nullptr, nullptr, Dd, 1);          // V2 = U2@Wr_r^T

    // 14-16. pair matrix P = C@G^T + U1@B'^T + A@GW^T
    dim3 gP(Nn / 64, Nn / 64);
    sgemm64<<<gP, 256>>>(pX4 + 2048, 4096, pX4 + 3072, 4096, pP, Nn, nullptr, nullptr, Dd, 1);
    sgemm64<<<gP, 256>>>(pU1, Dd, pX4 + 1024, 4096, pP, Nn, pP, nullptr, Dd, 1);
    sgemm64<<<gP, 256>>>(pX4, 4096, pGW, Dd, pP, Nn, pP, nullptr, Dd, 1);

    // 17. node scalars
    rowdots<<<Nn, 256>>>(pS1, pS2);

    // 18. big fused quadratic-form kernel over edges (the only E x D^2 GEMM)
    dim3 gQ(Dd / 64, (E + 63) / 64);
    quadk<<<gQ, 256>>>(rvf, pKq, pV1, pV2, sbj, obj, pquad, E);

    // 19. assemble logits
    logitsk<<<(E + 255) / 256, 256>>>(sbj, obj, E, Nn, 1.0f / sqrtf((float)Dd));

    // 20. deterministic segment softmax stats (sbj and obj in one launch)
    dim3 gS(Nn, 2);
    segstats<<<gS, 256>>>(sbj, obj, E);

    // 21. dense mixing matrix from softmax weights
    wmatk<<<(E + 255) / 256, 256>>>(sbj, obj, E, Nn);

    // 22-23. ctx = Wmat @ vf ; ctxW = ctx @ W_ctx + b_ctx
    dim3 gc(Dd / 64, Nn / 64);
    sgemm64<<<gc, 256>>>(pWmat, Nn, vf, Dd, pctx, Dd, nullptr, nullptr, Nn, 0);
    sgemm64<<<gc, 256>>>(pctx, Dd, Wctx, Dd, pctxW, Dd, nullptr, bctx, Dd, 0);

    // 24. final update into output (involved == node has edges)
    finalk<<<(Nn * Dd + 255) / 256, 256>>>(vf, out + (size_t)E * Dd, Nn * Dd);
}

// round 3
// speedup vs baseline: 1.3586x; 1.3586x over previous
#include <cuda_runtime.h>
#include <cuda_bf16.h>
#include <math.h>
#include <stdint.h>

#define Dd 1024
#define MAXN 1024
#define MAXE 32768

// ---------------- static scratch (no runtime allocation allowed) ----------------
struct Scratch {
    float X4[MAXN * 4 * Dd];      // [A | B' | C | G] per row, ld=4096
    float Wcat[Dd * 4 * Dd];      // [Wr_s | Wr_o | Ws_v | Wo_v], ld=4096
    float biascat[4 * Dd];        // [0 | b_rel | b_sbj | b_obj]
    float M[Dd * Dd];             // Ws_r @ Wo_r^T
    float Msym[Dd * Dd];          // M + M^T
    float T1[Dd * Dd];            // Wr_r @ M
    float Kq[Dd * Dd];            // Wr_r @ M @ Wr_r^T
    float CW[MAXN * Dd];          // C @ Wo_r^T
    float GW[MAXN * Dd];          // G @ Ws_r^T
    float U1[MAXN * Dd];          // A @ Msym + CW
    float U2[MAXN * Dd];          // B' @ Msym + GW
    float V1[MAXN * Dd];          // U1 @ Wr_r^T
    float V2[MAXN * Dd];          // U2 @ Wr_r^T
    float P[MAXN * MAXN];         // pair scalar matrix
    float S1[MAXN];
    float S2[MAXN];
    float logits[MAXE];
    float maxs[MAXN], sums[MAXN], maxo[MAXN], sumo[MAXN];
    float Wmat[MAXN * MAXN];
    float ctx[MAXN * Dd];
    float ctxW[MAXN * Dd];
};
static __device__ Scratch g_s;
static __device__ float g_Y[(size_t)MAXE * Dd];   // rvf @ Kq

// ---------------- PTX helpers ----------------
__device__ __forceinline__ uint32_t smem_u32(const void* p) {
    return (uint32_t)__cvta_generic_to_shared(p);
}
__device__ __forceinline__ void ldsm4(uint32_t& r0, uint32_t& r1, uint32_t& r2, uint32_t& r3, uint32_t a) {
    asm volatile("ldmatrix.sync.aligned.m8n8.x4.shared.b16 {%0,%1,%2,%3}, [%4];"
                 : "=r"(r0), "=r"(r1), "=r"(r2), "=r"(r3) : "r"(a));
}
__device__ __forceinline__ void ldsm2(uint32_t& r0, uint32_t& r1, uint32_t a) {
    asm volatile("ldmatrix.sync.aligned.m8n8.x2.shared.b16 {%0,%1}, [%2];"
                 : "=r"(r0), "=r"(r1) : "r"(a));
}
__device__ __forceinline__ void ldsm2t(uint32_t& r0, uint32_t& r1, uint32_t a) {
    asm volatile("ldmatrix.sync.aligned.m8n8.x2.trans.shared.b16 {%0,%1}, [%2];"
                 : "=r"(r0), "=r"(r1) : "r"(a));
}
__device__ __forceinline__ void mma16816(float* d, const uint32_t* a, const uint32_t* b) {
    asm volatile("mma.sync.aligned.m16n8k16.row.col.f32.bf16.bf16.f32 "
                 "{%0,%1,%2,%3}, {%4,%5,%6,%7}, {%8,%9}, {%0,%1,%2,%3};"
                 : "+f"(d[0]), "+f"(d[1]), "+f"(d[2]), "+f"(d[3])
                 : "r"(a[0]), "r"(a[1]), "r"(a[2]), "r"(a[3]), "r"(b[0]), "r"(b[1]));
}

// ---------------- split-bf16 tensor-core GEMM ----------------
// C[M,N] = A[M,K] @ op(B) (+addsrc) (+bias row), fp32 in/out.
// Split: x = hi + lo (both bf16); a*b ~= ah*bh + ah*bl + al*bh  (~2^-17 input precision).
// Tiles: BM=BN=128, BK=32. 256 threads = 8 warps (2 along M x 4 along N), warp tile 64x32.
// Requires M%128==0, N%128==0, K%32==0.
#define APITCH 48    // [128][48] bf16 rows (96B, 16B-aligned)
#define BPITCH 136   // transB=0 layout [32][136] bf16 (272B rows)
__global__ __launch_bounds__(256, 1)
void mgemm(const float* __restrict__ A, int lda,
           const float* __restrict__ B, int ldb,
           float* __restrict__ C, int ldc,
           const float* __restrict__ addsrc,
           const float* __restrict__ bias,
           int K, int transB)
{
    __shared__ __nv_bfloat16 Ah[128 * APITCH], Al[128 * APITCH];
    __shared__ __nv_bfloat16 Bh[128 * APITCH], Bl[128 * APITCH];  // reused as [32][BPITCH] when transB==0

    const int tid = threadIdx.x;
    const int lane = tid & 31, wid = tid >> 5;
    const int wm = wid & 1, wn = wid >> 1;          // warp grid 2 x 4
    const int m0 = blockIdx.y * 128, n0 = blockIdx.x * 128;
    const int l8 = lane & 7, grp = lane >> 3;
    const bool tb = (transB != 0);

    float acc[4][4][4] = {};

    for (int k0 = 0; k0 < K; k0 += 32) {
        // ---- load A tile (128x32 fp32), split to hi/lo bf16 ----
#pragma unroll
        for (int i = 0; i < 4; i++) {
            int linear = tid + i * 256;
            int r = linear >> 3, c4 = (linear & 7) << 2;
            float4 v = *(const float4*)(A + (size_t)(m0 + r) * lda + k0 + c4);
            float f[4] = {v.x, v.y, v.z, v.w};
#pragma unroll
            for (int j = 0; j < 4; j++) {
                __nv_bfloat16 h = __float2bfloat16(f[j]);
                Ah[r * APITCH + c4 + j] = h;
                Al[r * APITCH + c4 + j] = __float2bfloat16(f[j] - __bfloat162float(h));
            }
        }
        // ---- load B tile ----
        if (tb) {  // B is [N][K] row-major -> smem [n][k], pitch APITCH
#pragma unroll
            for (int i = 0; i < 4; i++) {
                int linear = tid + i * 256;
                int r = linear >> 3, c4 = (linear & 7) << 2;
                float4 v = *(const float4*)(B + (size_t)(n0 + r) * ldb + k0 + c4);
                float f[4] = {v.x, v.y, v.z, v.w};
#pragma unroll
                for (int j = 0; j < 4; j++) {
                    __nv_bfloat16 h = __float2bfloat16(f[j]);
                    Bh[r * APITCH + c4 + j] = h;
                    Bl[r * APITCH + c4 + j] = __float2bfloat16(f[j] - __bfloat162float(h));
                }
            }
        } else {   // B is [K][N] row-major -> smem [k][n], pitch BPITCH (read via ldmatrix.trans)
#pragma unroll
            for (int i = 0; i < 4; i++) {
                int linear = tid + i * 256;
                int kr = linear >> 5, c4 = (linear & 31) << 2;
                float4 v = *(const float4*)(B + (size_t)(k0 + kr) * ldb + n0 + c4);
                float f[4] = {v.x, v.y, v.z, v.w};
#pragma unroll
                for (int j = 0; j < 4; j++) {
                    __nv_bfloat16 h = __float2bfloat16(f[j]);
                    Bh[kr * BPITCH + c4 + j] = h;
                    Bl[kr * BPITCH + c4 + j] = __float2bfloat16(f[j] - __bfloat162float(h));
                }
            }
        }
        __syncthreads();

        // ---- compute: 2 k-steps of 16 ----
#pragma unroll
        for (int kk = 0; kk < 2; kk++) {
            const int kcol = kk * 16;
            uint32_t ah[4][4], al[4][4], bh[4][2], bl[4][2];
#pragma unroll
            for (int mt = 0; mt < 4; mt++) {
                int row = wm * 64 + mt * 16 + l8 + ((grp & 1) << 3);
                int col = kcol + ((grp >> 1) << 3);
                ldsm4(ah[mt][0], ah[mt][1], ah[mt][2], ah[mt][3], smem_u32(&Ah[row * APITCH + col]));
                ldsm4(al[mt][0], al[mt][1], al[mt][2], al[mt][3], smem_u32(&Al[row * APITCH + col]));
            }
            if (tb) {
#pragma unroll
                for (int nt = 0; nt < 4; nt++) {
                    int row = wn * 32 + nt * 8 + l8;
                    int col = kcol + ((grp & 1) << 3);
                    ldsm2(bh[nt][0], bh[nt][1], smem_u32(&Bh[row * APITCH + col]));
                    ldsm2(bl[nt][0], bl[nt][1], smem_u32(&Bl[row * APITCH + col]));
                }
            } else {
#pragma unroll
                for (int nt = 0; nt < 4; nt++) {
                    int ncol = wn * 32 + nt * 8;
                    int krow = kcol + l8 + ((grp & 1) << 3);
                    ldsm2t(bh[nt][0], bh[nt][1], smem_u32(&Bh[krow * BPITCH + ncol]));
                    ldsm2t(bl[nt][0], bl[nt][1], smem_u32(&Bl[krow * BPITCH + ncol]));
                }
            }
#pragma unroll
            for (int mt = 0; mt < 4; mt++)
#pragma unroll
                for (int nt = 0; nt < 4; nt++) {
                    mma16816(acc[mt][nt], ah[mt], bh[nt]);
                    mma16816(acc[mt][nt], ah[mt], bl[nt]);
                    mma16816(acc[mt][nt], al[mt], bh[nt]);
                }
        }
        __syncthreads();
    }

    // ---- epilogue ----
#pragma unroll
    for (int mt = 0; mt < 4; mt++)
#pragma unroll
        for (int nt = 0; nt < 4; nt++) {
            int m = m0 + wm * 64 + mt * 16 + (lane >> 2);
            int n = n0 + wn * 32 + nt * 8 + (lane & 3) * 2;
            float2 v0 = make_float2(acc[mt][nt][0], acc[mt][nt][1]);
            float2 v1 = make_float2(acc[mt][nt][2], acc[mt][nt][3]);
            if (addsrc) {
                float2 s0 = *(const float2*)(addsrc + (size_t)m * ldc + n);
                float2 s1 = *(const float2*)(addsrc + (size_t)(m + 8) * ldc + n);
                v0.x += s0.x; v0.y += s0.y; v1.x += s1.x; v1.y += s1.y;
            }
            if (bias) {
                float2 b = *(const float2*)(bias + n);
                v0.x += b.x; v0.y += b.y; v1.x += b.x; v1.y += b.y;
            }
            *(float2*)(C + (size_t)m * ldc + n) = v0;
            *(float2*)(C + (size_t)(m + 8) * ldc + n) = v1;
        }
}

// ---------------- small helper kernels (unchanged from passing round) ----------------
__global__ void buildcat(const float* __restrict__ Wrel, const float* __restrict__ Wsbj,
                         const float* __restrict__ Wobj, const float* __restrict__ brel,
                         const float* __restrict__ bsbj, const float* __restrict__ bobj)
{
    int idx = blockIdx.x * 256 + threadIdx.x;
    if (idx < Dd * 4 * Dd) {
        int k = idx >> 12;
        int rem = idx & 4095;
        int c = rem >> 10;
        int n = rem & 1023;
        float v;
        if (c == 0)      v = Wrel[k * Dd + n];
        else if (c == 1) v = Wrel[Dd * Dd + k * Dd + n];
        else if (c == 2) v = Wsbj[k * Dd + n];
        else             v = Wobj[k * Dd + n];
        g_s.Wcat[idx] = v;
    }
    if (idx < 4 * Dd) {
        int c = idx >> 10, n = idx & 1023;
        g_s.biascat[idx] = (c == 0) ? 0.f : (c == 1 ? brel[n] : (c == 2 ? bsbj[n] : bobj[n]));
    }
}

__global__ void msymk()
{
    int idx = blockIdx.x * 256 + threadIdx.x;
    if (idx < Dd * Dd) {
        int i = idx >> 10, j = idx & 1023;
        g_s.Msym[idx] = g_s.M[idx] + g_s.M[j * Dd + i];
    }
}

__global__ void zerok(float* p, int n)
{
    int i = blockIdx.x * 256 + threadIdx.x;
    if (i < n) p[i] = 0.f;
}

__global__ void copyk(const float* __restrict__ src, float* __restrict__ dst, long long n4)
{
    long long i = (long long)blockIdx.x * blockDim.x + threadIdx.x;
    if (i < n4) ((float4*)dst)[i] = ((const float4*)src)[i];
}

// S1[n] = 0.5*(rowdot(A,U1)+rowdot(A,CW)); S2[n] = 0.5*(rowdot(B',U2)+rowdot(B',GW))
__global__ void rowdots(float* __restrict__ S1, float* __restrict__ S2)
{
    int n = blockIdx.x, tid = threadIdx.x;
    const float* a  = g_s.X4 + (size_t)n * 4096;
    const float* bp = a + 1024;
    float s1 = 0.f, s2 = 0.f;
    for (int d = tid; d < Dd; d += 256) {
        s1 += a[d]  * (g_s.U1[(size_t)n * Dd + d] + g_s.CW[(size_t)n * Dd + d]);
        s2 += bp[d] * (g_s.U2[(size_t)n * Dd + d] + g_s.GW[(size_t)n * Dd + d]);
    }
    __shared__ float r1[256], r2[256];
    r1[tid] = s1; r2[tid] = s2; __syncthreads();
    for (int st = 128; st > 0; st >>= 1) {
        if (tid < st) { r1[tid] += r1[tid + st]; r2[tid] += r2[tid + st]; }
        __syncthreads();
    }
    if (tid == 0) { S1[n] = 0.5f * r1[0]; S2[n] = 0.5f * r2[0]; }
}

// fused quad reduce + logits: logits[e] = (sum_d (Y[e]+V1[s]+V2[o])*x[e] + P[s,o] + S1[s] + S2[o]) * scale
__global__ __launch_bounds__(256)
void qreduce(const float* __restrict__ X, const int* __restrict__ sbj,
             const int* __restrict__ obj, const float* __restrict__ Y,
             int Nn, float scale)
{
    int e = blockIdx.x, tid = threadIdx.x;
    int s = sbj[e], o = obj[e];
    const float4* x  = (const float4*)(X + (size_t)e * Dd);
    const float4* y  = (const float4*)(Y + (size_t)e * Dd);
    const float4* v1 = (const float4*)(g_s.V1 + (size_t)s * Dd);
    const float4* v2 = (const float4*)(g_s.V2 + (size_t)o * Dd);
    float4 xv = x[tid], yv = y[tid], a = v1[tid], b = v2[tid];
    float acc = (yv.x + a.x + b.x) * xv.x + (yv.y + a.y + b.y) * xv.y
              + (yv.z + a.z + b.z) * xv.z + (yv.w + a.w + b.w) * xv.w;
    acc += __shfl_xor_sync(0xffffffffu, acc, 16);
    acc += __shfl_xor_sync(0xffffffffu, acc, 8);
    acc += __shfl_xor_sync(0xffffffffu, acc, 4);
    acc += __shfl_xor_sync(0xffffffffu, acc, 2);
    acc += __shfl_xor_sync(0xffffffffu, acc, 1);
    __shared__ float red[8];
    if ((tid & 31) == 0) red[tid >> 5] = acc;
    __syncthreads();
    if (tid == 0) {
        float t = 0.f;
#pragma unroll
        for (int i = 0; i < 8; i++) t += red[i];
        g_s.logits[e] = (t + g_s.P[(size_t)s * Nn + o] + g_s.S1[s] + g_s.S2[o]) * scale;
    }
}

// deterministic segment softmax statistics for BOTH segmentations.
__global__ void segstats(const int* __restrict__ sbj, const int* __restrict__ obj, int E)
{
    int n = blockIdx.x, tid = threadIdx.x;
    const int* ind = (blockIdx.y == 0) ? sbj : obj;
    __shared__ float red[256];
    float m = -1e30f;
    for (int e = tid; e < E; e += 256)
        if (ind[e] == n) m = fmaxf(m, g_s.logits[e]);
    red[tid] = m; __syncthreads();
    for (int st = 128; st > 0; st >>= 1) {
        if (tid < st) red[tid] = fmaxf(red[tid], red[tid + st]);
        __syncthreads();
    }
    float Mv = red[0]; __syncthreads();
    float s = 0.f;
    for (int e = tid; e < E; e += 256)
        if (ind[e] == n) s += expf(g_s.logits[e] - Mv);
    red[tid] = s; __syncthreads();
    for (int st = 128; st > 0; st >>= 1) {
        if (tid < st) red[tid] += red[tid + st];
        __syncthreads();
    }
    if (tid == 0) {
        if (blockIdx.y == 0) { g_s.maxs[n] = Mv; g_s.sums[n] = red[0]; }
        else                 { g_s.maxo[n] = Mv; g_s.sumo[n] = red[0]; }
    }
}

// scatter softmax weights into dense N x N mixing matrix (<=2 commutative adds per cell)
__global__ void wmatk(const int* __restrict__ sbj, const int* __restrict__ obj,
                      int E, int Nn)
{
    int e = blockIdx.x * 256 + threadIdx.x;
    if (e >= E) return;
    float l = g_s.logits[e];
    int s = sbj[e], o = obj[e];
    float ws = expf(l - g_s.maxs[s]) / g_s.sums[s];
    float wo = expf(l - g_s.maxo[o]) / g_s.sumo[o];
    atomicAdd(&g_s.Wmat[(size_t)s * Nn + o], ws);
    atomicAdd(&g_s.Wmat[(size_t)o * Nn + s], wo);
}

__global__ void finalk(const float* __restrict__ vf, float* __restrict__ out, int total)
{
    int idx = blockIdx.x * 256 + threadIdx.x;
    if (idx >= total) return;
    int n = idx >> 10;
    bool inv = (g_s.sums[n] > 0.f) || (g_s.sumo[n] > 0.f);
    out[idx] = vf[idx] + (inv ? g_s.ctxW[idx] : 0.f);
}

// ---------------- host orchestration ----------------
extern "C" void kernel_launch(void* const* d_in, const int* in_sizes, int n_in,
                              void* d_out, int out_size)
{
    const float* vf   = (const float*)d_in[0];
    const float* rvf  = (const float*)d_in[1];
    const float* Wrel = (const float*)d_in[2];
    const float* Wsbj = (const float*)d_in[4];
    const float* Wobj = (const float*)d_in[6];
    const float* Wctx = (const float*)d_in[8];
    const float* bctx = (const float*)d_in[9];
    const int*   sbj  = (const int*)d_in[10];
    const int*   obj  = (const int*)d_in[11];
    const float* brel = (const float*)d_in[3];
    const float* bsbj = (const float*)d_in[5];
    const float* bobj = (const float*)d_in[7];

    const int Nn = in_sizes[0] / Dd;    // 768
    const int E  = in_sizes[10];        // 24576
    float* out = (float*)d_out;

    Scratch* S = nullptr;
    cudaGetSymbolAddress((void**)&S, g_s);
    float* pY = nullptr;
    cudaGetSymbolAddress((void**)&pY, g_Y);

    float* pX4   = S->X4;    float* pWcat = S->Wcat;  float* pbias = S->biascat;
    float* pM    = S->M;     float* pMsym = S->Msym;  float* pT1   = S->T1;
    float* pKq   = S->Kq;    float* pCW   = S->CW;    float* pGW   = S->GW;
    float* pU1   = S->U1;    float* pU2   = S->U2;    float* pV1   = S->V1;
    float* pV2   = S->V2;    float* pP    = S->P;     float* pS1   = S->S1;
    float* pS2   = S->S2;    float* pWmat = S->Wmat;
    float* pctx  = S->ctx;   float* pctxW = S->ctxW;

    const float* Wr_r = Wrel + 2 * Dd * Dd;
    const float* Ws_r = Wsbj + Dd * Dd;
    const float* Wo_r = Wobj + Dd * Dd;

    // 1. passthrough copy of rel_visual_feat into output
    long long n4 = (long long)E * Dd / 4;
    copyk<<<(unsigned)((n4 + 255) / 256), 256>>>(rvf, out, n4);

    // 2. concat weights + biases; zero Wmat
    buildcat<<<(Dd * 4 * Dd + 255) / 256, 256>>>(Wrel, Wsbj, Wobj, brel, bsbj, bobj);
    zerok<<<(Nn * Nn + 255) / 256, 256>>>(pWmat, Nn * Nn);

    // 3. X4 = vf @ [Wr_s|Wr_o|Ws_v|Wo_v] + [0|b_rel|b_sbj|b_obj]
    mgemm<<<dim3(4096 / 128, Nn / 128), 256>>>(vf, Dd, pWcat, 4096, pX4, 4096,
                                               nullptr, pbias, Dd, 0);

    // 4-7. weight-space chain: M, Msym, T1, Kq
    dim3 gD(Dd / 128, Dd / 128);
    mgemm<<<gD, 256>>>(Ws_r, Dd, Wo_r, Dd, pM, Dd, nullptr, nullptr, Dd, 1);
    msymk<<<(Dd * Dd + 255) / 256, 256>>>();
    mgemm<<<gD, 256>>>(Wr_r, Dd, pM, Dd, pT1, Dd, nullptr, nullptr, Dd, 0);
    mgemm<<<gD, 256>>>(pT1, Dd, Wr_r, Dd, pKq, Dd, nullptr, nullptr, Dd, 1);

    // 8-13. node matrices
    dim3 gN(Dd / 128, Nn / 128);
    mgemm<<<gN, 256>>>(pX4 + 2048, 4096, Wo_r, Dd, pCW, Dd, nullptr, nullptr, Dd, 1);
    mgemm<<<gN, 256>>>(pX4 + 3072, 4096, Ws_r, Dd, pGW, Dd, nullptr, nullptr, Dd, 1);
    mgemm<<<gN, 256>>>(pX4,        4096, pMsym, Dd, pU1, Dd, pCW, nullptr, Dd, 0);
    mgemm<<<gN, 256>>>(pX4 + 1024, 4096, pMsym, Dd, pU2, Dd, pGW, nullptr, Dd, 0);
    mgemm<<<gN, 256>>>(pU1, Dd, Wr_r, Dd, pV1, Dd, nullptr, nullptr, Dd, 1);
    mgemm<<<gN, 256>>>(pU2, Dd, Wr_r, Dd, pV2, Dd, nullptr, nullptr, Dd, 1);

    // 14-16. pair matrix P = C@G^T + U1@B'^T + A@GW^T
    dim3 gP(Nn / 128, Nn / 128);
    mgemm<<<gP, 256>>>(pX4 + 2048, 4096, pX4 + 3072, 4096, pP, Nn, nullptr, nullptr, Dd, 1);
    mgemm<<<gP, 256>>>(pU1, Dd, pX4 + 1024, 4096, pP, Nn, pP, nullptr, Dd, 1);
    mgemm<<<gP, 256>>>(pX4, 4096, pGW, Dd, pP, Nn, pP, nullptr, Dd, 1);

    // 17. node scalars
    rowdots<<<Nn, 256>>>(pS1, pS2);

    // 18. Y = rvf @ Kq  (the only E x D^2 GEMM)
    mgemm<<<dim3(Dd / 128, E / 128), 256>>>(rvf, Dd, pKq, Dd, pY, Dd,
                                            nullptr, nullptr, Dd, 0);

    // 19. fused quad reduce + logits
    qreduce<<<E, 256>>>(rvf, sbj, obj, pY, Nn, 1.0f / sqrtf((float)Dd));

    // 20. deterministic segment softmax stats (sbj and obj in one launch)
    segstats<<<dim3(Nn, 2), 256>>>(sbj, obj, E);

    // 21. dense mixing matrix from softmax weights
    wmatk<<<(E + 255) / 256, 256>>>(sbj, obj, E, Nn);

    // 22-23. ctx = Wmat @ vf ; ctxW = ctx @ W_ctx + b_ctx
    dim3 gc(Dd / 128, Nn / 128);
    mgemm<<<gc, 256>>>(pWmat, Nn, vf, Dd, pctx, Dd, nullptr, nullptr, Nn, 0);
    mgemm<<<gc, 256>>>(pctx, Dd, Wctx, Dd, pctxW, Dd, nullptr, bctx, Dd, 0);

    // 24. final update into output (involved == node has edges)
    finalk<<<(Nn * Dd + 255) / 256, 256>>>(vf, out + (size_t)E * Dd, Nn * Dd);
}

// round 5
// speedup vs baseline: 1.8252x; 1.3434x over previous
#include <cuda_runtime.h>
#include <cuda_bf16.h>
#include <math.h>
#include <stdint.h>

#define Dd 1024
#define MAXN 1024
#define MAXE 32768

// ================= static scratch =================
struct Scratch {
    float X4[MAXN * 4 * Dd];      // [A | B' | C | G], ld=4096
    float biascat[4 * Dd];
    float M[Dd * Dd];
    float T1[Dd * Dd];
    float Kq[Dd * Dd];
    float CW[MAXN * Dd];
    float GW[MAXN * Dd];
    float U1[MAXN * Dd];
    float U2[MAXN * Dd];
    float V1[MAXN * Dd];
    float V2[MAXN * Dd];
    float P[MAXN * MAXN];
    float S1[MAXN];
    float S2[MAXN];
    float logits[MAXE];
    float maxs[MAXN], sums[MAXN], maxo[MAXN], sumo[MAXN];
    float Wmat[MAXN * MAXN];
    float ctx[MAXN * Dd];
    float ctxW[MAXN * Dd];
};
static __device__ Scratch g_s;
static __device__ float g_Y[(size_t)MAXE * Dd];

// split bf16 operand storage
static __device__ __nv_bfloat16 g_rvfh[(size_t)MAXE * Dd], g_rvfl[(size_t)MAXE * Dd];
static __device__ __nv_bfloat16 g_vfh[MAXN * Dd],  g_vfl[MAXN * Dd];
static __device__ __nv_bfloat16 g_vfTh[Dd * MAXN], g_vfTl[Dd * MAXN];
static __device__ __nv_bfloat16 g_WcatTh[4 * Dd * Dd], g_WcatTl[4 * Dd * Dd];
static __device__ __nv_bfloat16 g_WctxTh[Dd * Dd], g_WctxTl[Dd * Dd];
static __device__ __nv_bfloat16 g_Wrrh[Dd * Dd], g_Wrrl[Dd * Dd];
static __device__ __nv_bfloat16 g_Wsrh[Dd * Dd], g_Wsrl[Dd * Dd];
static __device__ __nv_bfloat16 g_Worh[Dd * Dd], g_Worl[Dd * Dd];
static __device__ __nv_bfloat16 g_X4h[MAXN * 4 * Dd], g_X4l[MAXN * 4 * Dd];
static __device__ __nv_bfloat16 g_Msymh[Dd * Dd], g_Msyml[Dd * Dd];
static __device__ __nv_bfloat16 g_T1h[Dd * Dd], g_T1l[Dd * Dd];
static __device__ __nv_bfloat16 g_Kqh[Dd * Dd], g_Kql[Dd * Dd];
static __device__ __nv_bfloat16 g_U1h[MAXN * Dd], g_U1l[MAXN * Dd];
static __device__ __nv_bfloat16 g_U2h[MAXN * Dd], g_U2l[MAXN * Dd];
static __device__ __nv_bfloat16 g_GWh[MAXN * Dd], g_GWl[MAXN * Dd];
static __device__ __nv_bfloat16 g_Wmath[MAXN * MAXN], g_Wmatl[MAXN * MAXN];
static __device__ __nv_bfloat16 g_ctxh[MAXN * Dd], g_ctxl[MAXN * Dd];

// ================= PTX helpers =================
__device__ __forceinline__ uint32_t smem_u32(const void* p) {
    return (uint32_t)__cvta_generic_to_shared(p);
}
__device__ __forceinline__ void ldsm4(uint32_t& r0, uint32_t& r1, uint32_t& r2, uint32_t& r3, uint32_t a) {
    asm volatile("ldmatrix.sync.aligned.m8n8.x4.shared.b16 {%0,%1,%2,%3}, [%4];"
                 : "=r"(r0), "=r"(r1), "=r"(r2), "=r"(r3) : "r"(a));
}
__device__ __forceinline__ void ldsm2(uint32_t& r0, uint32_t& r1, uint32_t a) {
    asm volatile("ldmatrix.sync.aligned.m8n8.x2.shared.b16 {%0,%1}, [%2];"
                 : "=r"(r0), "=r"(r1) : "r"(a));
}
__device__ __forceinline__ void mma16816(float* d, const uint32_t* a, const uint32_t* b) {
    asm volatile("mma.sync.aligned.m16n8k16.row.col.f32.bf16.bf16.f32 "
                 "{%0,%1,%2,%3}, {%4,%5,%6,%7}, {%8,%9}, {%0,%1,%2,%3};"
                 : "+f"(d[0]), "+f"(d[1]), "+f"(d[2]), "+f"(d[3])
                 : "r"(a[0]), "r"(a[1]), "r"(a[2]), "r"(a[3]), "r"(b[0]), "r"(b[1]));
}
__device__ __forceinline__ void cpasync16(uint32_t saddr, const void* gaddr) {
    asm volatile("cp.async.cg.shared.global [%0], [%1], 16;" :: "r"(saddr), "l"(gaddr));
}
#define CP_COMMIT() asm volatile("cp.async.commit_group;" ::: "memory")
#define CP_WAIT(N)  asm volatile("cp.async.wait_group %0;" :: "n"(N) : "memory")

// ================= double-buffered split-bf16 mma.sync GEMM =================
// C[M,N] = cscale*(A @ B^T) (+addsrc)(+bias). A=[M,K] hi/lo bf16, B=[N,K] hi/lo bf16.
// BM=BN=128, BK=32. 256 threads = 8 warps (2 along M x 4 along N), warp tile 64x32.
// Requires M%128==0, N%128==0, K%32==0. smem pitch 80B -> conflict-free ldmatrix.
#define GP        40                       // pitch in bf16 (80 bytes)
#define TILE_B    (128 * GP * 2)           // 10240 bytes per matrix tile
#define STAGE_B   (4 * TILE_B)             // Ah,Al,Bh,Bl = 40960
#define SMEM_TOT  (2 * STAGE_B)            // 81920

__global__ __launch_bounds__(256, 1)
void mgemm2(const __nv_bfloat16* __restrict__ Ah, const __nv_bfloat16* __restrict__ Al, int lda,
            const __nv_bfloat16* __restrict__ Bh, const __nv_bfloat16* __restrict__ Bl, int ldb,
            float* __restrict__ C, int ldc,
            const float* __restrict__ addsrc, const float* __restrict__ bias,
            __nv_bfloat16* __restrict__ Chi, __nv_bfloat16* __restrict__ Clo,
            int K, float cscale)
{
    extern __shared__ char smem[];
    const int tid = threadIdx.x;
    const int lane = tid & 31, warp = tid >> 5;
    const int wm = warp & 1, wn = warp >> 1;
    const int m0 = blockIdx.y * 128, n0 = blockIdx.x * 128;
    const int l8 = lane & 7, grp = lane >> 3;
    const int nchunks = K >> 5;

    // load thread mapping: 512 16B-segments per matrix tile, 2 per thread
    const int r0 = tid >> 1, s0 = (tid & 1) << 4;        // rows 0..127, seg 0/16 bf16... wait
    // Each row is 64B of payload (32 bf16) = 4 x 16B. 128 rows * 4 = 512 segs; thread t -> segs t, t+256.
    auto load_stage = [&](int st, int kchunk) {
        const uint32_t sbase = smem_u32(smem) + st * STAGE_B;
        const int k0 = kchunk << 5;
#pragma unroll
        for (int it = 0; it < 2; it++) {
            int linear = tid + it * 256;
            int row = linear >> 2, seg = (linear & 3) << 3;    // seg in bf16 units (8 bf16 = 16B)
            uint32_t soff = (uint32_t)(row * 80 + seg * 2);
            const size_t ga = (size_t)(m0 + row) * lda + k0 + seg;
            cpasync16(sbase + soff,              Ah + ga);
            cpasync16(sbase + TILE_B + soff,     Al + ga);
            const size_t gb = (size_t)(n0 + row) * ldb + k0 + seg;
            cpasync16(sbase + 2 * TILE_B + soff, Bh + gb);
            cpasync16(sbase + 3 * TILE_B + soff, Bl + gb);
        }
    };

    float acc[4][4][4] = {};

    load_stage(0, 0);
    CP_COMMIT();

    for (int i = 0; i < nchunks; i++) {
        const int st = i & 1;
        if (i + 1 < nchunks) {
            load_stage(st ^ 1, i + 1);
            CP_COMMIT();
            CP_WAIT(1);
        } else {
            CP_WAIT(0);
        }
        __syncthreads();

        const char* base = smem + st * STAGE_B;
#pragma unroll
        for (int kk = 0; kk < 2; kk++) {
            const int kcol = kk * 16;
            uint32_t ah[4][4], al[4][4], bh[4][2], bl[4][2];
#pragma unroll
            for (int mt = 0; mt < 4; mt++) {
                int row = wm * 64 + mt * 16 + l8 + ((grp & 1) << 3);
                int col = kcol + ((grp >> 1) << 3);
                uint32_t a0 = smem_u32(base + row * 80 + col * 2);
                ldsm4(ah[mt][0], ah[mt][1], ah[mt][2], ah[mt][3], a0);
                ldsm4(al[mt][0], al[mt][1], al[mt][2], al[mt][3], a0 + TILE_B);
            }
#pragma unroll
            for (int nt = 0; nt < 4; nt++) {
                int row = wn * 32 + nt * 8 + l8;
                int col = kcol + ((grp & 1) << 3);
                uint32_t b0 = smem_u32(base + 2 * TILE_B + row * 80 + col * 2);
                ldsm2(bh[nt][0], bh[nt][1], b0);
                ldsm2(bl[nt][0], bl[nt][1], b0 + TILE_B);
            }
#pragma unroll
            for (int mt = 0; mt < 4; mt++)
#pragma unroll
                for (int nt = 0; nt < 4; nt++) {
                    mma16816(acc[mt][nt], ah[mt], bh[nt]);
                    mma16816(acc[mt][nt], ah[mt], bl[nt]);
                    mma16816(acc[mt][nt], al[mt], bh[nt]);
                }
        }
        __syncthreads();
    }

    // ---- epilogue ----
#pragma unroll
    for (int mt = 0; mt < 4; mt++)
#pragma unroll
        for (int nt = 0; nt < 4; nt++) {
            int m = m0 + wm * 64 + mt * 16 + (lane >> 2);
            int n = n0 + wn * 32 + nt * 8 + (lane & 3) * 2;
#pragma unroll
            for (int hrow = 0; hrow < 2; hrow++) {
                int mm = m + hrow * 8;
                float2 v = make_float2(acc[mt][nt][hrow * 2] * cscale,
                                       acc[mt][nt][hrow * 2 + 1] * cscale);
                if (addsrc) {
                    float2 s = *(const float2*)(addsrc + (size_t)mm * ldc + n);
                    v.x += s.x; v.y += s.y;
                }
                if (bias) {
                    float2 b = *(const float2*)(bias + n);
                    v.x += b.x; v.y += b.y;
                }
                *(float2*)(C + (size_t)mm * ldc + n) = v;
                if (Chi) {
                    __nv_bfloat16 h0 = __float2bfloat16(v.x), h1 = __float2bfloat16(v.y);
                    Chi[(size_t)mm * ldc + n]     = h0;
                    Chi[(size_t)mm * ldc + n + 1] = h1;
                    Clo[(size_t)mm * ldc + n]     = __float2bfloat16(v.x - __bfloat162float(h0));
                    Clo[(size_t)mm * ldc + n + 1] = __float2bfloat16(v.y - __bfloat162float(h1));
                }
            }
        }
}

// ================= conversion / transpose kernels =================
__global__ void splitk(const float* __restrict__ src, __nv_bfloat16* __restrict__ hi,
                       __nv_bfloat16* __restrict__ lo, long long n)
{
    for (long long i = (long long)blockIdx.x * blockDim.x + threadIdx.x; i < n;
         i += (long long)gridDim.x * blockDim.x) {
        float v = src[i];
        __nv_bfloat16 h = __float2bfloat16(v);
        hi[i] = h;
        lo[i] = __float2bfloat16(v - __bfloat162float(h));
    }
}

__global__ void tsplitk(const float* __restrict__ src, __nv_bfloat16* __restrict__ hi,
                        __nv_bfloat16* __restrict__ lo, int R, int C)
{
    __shared__ float tile[32][33];
    int cx = blockIdx.x * 32, ry = blockIdx.y * 32;
    int tx = threadIdx.x, ty = threadIdx.y;  // 32 x 8
#pragma unroll
    for (int i = 0; i < 32; i += 8)
        tile[ty + i][tx] = src[(size_t)(ry + ty + i) * C + cx + tx];
    __syncthreads();
#pragma unroll
    for (int i = 0; i < 32; i += 8) {
        float v = tile[tx][ty + i];
        __nv_bfloat16 h = __float2bfloat16(v);
        size_t o = (size_t)(cx + ty + i) * R + ry + tx;
        hi[o] = h;
        lo[o] = __float2bfloat16(v - __bfloat162float(h));
    }
}

__global__ void biascatk(const float* __restrict__ brel, const float* __restrict__ bsbj,
                         const float* __restrict__ bobj)
{
    int idx = blockIdx.x * 256 + threadIdx.x;
    if (idx < 4 * Dd) {
        int c = idx >> 10, n = idx & 1023;
        g_s.biascat[idx] = (c == 0) ? 0.f : (c == 1 ? brel[n] : (c == 2 ? bsbj[n] : bobj[n]));
    }
}

__global__ void msymk()   // Msym = M + M^T, split to bf16 hi/lo
{
    int idx = blockIdx.x * 256 + threadIdx.x;
    if (idx < Dd * Dd) {
        int i = idx >> 10, j = idx & 1023;
        float v = g_s.M[idx] + g_s.M[j * Dd + i];
        __nv_bfloat16 h = __float2bfloat16(v);
        g_Msymh[idx] = h;
        g_Msyml[idx] = __float2bfloat16(v - __bfloat162float(h));
    }
}

__global__ void zerok(float* p, int n)
{
    int i = blockIdx.x * 256 + threadIdx.x;
    if (i < n) p[i] = 0.f;
}

__global__ void copyk(const float* __restrict__ src, float* __restrict__ dst, long long n4)
{
    long long i = (long long)blockIdx.x * blockDim.x + threadIdx.x;
    if (i < n4) ((float4*)dst)[i] = ((const float4*)src)[i];
}

// ================= graph epilogue kernels =================
__global__ void rowdots(float* __restrict__ S1, float* __restrict__ S2)
{
    int n = blockIdx.x, tid = threadIdx.x;
    const float* a  = g_s.X4 + (size_t)n * 4096;
    const float* bp = a + 1024;
    float s1 = 0.f, s2 = 0.f;
    for (int d = tid; d < Dd; d += 256) {
        s1 += a[d]  * (g_s.U1[(size_t)n * Dd + d] + g_s.CW[(size_t)n * Dd + d]);
        s2 += bp[d] * (g_s.U2[(size_t)n * Dd + d] + g_s.GW[(size_t)n * Dd + d]);
    }
    __shared__ float r1[256], r2[256];
    r1[tid] = s1; r2[tid] = s2; __syncthreads();
    for (int st = 128; st > 0; st >>= 1) {
        if (tid < st) { r1[tid] += r1[tid + st]; r2[tid] += r2[tid + st]; }
        __syncthreads();
    }
    if (tid == 0) { S1[n] = 0.5f * r1[0]; S2[n] = 0.5f * r2[0]; }
}

__global__ __launch_bounds__(256)
void qreduce(const float* __restrict__ X, const int* __restrict__ sbj,
             const int* __restrict__ obj, const float* __restrict__ Y,
             int Nn, float scale)
{
    int e = blockIdx.x, tid = threadIdx.x;
    int s = sbj[e], o = obj[e];
    const float4* x  = (const float4*)(X + (size_t)e * Dd);
    const float4* y  = (const float4*)(Y + (size_t)e * Dd);
    const float4* v1 = (const float4*)(g_s.V1 + (size_t)s * Dd);
    const float4* v2 = (const float4*)(g_s.V2 + (size_t)o * Dd);
    float4 xv = x[tid], yv = y[tid], a = v1[tid], b = v2[tid];
    float acc = (yv.x + a.x + b.x) * xv.x + (yv.y + a.y + b.y) * xv.y
              + (yv.z + a.z + b.z) * xv.z + (yv.w + a.w + b.w) * xv.w;
    acc += __shfl_xor_sync(0xffffffffu, acc, 16);
    acc += __shfl_xor_sync(0xffffffffu, acc, 8);
    acc += __shfl_xor_sync(0xffffffffu, acc, 4);
    acc += __shfl_xor_sync(0xffffffffu, acc, 2);
    acc += __shfl_xor_sync(0xffffffffu, acc, 1);
    __shared__ float red[8];
    if ((tid & 31) == 0) red[tid >> 5] = acc;
    __syncthreads();
    if (tid == 0) {
        float t = 0.f;
#pragma unroll
        for (int i = 0; i < 8; i++) t += red[i];
        g_s.logits[e] = (t + g_s.P[(size_t)s * Nn + o] + g_s.S1[s] + g_s.S2[o]) * scale;
    }
}

__global__ void segstats(const int* __restrict__ sbj, const int* __restrict__ obj, int E)
{
    int n = blockIdx.x, tid = threadIdx.x;
    const int* ind = (blockIdx.y == 0) ? sbj : obj;
    __shared__ float red[256];
    float m = -1e30f;
    for (int e = tid; e < E; e += 256)
        if (ind[e] == n) m = fmaxf(m, g_s.logits[e]);
    red[tid] = m; __syncthreads();
    for (int st = 128; st > 0; st >>= 1) {
        if (tid < st) red[tid] = fmaxf(red[tid], red[tid + st]);
        __syncthreads();
    }
    float Mv = red[0]; __syncthreads();
    float s = 0.f;
    for (int e = tid; e < E; e += 256)
        if (ind[e] == n) s += expf(g_s.logits[e] - Mv);
    red[tid] = s; __syncthreads();
    for (int st = 128; st > 0; st >>= 1) {
        if (tid < st) red[tid] += red[tid + st];
        __syncthreads();
    }
    if (tid == 0) {
        if (blockIdx.y == 0) { g_s.maxs[n] = Mv; g_s.sums[n] = red[0]; }
        else                 { g_s.maxo[n] = Mv; g_s.sumo[n] = red[0]; }
    }
}

__global__ void wmatk(const int* __restrict__ sbj, const int* __restrict__ obj,
                      int E, int Nn)
{
    int e = blockIdx.x * 256 + threadIdx.x;
    if (e >= E) return;
    float l = g_s.logits[e];
    int s = sbj[e], o = obj[e];
    float ws = expf(l - g_s.maxs[s]) / g_s.sums[s];
    float wo = expf(l - g_s.maxo[o]) / g_s.sumo[o];
    atomicAdd(&g_s.Wmat[(size_t)s * Nn + o], ws);
    atomicAdd(&g_s.Wmat[(size_t)o * Nn + s], wo);
}

__global__ void finalk(const float* __restrict__ vf, float* __restrict__ out, int total)
{
    int idx = blockIdx.x * 256 + threadIdx.x;
    if (idx >= total) return;
    int n = idx >> 10;
    bool inv = (g_s.sums[n] > 0.f) || (g_s.sumo[n] > 0.f);
    out[idx] = vf[idx] + (inv ? g_s.ctxW[idx] : 0.f);
}

// ================= host orchestration =================
typedef __nv_bfloat16 bf16;

static void launch_gemm(const bf16* Ah, const bf16* Al, int lda,
                        const bf16* Bh, const bf16* Bl, int ldb,
                        float* C, int ldc, const float* addsrc, const float* bias,
                        bf16* Chi, bf16* Clo, int M, int N, int K, float cscale = 1.0f)
{
    dim3 grid(N / 128, M / 128);
    mgemm2<<<grid, 256, SMEM_TOT>>>(Ah, Al, lda, Bh, Bl, ldb, C, ldc,
                                    addsrc, bias, Chi, Clo, K, cscale);
}

extern "C" void kernel_launch(void* const* d_in, const int* in_sizes, int n_in,
                              void* d_out, int out_size)
{
    const float* vf   = (const float*)d_in[0];
    const float* rvf  = (const float*)d_in[1];
    const float* Wrel = (const float*)d_in[2];
    const float* brel = (const float*)d_in[3];
    const float* Wsbj = (const float*)d_in[4];
    const float* bsbj = (const float*)d_in[5];
    const float* Wobj = (const float*)d_in[6];
    const float* bobj = (const float*)d_in[7];
    const float* Wctx = (const float*)d_in[8];
    const float* bctx = (const float*)d_in[9];
    const int*   sbj  = (const int*)d_in[10];
    const int*   obj  = (const int*)d_in[11];

    const int Nn = in_sizes[0] / Dd;    // 768
    const int E  = in_sizes[10];        // 24576
    float* out = (float*)d_out;

    cudaFuncSetAttribute(mgemm2, cudaFuncAttributeMaxDynamicSharedMemorySize, SMEM_TOT);

    Scratch* S = nullptr;
    cudaGetSymbolAddress((void**)&S, g_s);
    float* pY;       cudaGetSymbolAddress((void**)&pY, g_Y);
    bf16 *rvfh, *rvfl, *vfh, *vfl, *vfTh, *vfTl, *WcatTh, *WcatTl, *WctxTh, *WctxTl;
    bf16 *Wrrh, *Wrrl, *Wsrh, *Wsrl, *Worh, *Worl, *X4h, *X4l, *Msh, *Msl;
    bf16 *T1h, *T1l, *Kqh, *Kql, *U1h, *U1l, *U2h, *U2l, *GWh, *GWl, *Wmh, *Wml, *cth, *ctl;
    cudaGetSymbolAddress((void**)&rvfh, g_rvfh);   cudaGetSymbolAddress((void**)&rvfl, g_rvfl);
    cudaGetSymbolAddress((void**)&vfh, g_vfh);     cudaGetSymbolAddress((void**)&vfl, g_vfl);
    cudaGetSymbolAddress((void**)&vfTh, g_vfTh);   cudaGetSymbolAddress((void**)&vfTl, g_vfTl);
    cudaGetSymbolAddress((void**)&WcatTh, g_WcatTh); cudaGetSymbolAddress((void**)&WcatTl, g_WcatTl);
    cudaGetSymbolAddress((void**)&WctxTh, g_WctxTh); cudaGetSymbolAddress((void**)&WctxTl, g_WctxTl);
    cudaGetSymbolAddress((void**)&Wrrh, g_Wrrh);   cudaGetSymbolAddress((void**)&Wrrl, g_Wrrl);
    cudaGetSymbolAddress((void**)&Wsrh, g_Wsrh);   cudaGetSymbolAddress((void**)&Wsrl, g_Wsrl);
    cudaGetSymbolAddress((void**)&Worh, g_Worh);   cudaGetSymbolAddress((void**)&Worl, g_Worl);
    cudaGetSymbolAddress((void**)&X4h, g_X4h);     cudaGetSymbolAddress((void**)&X4l, g_X4l);
    cudaGetSymbolAddress((void**)&Msh, g_Msymh);   cudaGetSymbolAddress((void**)&Msl, g_Msyml);
    cudaGetSymbolAddress((void**)&T1h, g_T1h);     cudaGetSymbolAddress((void**)&T1l, g_T1l);
    cudaGetSymbolAddress((void**)&Kqh, g_Kqh);     cudaGetSymbolAddress((void**)&Kql, g_Kql);
    cudaGetSymbolAddress((void**)&U1h, g_U1h);     cudaGetSymbolAddress((void**)&U1l, g_U1l);
    cudaGetSymbolAddress((void**)&U2h, g_U2h);     cudaGetSymbolAddress((void**)&U2l, g_U2l);
    cudaGetSymbolAddress((void**)&GWh, g_GWh);     cudaGetSymbolAddress((void**)&GWl, g_GWl);
    cudaGetSymbolAddress((void**)&Wmh, g_Wmath);   cudaGetSymbolAddress((void**)&Wml, g_Wmatl);
    cudaGetSymbolAddress((void**)&cth, g_ctxh);    cudaGetSymbolAddress((void**)&ctl, g_ctxl);

    const float* Wr_r = Wrel + 2 * Dd * Dd;
    const float* Ws_r = Wsbj + Dd * Dd;
    const float* Wo_r = Wobj + Dd * Dd;

    // 1. passthrough copy
    long long n4 = (long long)E * Dd / 4;
    copyk<<<(unsigned)((n4 + 255) / 256), 256>>>(rvf, out, n4);

    // 2. conversions / transposes of inputs
    splitk<<<2048, 256>>>(rvf, rvfh, rvfl, (long long)E * Dd);
    splitk<<<256, 256>>>(vf, vfh, vfl, (long long)Nn * Dd);
    splitk<<<512, 256>>>(Wr_r, Wrrh, Wrrl, (long long)Dd * Dd);
    splitk<<<512, 256>>>(Ws_r, Wsrh, Wsrl, (long long)Dd * Dd);
    splitk<<<512, 256>>>(Wo_r, Worh, Worl, (long long)Dd * Dd);
    tsplitk<<<dim3(Dd / 32, Nn / 32), dim3(32, 8)>>>(vf, vfTh, vfTl, Nn, Dd);
    tsplitk<<<dim3(Dd / 32, Dd / 32), dim3(32, 8)>>>(Wctx, WctxTh, WctxTl, Dd, Dd);
    // WcatT = [Wr_s^T | Wr_o^T | Ws_v^T | Wo_v^T] as 4 contiguous [1024][1024] blocks
    tsplitk<<<dim3(Dd / 32, Dd / 32), dim3(32, 8)>>>(Wrel,            WcatTh + 0 * Dd * Dd, WcatTl + 0 * Dd * Dd, Dd, Dd);
    tsplitk<<<dim3(Dd / 32, Dd / 32), dim3(32, 8)>>>(Wrel + Dd * Dd,  WcatTh + 1 * Dd * Dd, WcatTl + 1 * Dd * Dd, Dd, Dd);
    tsplitk<<<dim3(Dd / 32, Dd / 32), dim3(32, 8)>>>(Wsbj,            WcatTh + 2 * Dd * Dd, WcatTl + 2 * Dd * Dd, Dd, Dd);
    tsplitk<<<dim3(Dd / 32, Dd / 32), dim3(32, 8)>>>(Wobj,            WcatTh + 3 * Dd * Dd, WcatTl + 3 * Dd * Dd, Dd, Dd);
    biascatk<<<(4 * Dd + 255) / 256, 256>>>(brel, bsbj, bobj);
    zerok<<<(Nn * Nn + 255) / 256, 256>>>(S->Wmat, Nn * Nn);

    // 3. X4 = vf @ WcatT^T + biascat   [768 x 4096]
    launch_gemm(vfh, vfl, Dd, WcatTh, WcatTl, Dd, S->X4, 4096, nullptr, S->biascat,
                X4h, X4l, Nn, 4096, Dd);

    // 4-6. M = Ws_r @ Wo_r^T ; Msym = M + M^T (split) ; T1 = Wr_r @ Msym^T (=Wr_r@Msym) ;
    //      Kq = 0.5 * T1 @ Wr_r^T
    launch_gemm(Wsrh, Wsrl, Dd, Worh, Worl, Dd, S->M, Dd, nullptr, nullptr,
                nullptr, nullptr, Dd, Dd, Dd);
    msymk<<<(Dd * Dd + 255) / 256, 256>>>();
    launch_gemm(Wrrh, Wrrl, Dd, Msh, Msl, Dd, S->T1, Dd, nullptr, nullptr,
                T1h, T1l, Dd, Dd, Dd);
    launch_gemm(T1h, T1l, Dd, Wrrh, Wrrl, Dd, S->Kq, Dd, nullptr, nullptr,
                Kqh, Kql, Dd, Dd, Dd, 0.5f);

    // 7-12. node matrices
    launch_gemm(X4h + 2048, X4l + 2048, 4096, Worh, Worl, Dd, S->CW, Dd, nullptr, nullptr,
                nullptr, nullptr, Nn, Dd, Dd);                                   // CW = C@Wo_r^T
    launch_gemm(X4h + 3072, X4l + 3072, 4096, Wsrh, Wsrl, Dd, S->GW, Dd, nullptr, nullptr,
                GWh, GWl, Nn, Dd, Dd);                                           // GW = G@Ws_r^T
    launch_gemm(X4h, X4l, 4096, Msh, Msl, Dd, S->U1, Dd, S->CW, nullptr,
                U1h, U1l, Nn, Dd, Dd);                                           // U1 = A@Msym + CW
    launch_gemm(X4h + 1024, X4l + 1024, 4096, Msh, Msl, Dd, S->U2, Dd, S->GW, nullptr,
                U2h, U2l, Nn, Dd, Dd);                                           // U2 = B'@Msym + GW
    launch_gemm(U1h, U1l, Dd, Wrrh, Wrrl, Dd, S->V1, Dd, nullptr, nullptr,
                nullptr, nullptr, Nn, Dd, Dd);                                   // V1 = U1@Wr_r^T
    launch_gemm(U2h, U2l, Dd, Wrrh, Wrrl, Dd, S->V2, Dd, nullptr, nullptr,
                nullptr, nullptr, Nn, Dd, Dd);                                   // V2 = U2@Wr_r^T

    // 13-15. P = C@G^T + U1@B'^T + A@GW^T
    launch_gemm(X4h + 2048, X4l + 2048, 4096, X4h + 3072, X4l + 3072, 4096, S->P, Nn,
                nullptr, nullptr, nullptr, nullptr, Nn, Nn, Dd);
    launch_gemm(U1h, U1l, Dd, X4h + 1024, X4l + 1024, 4096, S->P, Nn,
                S->P, nullptr, nullptr, nullptr, Nn, Nn, Dd);
    launch_gemm(X4h, X4l, 4096, GWh, GWl, Dd, S->P, Nn,
                S->P, nullptr, nullptr, nullptr, Nn, Nn, Dd);

    // 16. node scalars
    rowdots<<<Nn, 256>>>(S->S1, S->S2);

    // 17. Y = rvf @ Kq  (E x D x D, Kq symmetric so Kq^T works)
    launch_gemm(rvfh, rvfl, Dd, Kqh, Kql, Dd, pY, Dd, nullptr, nullptr,
                nullptr, nullptr, E, Dd, Dd);

    // 18. logits
    qreduce<<<E, 256>>>(rvf, sbj, obj, pY, Nn, 1.0f / sqrtf((float)Dd));

    // 19-20. softmax stats + mixing matrix
    segstats<<<dim3(Nn, 2), 256>>>(sbj, obj, E);
    wmatk<<<(E + 255) / 256, 256>>>(sbj, obj, E, Nn);
    splitk<<<256, 256>>>(S->Wmat, Wmh, Wml, (long long)Nn * Nn);

    // 21-22. ctx = Wmat @ vf ; ctxW = ctx @ Wctx + bctx
    launch_gemm(Wmh, Wml, Nn, vfTh, vfTl, Nn, S->ctx, Dd, nullptr, nullptr,
                cth, ctl, Nn, Dd, Nn);
    launch_gemm(cth, ctl, Dd, WctxTh, WctxTl, Dd, S->ctxW, Dd, nullptr, bctx,
                nullptr, nullptr, Nn, Dd, Dd);

    // 23. final update
    finalk<<<(Nn * Dd + 255) / 256, 256>>>(vf, out + (size_t)E * Dd, Nn * Dd);
}

// round 7
// speedup vs baseline: 2.5082x; 1.3742x over previous
#include <cuda_runtime.h>
#include <cuda_bf16.h>
#include <math.h>
#include <stdint.h>

#define Dd 1024
#define MAXN 1024
#define MAXE 32768

typedef __nv_bfloat16 bf16;

// ================= static scratch =================
struct Scratch {
    float X4[MAXN * 4 * Dd];      // [A | B' | C | G], ld=4096
    float biascat[4 * Dd];
    float M[Dd * Dd];
    float T1[Dd * Dd];
    float Kq[Dd * Dd];
    float CW[MAXN * Dd];
    float GW[MAXN * Dd];
    float U1[MAXN * Dd];
    float U2[MAXN * Dd];
    float V1[MAXN * Dd];
    float V2[MAXN * Dd];
    float Pa[MAXN * MAXN];
    float Pb[MAXN * MAXN];
    float Pc[MAXN * MAXN];
    float S1[MAXN];
    float S2[MAXN];
    float quadP[(size_t)MAXE * 8];
    float logits[MAXE];
    float maxs[MAXN], sums[MAXN], maxo[MAXN], sumo[MAXN];
    float Wmat[MAXN * MAXN];
    float ctx[MAXN * Dd];
    float ctxW[MAXN * Dd];
};
static __device__ Scratch g_s;

// split bf16 operand storage
static __device__ bf16 g_rvfh[(size_t)MAXE * Dd], g_rvfl[(size_t)MAXE * Dd];
static __device__ bf16 g_vfh[MAXN * Dd],  g_vfl[MAXN * Dd];
static __device__ bf16 g_vfTh[Dd * MAXN], g_vfTl[Dd * MAXN];
static __device__ bf16 g_WcatTh[4 * Dd * Dd], g_WcatTl[4 * Dd * Dd];
static __device__ bf16 g_WctxTh[Dd * Dd], g_WctxTl[Dd * Dd];
static __device__ bf16 g_Wrrh[Dd * Dd], g_Wrrl[Dd * Dd];
static __device__ bf16 g_Wsrh[Dd * Dd], g_Wsrl[Dd * Dd];
static __device__ bf16 g_Worh[Dd * Dd], g_Worl[Dd * Dd];
static __device__ bf16 g_X4h[MAXN * 4 * Dd], g_X4l[MAXN * 4 * Dd];
static __device__ bf16 g_Msymh[Dd * Dd], g_Msyml[Dd * Dd];
static __device__ bf16 g_T1h[Dd * Dd], g_T1l[Dd * Dd];
static __device__ bf16 g_Kqh[Dd * Dd], g_Kql[Dd * Dd];
static __device__ bf16 g_U1h[MAXN * Dd], g_U1l[MAXN * Dd];
static __device__ bf16 g_U2h[MAXN * Dd], g_U2l[MAXN * Dd];
static __device__ bf16 g_GWh[MAXN * Dd], g_GWl[MAXN * Dd];
static __device__ bf16 g_Wmath[MAXN * MAXN], g_Wmatl[MAXN * MAXN];
static __device__ bf16 g_ctxh[MAXN * Dd], g_ctxl[MAXN * Dd];

// ================= PTX helpers =================
__device__ __forceinline__ uint32_t smem_u32(const void* p) {
    return (uint32_t)__cvta_generic_to_shared(p);
}
__device__ __forceinline__ void ldsm4(uint32_t& r0, uint32_t& r1, uint32_t& r2, uint32_t& r3, uint32_t a) {
    asm volatile("ldmatrix.sync.aligned.m8n8.x4.shared.b16 {%0,%1,%2,%3}, [%4];"
                 : "=r"(r0), "=r"(r1), "=r"(r2), "=r"(r3) : "r"(a));
}
__device__ __forceinline__ void ldsm2(uint32_t& r0, uint32_t& r1, uint32_t a) {
    asm volatile("ldmatrix.sync.aligned.m8n8.x2.shared.b16 {%0,%1}, [%2];"
                 : "=r"(r0), "=r"(r1) : "r"(a));
}
__device__ __forceinline__ void mma16816(float* d, const uint32_t* a, const uint32_t* b) {
    asm volatile("mma.sync.aligned.m16n8k16.row.col.f32.bf16.bf16.f32 "
                 "{%0,%1,%2,%3}, {%4,%5,%6,%7}, {%8,%9}, {%0,%1,%2,%3};"
                 : "+f"(d[0]), "+f"(d[1]), "+f"(d[2]), "+f"(d[3])
                 : "r"(a[0]), "r"(a[1]), "r"(a[2]), "r"(a[3]), "r"(b[0]), "r"(b[1]));
}
__device__ __forceinline__ void cpasync16(uint32_t saddr, const void* gaddr) {
    asm volatile("cp.async.cg.shared.global [%0], [%1], 16;" :: "r"(saddr), "l"(gaddr));
}
#define CP_COMMIT() asm volatile("cp.async.commit_group;" ::: "memory")
#define CP_WAIT(N)  asm volatile("cp.async.wait_group %0;" :: "n"(N) : "memory")

// ================= batched split-bf16 mma.sync GEMM =================
// Each desc: C[M,N] = cscale*(A @ B^T) (+addsrc)(+bias); optional bf16 hi/lo C emit;
// optional "quad" epilogue: quadP[m*8+blkx] = sum_n (val + V1[sbj[m]] + V2[obj[m]])*x[m,n].
// BM=BN=128, BK=64, 3-stage cp.async pipeline, 1 sync per chunk.
struct GemmDesc {
    const bf16 *Ah, *Al, *Bh, *Bl;
    const float *addsrc, *bias;
    float* C;
    bf16 *Chi, *Clo;
    const float* xptr;          // quad mode: fp32 A source (rvf)
    const int *sbjp, *objp;     // quad mode
    const float *v1p, *v2p;     // quad mode
    float* qp;                  // quad mode: quadP output
    int lda, ldb, ldc, K, mb, nb;
    float cscale;
    int pad;
};
struct GemmBatch { GemmDesc d[4]; };

#define TILE_B    (128 * 144)              // 18432 B per matrix tile (pitch 144)
#define STAGE_B   (4 * TILE_B)             // 73728
#define SMEM_TOT  (3 * STAGE_B)            // 221184

__global__ __launch_bounds__(256, 1)
void mgemm3(GemmBatch batch)
{
    extern __shared__ char smem[];
    const GemmDesc d = batch.d[blockIdx.z];
    if ((int)blockIdx.y >= d.mb || (int)blockIdx.x >= d.nb) return;

    const int tid = threadIdx.x;
    const int lane = tid & 31, warp = tid >> 5;
    const int wm = warp & 1, wn = warp >> 1;
    const int m0 = blockIdx.y * 128, n0 = blockIdx.x * 128;
    const int l8 = lane & 7, grp = lane >> 3;
    const int lda = d.lda, ldb = d.ldb;
    const bf16 *Ah = d.Ah, *Al = d.Al, *Bh = d.Bh, *Bl = d.Bl;
    const int nchunks = d.K >> 6;

    auto load_stage = [&](int stg, int chunk) {
        const uint32_t sbase = smem_u32(smem) + stg * STAGE_B;
        const int k0 = chunk << 6;
#pragma unroll
        for (int it = 0; it < 4; it++) {
            int linear = tid + it * 256;                 // 0..1023
            int row = linear >> 3, seg = (linear & 7) << 3;  // seg in bf16 units
            uint32_t soff = (uint32_t)(row * 144 + seg * 2);
            size_t ga = (size_t)(m0 + row) * lda + k0 + seg;
            cpasync16(sbase + soff,                  Ah + ga);
            cpasync16(sbase + TILE_B + soff,         Al + ga);
            size_t gb = (size_t)(n0 + row) * ldb + k0 + seg;
            cpasync16(sbase + 2 * TILE_B + soff,     Bh + gb);
            cpasync16(sbase + 3 * TILE_B + soff,     Bl + gb);
        }
    };

    float acc[4][4][4] = {};

    load_stage(0, 0);
    CP_COMMIT();
    if (nchunks > 1) { load_stage(1, 1); CP_COMMIT(); }

    int st = 0;
    for (int i = 0; i < nchunks; i++) {
        if (i + 1 < nchunks) CP_WAIT(1); else CP_WAIT(0);
        __syncthreads();
        if (i + 2 < nchunks) {
            int nxt = st + 2; if (nxt >= 3) nxt -= 3;
            load_stage(nxt, i + 2);
            CP_COMMIT();
        }

        const char* base = smem + st * STAGE_B;
#pragma unroll
        for (int kk = 0; kk < 4; kk++) {
            const int kcol = kk * 16;
            uint32_t ah[4][4], al[4][4], bh[4][2], bl[4][2];
#pragma unroll
            for (int mt = 0; mt < 4; mt++) {
                int row = wm * 64 + mt * 16 + l8 + ((grp & 1) << 3);
                int col = kcol + ((grp >> 1) << 3);
                uint32_t a0 = smem_u32(base + row * 144 + col * 2);
                ldsm4(ah[mt][0], ah[mt][1], ah[mt][2], ah[mt][3], a0);
                ldsm4(al[mt][0], al[mt][1], al[mt][2], al[mt][3], a0 + TILE_B);
            }
#pragma unroll
            for (int nt = 0; nt < 4; nt++) {
                int row = wn * 32 + nt * 8 + l8;
                int col = kcol + ((grp & 1) << 3);
                uint32_t b0 = smem_u32(base + 2 * TILE_B + row * 144 + col * 2);
                ldsm2(bh[nt][0], bh[nt][1], b0);
                ldsm2(bl[nt][0], bl[nt][1], b0 + TILE_B);
            }
            // split terms OUTERMOST: same-acc reuse distance = 16 MMAs
#pragma unroll
            for (int mt = 0; mt < 4; mt++)
#pragma unroll
                for (int nt = 0; nt < 4; nt++) mma16816(acc[mt][nt], ah[mt], bh[nt]);
#pragma unroll
            for (int mt = 0; mt < 4; mt++)
#pragma unroll
                for (int nt = 0; nt < 4; nt++) mma16816(acc[mt][nt], ah[mt], bl[nt]);
#pragma unroll
            for (int mt = 0; mt < 4; mt++)
#pragma unroll
                for (int nt = 0; nt < 4; nt++) mma16816(acc[mt][nt], al[mt], bh[nt]);
        }
        if (++st == 3) st = 0;
    }

    if (d.qp) {
        // fused quadratic epilogue: per-row partial of (val + V1[s] + V2[o]) . x
        float pt[4], pb[4];
#pragma unroll
        for (int mt = 0; mt < 4; mt++) {
            int mtop = m0 + wm * 64 + mt * 16 + (lane >> 2);
            int mbot = mtop + 8;
            int s1 = d.sbjp[mtop], o1 = d.objp[mtop];
            int s2 = d.sbjp[mbot], o2 = d.objp[mbot];
            float at = 0.f, ab = 0.f;
#pragma unroll
            for (int nt = 0; nt < 4; nt++) {
                int n = n0 + wn * 32 + nt * 8 + (lane & 3) * 2;
                float2 xt = *(const float2*)(d.xptr + (size_t)mtop * lda + n);
                float2 xb = *(const float2*)(d.xptr + (size_t)mbot * lda + n);
                float2 v1t = *(const float2*)(d.v1p + (size_t)s1 * Dd + n);
                float2 v2t = *(const float2*)(d.v2p + (size_t)o1 * Dd + n);
                float2 v1b = *(const float2*)(d.v1p + (size_t)s2 * Dd + n);
                float2 v2b = *(const float2*)(d.v2p + (size_t)o2 * Dd + n);
                at += (acc[mt][nt][0] + v1t.x + v2t.x) * xt.x
                    + (acc[mt][nt][1] + v1t.y + v2t.y) * xt.y;
                ab += (acc[mt][nt][2] + v1b.x + v2b.x) * xb.x
                    + (acc[mt][nt][3] + v1b.y + v2b.y) * xb.y;
            }
            at += __shfl_xor_sync(0xffffffffu, at, 1);
            at += __shfl_xor_sync(0xffffffffu, at, 2);
            ab += __shfl_xor_sync(0xffffffffu, ab, 1);
            ab += __shfl_xor_sync(0xffffffffu, ab, 2);
            pt[mt] = at; pb[mt] = ab;
        }
        __syncthreads();                    // all compute done; reuse smem
        float* qs = (float*)smem;           // [128][4]
        if ((lane & 3) == 0) {
#pragma unroll
            for (int mt = 0; mt < 4; mt++) {
                int rt = wm * 64 + mt * 16 + (lane >> 2);
                qs[rt * 4 + wn] = pt[mt];
                qs[(rt + 8) * 4 + wn] = pb[mt];
            }
        }
        __syncthreads();
        if (tid < 128) {
            float q = qs[tid * 4] + qs[tid * 4 + 1] + qs[tid * 4 + 2] + qs[tid * 4 + 3];
            d.qp[(size_t)(m0 + tid) * 8 + blockIdx.x] = q;
        }
        return;
    }

    // ---- standard epilogue ----
    const int ldc = d.ldc;
#pragma unroll
    for (int mt = 0; mt < 4; mt++)
#pragma unroll
        for (int nt = 0; nt < 4; nt++) {
            int m = m0 + wm * 64 + mt * 16 + (lane >> 2);
            int n = n0 + wn * 32 + nt * 8 + (lane & 3) * 2;
#pragma unroll
            for (int hrow = 0; hrow < 2; hrow++) {
                int mm = m + hrow * 8;
                float2 v = make_float2(acc[mt][nt][hrow * 2] * d.cscale,
                                       acc[mt][nt][hrow * 2 + 1] * d.cscale);
                if (d.addsrc) {
                    float2 s = *(const float2*)(d.addsrc + (size_t)mm * ldc + n);
                    v.x += s.x; v.y += s.y;
                }
                if (d.bias) {
                    float2 b = *(const float2*)(d.bias + n);
                    v.x += b.x; v.y += b.y;
                }
                *(float2*)(d.C + (size_t)mm * ldc + n) = v;
                if (d.Chi) {
                    bf16 h0 = __float2bfloat16(v.x), h1 = __float2bfloat16(v.y);
                    d.Chi[(size_t)mm * ldc + n]     = h0;
                    d.Chi[(size_t)mm * ldc + n + 1] = h1;
                    d.Clo[(size_t)mm * ldc + n]     = __float2bfloat16(v.x - __bfloat162float(h0));
                    d.Clo[(size_t)mm * ldc + n + 1] = __float2bfloat16(v.y - __bfloat162float(h1));
                }
            }
        }
}

// ================= conversion / transpose kernels =================
__global__ void splitk(const float* __restrict__ src, bf16* __restrict__ hi,
                       bf16* __restrict__ lo, long long n)
{
    for (long long i = (long long)blockIdx.x * blockDim.x + threadIdx.x; i < n;
         i += (long long)gridDim.x * blockDim.x) {
        float v = src[i];
        bf16 h = __float2bfloat16(v);
        hi[i] = h;
        lo[i] = __float2bfloat16(v - __bfloat162float(h));
    }
}

__global__ void tsplitk(const float* __restrict__ src, bf16* __restrict__ hi,
                        bf16* __restrict__ lo, int R, int C)
{
    __shared__ float tile[32][33];
    int cx = blockIdx.x * 32, ry = blockIdx.y * 32;
    int tx = threadIdx.x, ty = threadIdx.y;  // 32 x 8
#pragma unroll
    for (int i = 0; i < 32; i += 8)
        tile[ty + i][tx] = src[(size_t)(ry + ty + i) * C + cx + tx];
    __syncthreads();
#pragma unroll
    for (int i = 0; i < 32; i += 8) {
        float v = tile[tx][ty + i];
        bf16 h = __float2bfloat16(v);
        size_t o = (size_t)(cx + ty + i) * R + ry + tx;
        hi[o] = h;
        lo[o] = __float2bfloat16(v - __bfloat162float(h));
    }
}

__global__ void biascatk(const float* __restrict__ brel, const float* __restrict__ bsbj,
                         const float* __restrict__ bobj)
{
    int idx = blockIdx.x * 256 + threadIdx.x;
    if (idx < 4 * Dd) {
        int c = idx >> 10, n = idx & 1023;
        g_s.biascat[idx] = (c == 0) ? 0.f : (c == 1 ? brel[n] : (c == 2 ? bsbj[n] : bobj[n]));
    }
}

__global__ void msymk()   // Msym = M + M^T, split to bf16 hi/lo
{
    int idx = blockIdx.x * 256 + threadIdx.x;
    if (idx < Dd * Dd) {
        int i = idx >> 10, j = idx & 1023;
        float v = g_s.M[idx] + g_s.M[j * Dd + i];
        bf16 h = __float2bfloat16(v);
        g_Msymh[idx] = h;
        g_Msyml[idx] = __float2bfloat16(v - __bfloat162float(h));
    }
}

__global__ void zerok(float* p, int n)
{
    int i = blockIdx.x * 256 + threadIdx.x;
    if (i < n) p[i] = 0.f;
}

__global__ void copyk(const float* __restrict__ src, float* __restrict__ dst, long long n4)
{
    long long i = (long long)blockIdx.x * blockDim.x + threadIdx.x;
    if (i < n4) ((float4*)dst)[i] = ((const float4*)src)[i];
}

// ================= graph epilogue kernels =================
__global__ void rowdots(float* __restrict__ S1, float* __restrict__ S2)
{
    int n = blockIdx.x, tid = threadIdx.x;
    const float* a  = g_s.X4 + (size_t)n * 4096;
    const float* bp = a + 1024;
    float s1 = 0.f, s2 = 0.f;
    for (int d = tid; d < Dd; d += 256) {
        s1 += a[d]  * (g_s.U1[(size_t)n * Dd + d] + g_s.CW[(size_t)n * Dd + d]);
        s2 += bp[d] * (g_s.U2[(size_t)n * Dd + d] + g_s.GW[(size_t)n * Dd + d]);
    }
    __shared__ float r1[256], r2[256];
    r1[tid] = s1; r2[tid] = s2; __syncthreads();
    for (int st = 128; st > 0; st >>= 1) {
        if (tid < st) { r1[tid] += r1[tid + st]; r2[tid] += r2[tid + st]; }
        __syncthreads();
    }
    if (tid == 0) { S1[n] = 0.5f * r1[0]; S2[n] = 0.5f * r2[0]; }
}

__global__ void logitsk(const int* __restrict__ sbj, const int* __restrict__ obj,
                        int E, int Nn, float scale)
{
    int e = blockIdx.x * 256 + threadIdx.x;
    if (e >= E) return;
    const float* qp = g_s.quadP + (size_t)e * 8;
    float q = qp[0] + qp[1] + qp[2] + qp[3] + qp[4] + qp[5] + qp[6] + qp[7];
    int s = sbj[e], o = obj[e];
    size_t po = (size_t)s * Nn + o;
    g_s.logits[e] = (q + g_s.Pa[po] + g_s.Pb[po] + g_s.Pc[po] + g_s.S1[s] + g_s.S2[o]) * scale;
}

__global__ void segstats(const int* __restrict__ sbj, const int* __restrict__ obj, int E)
{
    int n = blockIdx.x, tid = threadIdx.x;
    const int* ind = (blockIdx.y == 0) ? sbj : obj;
    __shared__ float red[256];
    float m = -1e30f;
    for (int e = tid; e < E; e += 256)
        if (ind[e] == n) m = fmaxf(m, g_s.logits[e]);
    red[tid] = m; __syncthreads();
    for (int st = 128; st > 0; st >>= 1) {
        if (tid < st) red[tid] = fmaxf(red[tid], red[tid + st]);
        __syncthreads();
    }
    float Mv = red[0]; __syncthreads();
    float s = 0.f;
    for (int e = tid; e < E; e += 256)
        if (ind[e] == n) s += expf(g_s.logits[e] - Mv);
    red[tid] = s; __syncthreads();
    for (int st = 128; st > 0; st >>= 1) {
        if (tid < st) red[tid] += red[tid + st];
        __syncthreads();
    }
    if (tid == 0) {
        if (blockIdx.y == 0) { g_s.maxs[n] = Mv; g_s.sums[n] = red[0]; }
        else                 { g_s.maxo[n] = Mv; g_s.sumo[n] = red[0]; }
    }
}

__global__ void wmatk(const int* __restrict__ sbj, const int* __restrict__ obj,
                      int E, int Nn)
{
    int e = blockIdx.x * 256 + threadIdx.x;
    if (e >= E) return;
    float l = g_s.logits[e];
    int s = sbj[e], o = obj[e];
    float ws = expf(l - g_s.maxs[s]) / g_s.sums[s];
    float wo = expf(l - g_s.maxo[o]) / g_s.sumo[o];
    atomicAdd(&g_s.Wmat[(size_t)s * Nn + o], ws);
    atomicAdd(&g_s.Wmat[(size_t)o * Nn + s], wo);
}

__global__ void finalk(const float* __restrict__ vf, float* __restrict__ out, int total)
{
    int idx = blockIdx.x * 256 + threadIdx.x;
    if (idx >= total) return;
    int n = idx >> 10;
    bool inv = (g_s.sums[n] > 0.f) || (g_s.sumo[n] > 0.f);
    out[idx] = vf[idx] + (inv ? g_s.ctxW[idx] : 0.f);
}

// ================= host orchestration =================
static GemmDesc mkdesc(const bf16* Ah, const bf16* Al, int lda,
                       const bf16* Bh, const bf16* Bl, int ldb,
                       float* C, int ldc, const float* addsrc, const float* bias,
                       bf16* Chi, bf16* Clo, int M, int N, int K, float cscale = 1.0f)
{
    GemmDesc d{};
    d.Ah = Ah; d.Al = Al; d.Bh = Bh; d.Bl = Bl;
    d.addsrc = addsrc; d.bias = bias; d.C = C; d.Chi = Chi; d.Clo = Clo;
    d.lda = lda; d.ldb = ldb; d.ldc = ldc; d.K = K;
    d.mb = M / 128; d.nb = N / 128; d.cscale = cscale;
    return d;
}

static void launch_batch(GemmDesc* ds, int nd)
{
    GemmBatch b{};
    int mx = 0, nx = 0;
    for (int i = 0; i < nd; i++) { b.d[i] = ds[i]; if (ds[i].mb > mx) mx = ds[i].mb; if (ds[i].nb > nx) nx = ds[i].nb; }
    for (int i = nd; i < 4; i++) { b.d[i] = ds[0]; }   // unused slots (z < nd only)
    dim3 grid(nx, mx, nd);
    mgemm3<<<grid, 256, SMEM_TOT>>>(b);
}

extern "C" void kernel_launch(void* const* d_in, const int* in_sizes, int n_in,
                              void* d_out, int out_size)
{
    const float* vf   = (const float*)d_in[0];
    const float* rvf  = (const float*)d_in[1];
    const float* Wrel = (const float*)d_in[2];
    const float* brel = (const float*)d_in[3];
    const float* Wsbj = (const float*)d_in[4];
    const float* bsbj = (const float*)d_in[5];
    const float* Wobj = (const float*)d_in[6];
    const float* bobj = (const float*)d_in[7];
    const float* Wctx = (const float*)d_in[8];
    const float* bctx = (const float*)d_in[9];
    const int*   sbj  = (const int*)d_in[10];
    const int*   obj  = (const int*)d_in[11];

    const int Nn = in_sizes[0] / Dd;    // 768
    const int E  = in_sizes[10];        // 24576
    float* out = (float*)d_out;

    cudaFuncSetAttribute(mgemm3, cudaFuncAttributeMaxDynamicSharedMemorySize, SMEM_TOT);

    Scratch* S = nullptr;
    cudaGetSymbolAddress((void**)&S, g_s);
    bf16 *rvfh, *rvfl, *vfh, *vfl, *vfTh, *vfTl, *WcatTh, *WcatTl, *WctxTh, *WctxTl;
    bf16 *Wrrh, *Wrrl, *Wsrh, *Wsrl, *Worh, *Worl, *X4h, *X4l, *Msh, *Msl;
    bf16 *T1h, *T1l, *Kqh, *Kql, *U1h, *U1l, *U2h, *U2l, *GWh, *GWl, *Wmh, *Wml, *cth, *ctl;
    cudaGetSymbolAddress((void**)&rvfh, g_rvfh);   cudaGetSymbolAddress((void**)&rvfl, g_rvfl);
    cudaGetSymbolAddress((void**)&vfh, g_vfh);     cudaGetSymbolAddress((void**)&vfl, g_vfl);
    cudaGetSymbolAddress((void**)&vfTh, g_vfTh);   cudaGetSymbolAddress((void**)&vfTl, g_vfTl);
    cudaGetSymbolAddress((void**)&WcatTh, g_WcatTh); cudaGetSymbolAddress((void**)&WcatTl, g_WcatTl);
    cudaGetSymbolAddress((void**)&WctxTh, g_WctxTh); cudaGetSymbolAddress((void**)&WctxTl, g_WctxTl);
    cudaGetSymbolAddress((void**)&Wrrh, g_Wrrh);   cudaGetSymbolAddress((void**)&Wrrl, g_Wrrl);
    cudaGetSymbolAddress((void**)&Wsrh, g_Wsrh);   cudaGetSymbolAddress((void**)&Wsrl, g_Wsrl);
    cudaGetSymbolAddress((void**)&Worh, g_Worh);   cudaGetSymbolAddress((void**)&Worl, g_Worl);
    cudaGetSymbolAddress((void**)&X4h, g_X4h);     cudaGetSymbolAddress((void**)&X4l, g_X4l);
    cudaGetSymbolAddress((void**)&Msh, g_Msymh);   cudaGetSymbolAddress((void**)&Msl, g_Msyml);
    cudaGetSymbolAddress((void**)&T1h, g_T1h);     cudaGetSymbolAddress((void**)&T1l, g_T1l);
    cudaGetSymbolAddress((void**)&Kqh, g_Kqh);     cudaGetSymbolAddress((void**)&Kql, g_Kql);
    cudaGetSymbolAddress((void**)&U1h, g_U1h);     cudaGetSymbolAddress((void**)&U1l, g_U1l);
    cudaGetSymbolAddress((void**)&U2h, g_U2h);     cudaGetSymbolAddress((void**)&U2l, g_U2l);
    cudaGetSymbolAddress((void**)&GWh, g_GWh);     cudaGetSymbolAddress((void**)&GWl, g_GWl);
    cudaGetSymbolAddress((void**)&Wmh, g_Wmath);   cudaGetSymbolAddress((void**)&Wml, g_Wmatl);
    cudaGetSymbolAddress((void**)&cth, g_ctxh);    cudaGetSymbolAddress((void**)&ctl, g_ctxl);

    const float* Wr_r = Wrel + 2 * Dd * Dd;
    const float* Ws_r = Wsbj + Dd * Dd;
    const float* Wo_r = Wobj + Dd * Dd;

    // 1. passthrough copy + input conversions
    long long n4 = (long long)E * Dd / 4;
    copyk<<<(unsigned)((n4 + 255) / 256), 256>>>(rvf, out, n4);
    splitk<<<2048, 256>>>(rvf, rvfh, rvfl, (long long)E * Dd);
    splitk<<<256, 256>>>(vf, vfh, vfl, (long long)Nn * Dd);
    splitk<<<512, 256>>>(Wr_r, Wrrh, Wrrl, (long long)Dd * Dd);
    splitk<<<512, 256>>>(Ws_r, Wsrh, Wsrl, (long long)Dd * Dd);
    splitk<<<512, 256>>>(Wo_r, Worh, Worl, (long long)Dd * Dd);
    tsplitk<<<dim3(Dd / 32, Nn / 32), dim3(32, 8)>>>(vf, vfTh, vfTl, Nn, Dd);
    tsplitk<<<dim3(Dd / 32, Dd / 32), dim3(32, 8)>>>(Wctx, WctxTh, WctxTl, Dd, Dd);
    tsplitk<<<dim3(Dd / 32, Dd / 32), dim3(32, 8)>>>(Wrel,           WcatTh + 0 * Dd * Dd, WcatTl + 0 * Dd * Dd, Dd, Dd);
    tsplitk<<<dim3(Dd / 32, Dd / 32), dim3(32, 8)>>>(Wrel + Dd * Dd, WcatTh + 1 * Dd * Dd, WcatTl + 1 * Dd * Dd, Dd, Dd);
    tsplitk<<<dim3(Dd / 32, Dd / 32), dim3(32, 8)>>>(Wsbj,           WcatTh + 2 * Dd * Dd, WcatTl + 2 * Dd * Dd, Dd, Dd);
    tsplitk<<<dim3(Dd / 32, Dd / 32), dim3(32, 8)>>>(Wobj,           WcatTh + 3 * Dd * Dd, WcatTl + 3 * Dd * Dd, Dd, Dd);
    biascatk<<<(4 * Dd + 255) / 256, 256>>>(brel, bsbj, bobj);
    zerok<<<(Nn * Nn + 255) / 256, 256>>>(S->Wmat, Nn * Nn);

    // batch 1: X4 = vf@WcatT^T + biascat ; M = Ws_r@Wo_r^T
    {
        GemmDesc ds[2] = {
            mkdesc(vfh, vfl, Dd, WcatTh, WcatTl, Dd, S->X4, 4096, nullptr, S->biascat, X4h, X4l, Nn, 4096, Dd),
            mkdesc(Wsrh, Wsrl, Dd, Worh, Worl, Dd, S->M, Dd, nullptr, nullptr, nullptr, nullptr, Dd, Dd, Dd)
        };
        launch_batch(ds, 2);
    }
    msymk<<<(Dd * Dd + 255) / 256, 256>>>();

    // batch 2: CW, GW, Pa=C@G^T, T1=Wr_r@Msym
    {
        GemmDesc ds[4] = {
            mkdesc(X4h + 2048, X4l + 2048, 4096, Worh, Worl, Dd, S->CW, Dd, nullptr, nullptr, nullptr, nullptr, Nn, Dd, Dd),
            mkdesc(X4h + 3072, X4l + 3072, 4096, Wsrh, Wsrl, Dd, S->GW, Dd, nullptr, nullptr, GWh, GWl, Nn, Dd, Dd),
            mkdesc(X4h + 2048, X4l + 2048, 4096, X4h + 3072, X4l + 3072, 4096, S->Pa, Nn, nullptr, nullptr, nullptr, nullptr, Nn, Nn, Dd),
            mkdesc(Wrrh, Wrrl, Dd, Msh, Msl, Dd, S->T1, Dd, nullptr, nullptr, T1h, T1l, Dd, Dd, Dd)
        };
        launch_batch(ds, 4);
    }

    // batch 3: U1=A@Msym+CW, U2=B'@Msym+GW, Kq=0.5*T1@Wr_r^T
    {
        GemmDesc ds[3] = {
            mkdesc(X4h, X4l, 4096, Msh, Msl, Dd, S->U1, Dd, S->CW, nullptr, U1h, U1l, Nn, Dd, Dd),
            mkdesc(X4h + 1024, X4l + 1024, 4096, Msh, Msl, Dd, S->U2, Dd, S->GW, nullptr, U2h, U2l, Nn, Dd, Dd),
            mkdesc(T1h, T1l, Dd, Wrrh, Wrrl, Dd, S->Kq, Dd, nullptr, nullptr, Kqh, Kql, Dd, Dd, Dd, 0.5f)
        };
        launch_batch(ds, 3);
    }
    rowdots<<<Nn, 256>>>(S->S1, S->S2);

    // batch 4: V1, V2, Pb=U1@B'^T, Pc=A@GW^T
    {
        GemmDesc ds[4] = {
            mkdesc(U1h, U1l, Dd, Wrrh, Wrrl, Dd, S->V1, Dd, nullptr, nullptr, nullptr, nullptr, Nn, Dd, Dd),
            mkdesc(U2h, U2l, Dd, Wrrh, Wrrl, Dd, S->V2, Dd, nullptr, nullptr, nullptr, nullptr, Nn, Dd, Dd),
            mkdesc(U1h, U1l, Dd, X4h + 1024, X4l + 1024, 4096, S->Pb, Nn, nullptr, nullptr, nullptr, nullptr, Nn, Nn, Dd),
            mkdesc(X4h, X4l, 4096, GWh, GWl, Dd, S->Pc, Nn, nullptr, nullptr, nullptr, nullptr, Nn, Nn, Dd)
        };
        launch_batch(ds, 4);
    }

    // batch 5: Y = rvf@Kq with fused quad epilogue -> quadP
    {
        GemmDesc d = mkdesc(rvfh, rvfl, Dd, Kqh, Kql, Dd, nullptr, Dd, nullptr, nullptr,
                            nullptr, nullptr, E, Dd, Dd);
        d.xptr = rvf; d.sbjp = sbj; d.objp = obj; d.v1p = S->V1; d.v2p = S->V2;
        d.qp = S->quadP;
        launch_batch(&d, 1);
    }

    // logits, softmax stats, mixing matrix
    logitsk<<<(E + 255) / 256, 256>>>(sbj, obj, E, Nn, 1.0f / sqrtf((float)Dd));
    segstats<<<dim3(Nn, 2), 256>>>(sbj, obj, E);
    wmatk<<<(E + 255) / 256, 256>>>(sbj, obj, E, Nn);
    splitk<<<256, 256>>>(S->Wmat, Wmh, Wml, (long long)Nn * Nn);

    // ctx = Wmat@vf ; ctxW = ctx@Wctx + bctx
    {
        GemmDesc d = mkdesc(Wmh, Wml, Nn, vfTh, vfTl, Nn, S->ctx, Dd, nullptr, nullptr,
                            cth, ctl, Nn, Dd, Nn);
        launch_batch(&d, 1);
    }
    {
        GemmDesc d = mkdesc(cth, ctl, Dd, WctxTh, WctxTl, Dd, S->ctxW, Dd, nullptr, bctx,
                            nullptr, nullptr, Nn, Dd, Dd);
        launch_batch(&d, 1);
    }

    // final update
    finalk<<<(Nn * Dd + 255) / 256, 256>>>(vf, out + (size_t)E * Dd, Nn * Dd);
}

// round 8
// speedup vs baseline: 3.0013x; 1.1966x over previous
#include <cuda_runtime.h>
#include <cuda_bf16.h>
#include <cuda_fp16.h>
#include <math.h>
#include <stdint.h>

#define Dd 1024
#define MAXN 1024
#define MAXE 32768

typedef __nv_bfloat16 bf16;

// ================= static scratch =================
struct Scratch {
    float X4[MAXN * 4 * Dd];      // [A | B' | C | G], ld=4096
    float biascat[4 * Dd];
    float M[Dd * Dd];
    float T1[Dd * Dd];
    float Kq[Dd * Dd];
    float CW[MAXN * Dd];
    float GW[MAXN * Dd];
    float U1[MAXN * Dd];
    float U2[MAXN * Dd];
    float V1[MAXN * Dd];
    float V2[MAXN * Dd];
    float Pa[MAXN * MAXN];
    float Pb[MAXN * MAXN];
    float Pc[MAXN * MAXN];
    float S1[MAXN];
    float S2[MAXN];
    float quadP[(size_t)MAXE * 8];
    float logits[MAXE];
    float maxs[MAXN], sums[MAXN], maxo[MAXN], sumo[MAXN];
    float Wmat[MAXN * MAXN];
    float ctx[MAXN * Dd];
    float ctxW[MAXN * Dd];
};
static __device__ Scratch g_s;

// fp16 operands for the quad GEMM
static __device__ __half g_rvf16h[(size_t)MAXE * Dd], g_rvf16l[(size_t)MAXE * Dd];
static __device__ __half g_Kq16h[Dd * Dd];

// split bf16 operand storage
static __device__ bf16 g_vfh[MAXN * Dd],  g_vfl[MAXN * Dd];
static __device__ bf16 g_vfTh[Dd * MAXN], g_vfTl[Dd * MAXN];
static __device__ bf16 g_WcatTh[4 * Dd * Dd], g_WcatTl[4 * Dd * Dd];
static __device__ bf16 g_WctxTh[Dd * Dd], g_WctxTl[Dd * Dd];
static __device__ bf16 g_Wrrh[Dd * Dd], g_Wrrl[Dd * Dd];
static __device__ bf16 g_Wsrh[Dd * Dd], g_Wsrl[Dd * Dd];
static __device__ bf16 g_Worh[Dd * Dd], g_Worl[Dd * Dd];
static __device__ bf16 g_X4h[MAXN * 4 * Dd], g_X4l[MAXN * 4 * Dd];
static __device__ bf16 g_Msymh[Dd * Dd], g_Msyml[Dd * Dd];
static __device__ bf16 g_T1h[Dd * Dd], g_T1l[Dd * Dd];
static __device__ bf16 g_U1h[MAXN * Dd], g_U1l[MAXN * Dd];
static __device__ bf16 g_U2h[MAXN * Dd], g_U2l[MAXN * Dd];
static __device__ bf16 g_GWh[MAXN * Dd], g_GWl[MAXN * Dd];
static __device__ bf16 g_Wmath[MAXN * MAXN], g_Wmatl[MAXN * MAXN];
static __device__ bf16 g_ctxh[MAXN * Dd], g_ctxl[MAXN * Dd];

// ================= PTX helpers =================
__device__ __forceinline__ uint32_t smem_u32(const void* p) {
    return (uint32_t)__cvta_generic_to_shared(p);
}
__device__ __forceinline__ void ldsm4(uint32_t& r0, uint32_t& r1, uint32_t& r2, uint32_t& r3, uint32_t a) {
    asm volatile("ldmatrix.sync.aligned.m8n8.x4.shared.b16 {%0,%1,%2,%3}, [%4];"
                 : "=r"(r0), "=r"(r1), "=r"(r2), "=r"(r3) : "r"(a));
}
__device__ __forceinline__ void mma_bf(float* d, const uint32_t* a, const uint32_t* b) {
    asm volatile("mma.sync.aligned.m16n8k16.row.col.f32.bf16.bf16.f32 "
                 "{%0,%1,%2,%3}, {%4,%5,%6,%7}, {%8,%9}, {%0,%1,%2,%3};"
                 : "+f"(d[0]), "+f"(d[1]), "+f"(d[2]), "+f"(d[3])
                 : "r"(a[0]), "r"(a[1]), "r"(a[2]), "r"(a[3]), "r"(b[0]), "r"(b[1]));
}
__device__ __forceinline__ void mma_fp(float* d, const uint32_t* a, const uint32_t* b) {
    asm volatile("mma.sync.aligned.m16n8k16.row.col.f32.f16.f16.f32 "
                 "{%0,%1,%2,%3}, {%4,%5,%6,%7}, {%8,%9}, {%0,%1,%2,%3};"
                 : "+f"(d[0]), "+f"(d[1]), "+f"(d[2]), "+f"(d[3])
                 : "r"(a[0]), "r"(a[1]), "r"(a[2]), "r"(a[3]), "r"(b[0]), "r"(b[1]));
}
__device__ __forceinline__ void cpasync16(uint32_t saddr, const void* gaddr) {
    asm volatile("cp.async.cg.shared.global [%0], [%1], 16;" :: "r"(saddr), "l"(gaddr));
}
#define CP_COMMIT() asm volatile("cp.async.commit_group;" ::: "memory")
#define CP_WAIT(N)  asm volatile("cp.async.wait_group %0;" :: "n"(N) : "memory")

// ================= batched split mma.sync GEMM =================
// MODE 0: bf16 3-term split (ah*bh + ah*bl + al*bh).
// MODE 1: fp16 2-term (A exact hi+lo, B single: ah*bh + al*bh). Bl unused.
// Each desc: C = cscale*(A @ B^T) (+addsrc)(+bias); emit: 0 none, 1 bf16 hi/lo, 2 fp16 hi.
// Quad mode (qp != null): quadP[m*8+blkx] = sum_n (val + V1[sbj[m]] + V2[obj[m]])*x[m,n].
// BM=BN=128, BK=64, 3-stage cp.async pipeline.
struct GemmDesc {
    const bf16 *Ah, *Al, *Bh, *Bl;
    const float *addsrc, *bias;
    float* C;
    bf16 *Chi, *Clo;
    const float* xptr;
    const int *sbjp, *objp;
    const float *v1p, *v2p;
    float* qp;
    int lda, ldb, ldc, K, mb, nb;
    float cscale;
    int emit;
};
struct GemmBatch { GemmDesc d[4]; };

#define TILE_B    (128 * 144)              // 18432 B per matrix tile (pitch 144)
#define STAGE_B   (4 * TILE_B)             // 73728
#define SMEM_TOT  (3 * STAGE_B)            // 221184

template <int MODE>
__global__ __launch_bounds__(256, 1)
void mgemm3(GemmBatch batch)
{
    extern __shared__ char smem[];
    const GemmDesc d = batch.d[blockIdx.z];
    if ((int)blockIdx.y >= d.mb || (int)blockIdx.x >= d.nb) return;

    const int tid = threadIdx.x;
    const int lane = tid & 31, warp = tid >> 5;
    const int wm = warp & 1, wn = warp >> 1;
    const int m0 = blockIdx.y * 128, n0 = blockIdx.x * 128;
    const int l8 = lane & 7, grp = lane >> 3;
    const int lda = d.lda, ldb = d.ldb;
    const bf16 *Ah = d.Ah, *Al = d.Al, *Bh = d.Bh, *Bl = d.Bl;
    const int nchunks = d.K >> 6;

    auto load_stage = [&](int stg, int chunk) {
        const uint32_t sbase = smem_u32(smem) + stg * STAGE_B;
        const int k0 = chunk << 6;
#pragma unroll
        for (int it = 0; it < 4; it++) {
            int linear = tid + it * 256;
            int row = linear >> 3, seg = (linear & 7) << 3;
            uint32_t soff = (uint32_t)(row * 144 + seg * 2);
            size_t ga = (size_t)(m0 + row) * lda + k0 + seg;
            cpasync16(sbase + soff,              Ah + ga);
            cpasync16(sbase + TILE_B + soff,     Al + ga);
            size_t gb = (size_t)(n0 + row) * ldb + k0 + seg;
            cpasync16(sbase + 2 * TILE_B + soff, Bh + gb);
            if (MODE == 0)
                cpasync16(sbase + 3 * TILE_B + soff, Bl + gb);
        }
    };

    float acc[4][4][4] = {};

    load_stage(0, 0);
    CP_COMMIT();
    if (nchunks > 1) { load_stage(1, 1); CP_COMMIT(); }

    int st = 0;
    for (int i = 0; i < nchunks; i++) {
        if (i + 1 < nchunks) CP_WAIT(1); else CP_WAIT(0);
        __syncthreads();
        if (i + 2 < nchunks) {
            int nxt = st + 2; if (nxt >= 3) nxt -= 3;
            load_stage(nxt, i + 2);
            CP_COMMIT();
        }

        const char* base = smem + st * STAGE_B;
#pragma unroll
        for (int kk = 0; kk < 4; kk++) {
            const int kcol = kk * 16;
            uint32_t ah[4][4], al[4][4], bh[4][2], bl[4][2];
#pragma unroll
            for (int mt = 0; mt < 4; mt++) {
                int row = wm * 64 + mt * 16 + l8 + ((grp & 1) << 3);
                int col = kcol + ((grp >> 1) << 3);
                uint32_t a0 = smem_u32(base + row * 144 + col * 2);
                ldsm4(ah[mt][0], ah[mt][1], ah[mt][2], ah[mt][3], a0);
                ldsm4(al[mt][0], al[mt][1], al[mt][2], al[mt][3], a0 + TILE_B);
            }
            // B via ldmatrix.x4: one instruction covers 2 n-blocks x 2 k-halves
#pragma unroll
            for (int ntp = 0; ntp < 2; ntp++) {
                int row = wn * 32 + ntp * 16 + ((grp >> 1) << 3) + l8;
                int col = kcol + ((grp & 1) << 3);
                uint32_t b0 = smem_u32(base + 2 * TILE_B + row * 144 + col * 2);
                ldsm4(bh[2 * ntp][0], bh[2 * ntp][1], bh[2 * ntp + 1][0], bh[2 * ntp + 1][1], b0);
                if (MODE == 0)
                    ldsm4(bl[2 * ntp][0], bl[2 * ntp][1], bl[2 * ntp + 1][0], bl[2 * ntp + 1][1],
                          b0 + TILE_B);
            }
            // split terms OUTERMOST: same-acc reuse distance = 16 MMAs
#pragma unroll
            for (int mt = 0; mt < 4; mt++)
#pragma unroll
                for (int nt = 0; nt < 4; nt++) {
                    if (MODE == 0) mma_bf(acc[mt][nt], ah[mt], bh[nt]);
                    else           mma_fp(acc[mt][nt], ah[mt], bh[nt]);
                }
            if (MODE == 0) {
#pragma unroll
                for (int mt = 0; mt < 4; mt++)
#pragma unroll
                    for (int nt = 0; nt < 4; nt++) mma_bf(acc[mt][nt], ah[mt], bl[nt]);
            }
#pragma unroll
            for (int mt = 0; mt < 4; mt++)
#pragma unroll
                for (int nt = 0; nt < 4; nt++) {
                    if (MODE == 0) mma_bf(acc[mt][nt], al[mt], bh[nt]);
                    else           mma_fp(acc[mt][nt], al[mt], bh[nt]);
                }
        }
        if (++st == 3) st = 0;
    }

    if (d.qp) {
        // fused quadratic epilogue: per-row partial of (val + V1[s] + V2[o]) . x
        float pt[4], pb[4];
#pragma unroll
        for (int mt = 0; mt < 4; mt++) {
            int mtop = m0 + wm * 64 + mt * 16 + (lane >> 2);
            int mbot = mtop + 8;
            int s1 = d.sbjp[mtop], o1 = d.objp[mtop];
            int s2 = d.sbjp[mbot], o2 = d.objp[mbot];
            float at = 0.f, ab = 0.f;
#pragma unroll
            for (int nt = 0; nt < 4; nt++) {
                int n = n0 + wn * 32 + nt * 8 + (lane & 3) * 2;
                float2 xt = *(const float2*)(d.xptr + (size_t)mtop * lda + n);
                float2 xb = *(const float2*)(d.xptr + (size_t)mbot * lda + n);
                float2 v1t = *(const float2*)(d.v1p + (size_t)s1 * Dd + n);
                float2 v2t = *(const float2*)(d.v2p + (size_t)o1 * Dd + n);
                float2 v1b = *(const float2*)(d.v1p + (size_t)s2 * Dd + n);
                float2 v2b = *(const float2*)(d.v2p + (size_t)o2 * Dd + n);
                at += (acc[mt][nt][0] + v1t.x + v2t.x) * xt.x
                    + (acc[mt][nt][1] + v1t.y + v2t.y) * xt.y;
                ab += (acc[mt][nt][2] + v1b.x + v2b.x) * xb.x
                    + (acc[mt][nt][3] + v1b.y + v2b.y) * xb.y;
            }
            at += __shfl_xor_sync(0xffffffffu, at, 1);
            at += __shfl_xor_sync(0xffffffffu, at, 2);
            ab += __shfl_xor_sync(0xffffffffu, ab, 1);
            ab += __shfl_xor_sync(0xffffffffu, ab, 2);
            pt[mt] = at; pb[mt] = ab;
        }
        __syncthreads();
        float* qs = (float*)smem;           // [128][4]
        if ((lane & 3) == 0) {
#pragma unroll
            for (int mt = 0; mt < 4; mt++) {
                int rt = wm * 64 + mt * 16 + (lane >> 2);
                qs[rt * 4 + wn] = pt[mt];
                qs[(rt + 8) * 4 + wn] = pb[mt];
            }
        }
        __syncthreads();
        if (tid < 128) {
            float q = qs[tid * 4] + qs[tid * 4 + 1] + qs[tid * 4 + 2] + qs[tid * 4 + 3];
            d.qp[(size_t)(m0 + tid) * 8 + blockIdx.x] = q;
        }
        return;
    }

    // ---- standard epilogue ----
    const int ldc = d.ldc;
#pragma unroll
    for (int mt = 0; mt < 4; mt++)
#pragma unroll
        for (int nt = 0; nt < 4; nt++) {
            int m = m0 + wm * 64 + mt * 16 + (lane >> 2);
            int n = n0 + wn * 32 + nt * 8 + (lane & 3) * 2;
#pragma unroll
            for (int hrow = 0; hrow < 2; hrow++) {
                int mm = m + hrow * 8;
                float2 v = make_float2(acc[mt][nt][hrow * 2] * d.cscale,
                                       acc[mt][nt][hrow * 2 + 1] * d.cscale);
                if (d.addsrc) {
                    float2 s = *(const float2*)(d.addsrc + (size_t)mm * ldc + n);
                    v.x += s.x; v.y += s.y;
                }
                if (d.bias) {
                    float2 b = *(const float2*)(d.bias + n);
                    v.x += b.x; v.y += b.y;
                }
                *(float2*)(d.C + (size_t)mm * ldc + n) = v;
                if (d.emit == 1) {
                    bf16 h0 = __float2bfloat16(v.x), h1 = __float2bfloat16(v.y);
                    d.Chi[(size_t)mm * ldc + n]     = h0;
                    d.Chi[(size_t)mm * ldc + n + 1] = h1;
                    d.Clo[(size_t)mm * ldc + n]     = __float2bfloat16(v.x - __bfloat162float(h0));
                    d.Clo[(size_t)mm * ldc + n + 1] = __float2bfloat16(v.y - __bfloat162float(h1));
                } else if (d.emit == 2) {
                    __half* H = (__half*)d.Chi;
                    H[(size_t)mm * ldc + n]     = __float2half_rn(v.x);
                    H[(size_t)mm * ldc + n + 1] = __float2half_rn(v.y);
                }
            }
        }
}

// ================= prologue kernels =================
// rvf: one read -> passthrough copy + fp16 hi/lo split
__global__ void rvfprep(const float4* __restrict__ src, float4* __restrict__ out,
                        __half2* __restrict__ hi, __half2* __restrict__ lo, long long n4)
{
    for (long long i = (long long)blockIdx.x * blockDim.x + threadIdx.x; i < n4;
         i += (long long)gridDim.x * blockDim.x) {
        float4 v = src[i];
        out[i] = v;
        __half hx = __float2half_rn(v.x), hy = __float2half_rn(v.y);
        __half hz = __float2half_rn(v.z), hw = __float2half_rn(v.w);
        hi[2 * i]     = __halves2half2(hx, hy);
        hi[2 * i + 1] = __halves2half2(hz, hw);
        lo[2 * i]     = __halves2half2(__float2half_rn(v.x - __half2float(hx)),
                                       __float2half_rn(v.y - __half2float(hy)));
        lo[2 * i + 1] = __halves2half2(__float2half_rn(v.z - __half2float(hz)),
                                       __float2half_rn(v.w - __half2float(hw)));
    }
}

struct SplitDesc { const float* src; bf16 *hi, *lo; long long n; };
struct SplitBatch { SplitDesc d[4]; };
__global__ void splitmulti(SplitBatch b)
{
    SplitDesc d = b.d[blockIdx.z];
    for (long long i = (long long)blockIdx.x * blockDim.x + threadIdx.x; i < d.n;
         i += (long long)gridDim.x * blockDim.x) {
        float v = d.src[i];
        bf16 h = __float2bfloat16(v);
        d.hi[i] = h;
        d.lo[i] = __float2bfloat16(v - __bfloat162float(h));
    }
}

__global__ void splitk(const float* __restrict__ src, bf16* __restrict__ hi,
                       bf16* __restrict__ lo, long long n)
{
    for (long long i = (long long)blockIdx.x * blockDim.x + threadIdx.x; i < n;
         i += (long long)gridDim.x * blockDim.x) {
        float v = src[i];
        bf16 h = __float2bfloat16(v);
        hi[i] = h;
        lo[i] = __float2bfloat16(v - __bfloat162float(h));
    }
}

struct TSplitDesc { const float* src; bf16 *hi, *lo; int R; };
struct TSplitBatch { TSplitDesc d[6]; };
__global__ void tsplitmulti(TSplitBatch b)   // src [R][1024] -> dst [1024][R] hi/lo
{
    TSplitDesc d = b.d[blockIdx.z];
    __shared__ float tile[32][33];
    int cx = blockIdx.x * 32, ry = blockIdx.y * 32;
    if (ry >= d.R) return;
    int tx = threadIdx.x, ty = threadIdx.y;  // 32 x 8
#pragma unroll
    for (int i = 0; i < 32; i += 8)
        tile[ty + i][tx] = d.src[(size_t)(ry + ty + i) * Dd + cx + tx];
    __syncthreads();
#pragma unroll
    for (int i = 0; i < 32; i += 8) {
        float v = tile[tx][ty + i];
        bf16 h = __float2bfloat16(v);
        size_t o = (size_t)(cx + ty + i) * d.R + ry + tx;
        d.hi[o] = h;
        d.lo[o] = __float2bfloat16(v - __bfloat162float(h));
    }
}

__global__ void zerobiask(const float* __restrict__ brel, const float* __restrict__ bsbj,
                          const float* __restrict__ bobj, int nn2)
{
    int idx = blockIdx.x * 256 + threadIdx.x;
    if (idx < nn2) g_s.Wmat[idx] = 0.f;
    if (idx < 4 * Dd) {
        int c = idx >> 10, n = idx & 1023;
        g_s.biascat[idx] = (c == 0) ? 0.f : (c == 1 ? brel[n] : (c == 2 ? bsbj[n] : bobj[n]));
    }
}

__global__ void msymk()   // Msym = M + M^T, split to bf16 hi/lo
{
    int idx = blockIdx.x * 256 + threadIdx.x;
    if (idx < Dd * Dd) {
        int i = idx >> 10, j = idx & 1023;
        float v = g_s.M[idx] + g_s.M[j * Dd + i];
        bf16 h = __float2bfloat16(v);
        g_Msymh[idx] = h;
        g_Msyml[idx] = __float2bfloat16(v - __bfloat162float(h));
    }
}

// ================= graph epilogue kernels =================
__global__ void rowdots(float* __restrict__ S1, float* __restrict__ S2)
{
    int n = blockIdx.x, tid = threadIdx.x;
    const float* a  = g_s.X4 + (size_t)n * 4096;
    const float* bp = a + 1024;
    float s1 = 0.f, s2 = 0.f;
    for (int d = tid; d < Dd; d += 256) {
        s1 += a[d]  * (g_s.U1[(size_t)n * Dd + d] + g_s.CW[(size_t)n * Dd + d]);
        s2 += bp[d] * (g_s.U2[(size_t)n * Dd + d] + g_s.GW[(size_t)n * Dd + d]);
    }
    __shared__ float r1[256], r2[256];
    r1[tid] = s1; r2[tid] = s2; __syncthreads();
    for (int st = 128; st > 0; st >>= 1) {
        if (tid < st) { r1[tid] += r1[tid + st]; r2[tid] += r2[tid + st]; }
        __syncthreads();
    }
    if (tid == 0) { S1[n] = 0.5f * r1[0]; S2[n] = 0.5f * r2[0]; }
}

__global__ void logitsk(const int* __restrict__ sbj, const int* __restrict__ obj,
                        int E, int Nn, float scale)
{
    int e = blockIdx.x * 256 + threadIdx.x;
    if (e >= E) return;
    const float* qp = g_s.quadP + (size_t)e * 8;
    float q = qp[0] + qp[1] + qp[2] + qp[3] + qp[4] + qp[5] + qp[6] + qp[7];
    int s = sbj[e], o = obj[e];
    size_t po = (size_t)s * Nn + o;
    g_s.logits[e] = (q + g_s.Pa[po] + g_s.Pb[po] + g_s.Pc[po] + g_s.S1[s] + g_s.S2[o]) * scale;
}

__global__ void segstats(const int* __restrict__ sbj, const int* __restrict__ obj, int E)
{
    int n = blockIdx.x, tid = threadIdx.x;
    const int* ind = (blockIdx.y == 0) ? sbj : obj;
    __shared__ float red[256];
    float m = -1e30f;
    for (int e = tid; e < E; e += 256)
        if (ind[e] == n) m = fmaxf(m, g_s.logits[e]);
    red[tid] = m; __syncthreads();
    for (int st = 128; st > 0; st >>= 1) {
        if (tid < st) red[tid] = fmaxf(red[tid], red[tid + st]);
        __syncthreads();
    }
    float Mv = red[0]; __syncthreads();
    float s = 0.f;
    for (int e = tid; e < E; e += 256)
        if (ind[e] == n) s += expf(g_s.logits[e] - Mv);
    red[tid] = s; __syncthreads();
    for (int st = 128; st > 0; st >>= 1) {
        if (tid < st) red[tid] += red[tid + st];
        __syncthreads();
    }
    if (tid == 0) {
        if (blockIdx.y == 0) { g_s.maxs[n] = Mv; g_s.sums[n] = red[0]; }
        else                 { g_s.maxo[n] = Mv; g_s.sumo[n] = red[0]; }
    }
}

__global__ void wmatk(const int* __restrict__ sbj, const int* __restrict__ obj,
                      int E, int Nn)
{
    int e = blockIdx.x * 256 + threadIdx.x;
    if (e >= E) return;
    float l = g_s.logits[e];
    int s = sbj[e], o = obj[e];
    float ws = expf(l - g_s.maxs[s]) / g_s.sums[s];
    float wo = expf(l - g_s.maxo[o]) / g_s.sumo[o];
    atomicAdd(&g_s.Wmat[(size_t)s * Nn + o], ws);
    atomicAdd(&g_s.Wmat[(size_t)o * Nn + s], wo);
}

__global__ void finalk(const float* __restrict__ vf, float* __restrict__ out, int total)
{
    int idx = blockIdx.x * 256 + threadIdx.x;
    if (idx >= total) return;
    int n = idx >> 10;
    bool inv = (g_s.sums[n] > 0.f) || (g_s.sumo[n] > 0.f);
    out[idx] = vf[idx] + (inv ? g_s.ctxW[idx] : 0.f);
}

// ================= host orchestration =================
static GemmDesc mkdesc(const bf16* Ah, const bf16* Al, int lda,
                       const bf16* Bh, const bf16* Bl, int ldb,
                       float* C, int ldc, const float* addsrc, const float* bias,
                       bf16* Chi, bf16* Clo, int M, int N, int K, float cscale = 1.0f)
{
    GemmDesc d{};
    d.Ah = Ah; d.Al = Al; d.Bh = Bh; d.Bl = Bl;
    d.addsrc = addsrc; d.bias = bias; d.C = C; d.Chi = Chi; d.Clo = Clo;
    d.lda = lda; d.ldb = ldb; d.ldc = ldc; d.K = K;
    d.mb = M / 128; d.nb = N / 128; d.cscale = cscale;
    d.emit = Chi ? 1 : 0;
    return d;
}

template <int MODE>
static void launch_batch(GemmDesc* ds, int nd)
{
    GemmBatch b{};
    int mx = 0, nx = 0;
    for (int i = 0; i < nd; i++) { b.d[i] = ds[i]; if (ds[i].mb > mx) mx = ds[i].mb; if (ds[i].nb > nx) nx = ds[i].nb; }
    for (int i = nd; i < 4; i++) { b.d[i] = ds[0]; }
    dim3 grid(nx, mx, nd);
    mgemm3<MODE><<<grid, 256, SMEM_TOT>>>(b);
}

extern "C" void kernel_launch(void* const* d_in, const int* in_sizes, int n_in,
                              void* d_out, int out_size)
{
    const float* vf   = (const float*)d_in[0];
    const float* rvf  = (const float*)d_in[1];
    const float* Wrel = (const float*)d_in[2];
    const float* brel = (const float*)d_in[3];
    const float* Wsbj = (const float*)d_in[4];
    const float* bsbj = (const float*)d_in[5];
    const float* Wobj = (const float*)d_in[6];
    const float* bobj = (const float*)d_in[7];
    const float* Wctx = (const float*)d_in[8];
    const float* bctx = (const float*)d_in[9];
    const int*   sbj  = (const int*)d_in[10];
    const int*   obj  = (const int*)d_in[11];

    const int Nn = in_sizes[0] / Dd;    // 768
    const int E  = in_sizes[10];        // 24576
    float* out = (float*)d_out;

    cudaFuncSetAttribute(mgemm3<0>, cudaFuncAttributeMaxDynamicSharedMemorySize, SMEM_TOT);
    cudaFuncSetAttribute(mgemm3<1>, cudaFuncAttributeMaxDynamicSharedMemorySize, SMEM_TOT);

    Scratch* S = nullptr;
    cudaGetSymbolAddress((void**)&S, g_s);
    __half *rvf16h, *rvf16l, *Kq16h;
    bf16 *vfh, *vfl, *vfTh, *vfTl, *WcatTh, *WcatTl, *WctxTh, *WctxTl;
    bf16 *Wrrh, *Wrrl, *Wsrh, *Wsrl, *Worh, *Worl, *X4h, *X4l, *Msh, *Msl;
    bf16 *T1h, *T1l, *U1h, *U1l, *U2h, *U2l, *GWh, *GWl, *Wmh, *Wml, *cth, *ctl;
    cudaGetSymbolAddress((void**)&rvf16h, g_rvf16h); cudaGetSymbolAddress((void**)&rvf16l, g_rvf16l);
    cudaGetSymbolAddress((void**)&Kq16h, g_Kq16h);
    cudaGetSymbolAddress((void**)&vfh, g_vfh);     cudaGetSymbolAddress((void**)&vfl, g_vfl);
    cudaGetSymbolAddress((void**)&vfTh, g_vfTh);   cudaGetSymbolAddress((void**)&vfTl, g_vfTl);
    cudaGetSymbolAddress((void**)&WcatTh, g_WcatTh); cudaGetSymbolAddress((void**)&WcatTl, g_WcatTl);
    cudaGetSymbolAddress((void**)&WctxTh, g_WctxTh); cudaGetSymbolAddress((void**)&WctxTl, g_WctxTl);
    cudaGetSymbolAddress((void**)&Wrrh, g_Wrrh);   cudaGetSymbolAddress((void**)&Wrrl, g_Wrrl);
    cudaGetSymbolAddress((void**)&Wsrh, g_Wsrh);   cudaGetSymbolAddress((void**)&Wsrl, g_Wsrl);
    cudaGetSymbolAddress((void**)&Worh, g_Worh);   cudaGetSymbolAddress((void**)&Worl, g_Worl);
    cudaGetSymbolAddress((void**)&X4h, g_X4h);     cudaGetSymbolAddress((void**)&X4l, g_X4l);
    cudaGetSymbolAddress((void**)&Msh, g_Msymh);   cudaGetSymbolAddress((void**)&Msl, g_Msyml);
    cudaGetSymbolAddress((void**)&T1h, g_T1h);     cudaGetSymbolAddress((void**)&T1l, g_T1l);
    cudaGetSymbolAddress((void**)&U1h, g_U1h);     cudaGetSymbolAddress((void**)&U1l, g_U1l);
    cudaGetSymbolAddress((void**)&U2h, g_U2h);     cudaGetSymbolAddress((void**)&U2l, g_U2l);
    cudaGetSymbolAddress((void**)&GWh, g_GWh);     cudaGetSymbolAddress((void**)&GWl, g_GWl);
    cudaGetSymbolAddress((void**)&Wmh, g_Wmath);   cudaGetSymbolAddress((void**)&Wml, g_Wmatl);
    cudaGetSymbolAddress((void**)&cth, g_ctxh);    cudaGetSymbolAddress((void**)&ctl, g_ctxl);

    const float* Wr_r = Wrel + 2 * Dd * Dd;
    const float* Ws_r = Wsbj + Dd * Dd;
    const float* Wo_r = Wobj + Dd * Dd;

    // 1. rvf: fused passthrough copy + fp16 split (one read)
    long long n4 = (long long)E * Dd / 4;
    rvfprep<<<4096, 256>>>((const float4*)rvf, (float4*)out,
                           (__half2*)rvf16h, (__half2*)rvf16l, n4);

    // 2. batched bf16 splits (vf + 3 weight blocks)
    {
        SplitBatch sb{};
        sb.d[0] = { vf,   vfh,  vfl,  (long long)Nn * Dd };
        sb.d[1] = { Wr_r, Wrrh, Wrrl, (long long)Dd * Dd };
        sb.d[2] = { Ws_r, Wsrh, Wsrl, (long long)Dd * Dd };
        sb.d[3] = { Wo_r, Worh, Worl, (long long)Dd * Dd };
        splitmulti<<<dim3(512, 1, 4), 256>>>(sb);
    }
    // 3. batched transposed splits (vfT, WctxT, 4 WcatT blocks)
    {
        TSplitBatch tb{};
        tb.d[0] = { vf,             vfTh,                 vfTl,                 Nn };
        tb.d[1] = { Wctx,           WctxTh,               WctxTl,               Dd };
        tb.d[2] = { Wrel,           WcatTh + 0 * Dd * Dd, WcatTl + 0 * Dd * Dd, Dd };
        tb.d[3] = { Wrel + Dd * Dd, WcatTh + 1 * Dd * Dd, WcatTl + 1 * Dd * Dd, Dd };
        tb.d[4] = { Wsbj,           WcatTh + 2 * Dd * Dd, WcatTl + 2 * Dd * Dd, Dd };
        tb.d[5] = { Wobj,           WcatTh + 3 * Dd * Dd, WcatTl + 3 * Dd * Dd, Dd };
        tsplitmulti<<<dim3(32, 32, 6), dim3(32, 8)>>>(tb);
    }
    // 4. zero Wmat + biascat
    zerobiask<<<(Nn * Nn + 255) / 256, 256>>>(brel, bsbj, bobj, Nn * Nn);

    // batch 1: X4 = vf@WcatT^T + biascat ; M = Ws_r@Wo_r^T
    {
        GemmDesc ds[2] = {
            mkdesc(vfh, vfl, Dd, WcatTh, WcatTl, Dd, S->X4, 4096, nullptr, S->biascat, X4h, X4l, Nn, 4096, Dd),
            mkdesc(Wsrh, Wsrl, Dd, Worh, Worl, Dd, S->M, Dd, nullptr, nullptr, nullptr, nullptr, Dd, Dd, Dd)
        };
        launch_batch<0>(ds, 2);
    }
    msymk<<<(Dd * Dd + 255) / 256, 256>>>();

    // batch 2: CW, GW, Pa=C@G^T, T1=Wr_r@Msym
    {
        GemmDesc ds[4] = {
            mkdesc(X4h + 2048, X4l + 2048, 4096, Worh, Worl, Dd, S->CW, Dd, nullptr, nullptr, nullptr, nullptr, Nn, Dd, Dd),
            mkdesc(X4h + 3072, X4l + 3072, 4096, Wsrh, Wsrl, Dd, S->GW, Dd, nullptr, nullptr, GWh, GWl, Nn, Dd, Dd),
            mkdesc(X4h + 2048, X4l + 2048, 4096, X4h + 3072, X4l + 3072, 4096, S->Pa, Nn, nullptr, nullptr, nullptr, nullptr, Nn, Nn, Dd),
            mkdesc(Wrrh, Wrrl, Dd, Msh, Msl, Dd, S->T1, Dd, nullptr, nullptr, T1h, T1l, Dd, Dd, Dd)
        };
        launch_batch<0>(ds, 4);
    }

    // batch 3: U1=A@Msym+CW, U2=B'@Msym+GW, Kq=0.5*T1@Wr_r^T (emit fp16 hi)
    {
        GemmDesc ds[3] = {
            mkdesc(X4h, X4l, 4096, Msh, Msl, Dd, S->U1, Dd, S->CW, nullptr, U1h, U1l, Nn, Dd, Dd),
            mkdesc(X4h + 1024, X4l + 1024, 4096, Msh, Msl, Dd, S->U2, Dd, S->GW, nullptr, U2h, U2l, Nn, Dd, Dd),
            mkdesc(T1h, T1l, Dd, Wrrh, Wrrl, Dd, S->Kq, Dd, nullptr, nullptr, (bf16*)Kq16h, nullptr, Dd, Dd, Dd, 0.5f)
        };
        ds[2].emit = 2;
        launch_batch<0>(ds, 3);
    }
    rowdots<<<Nn, 256>>>(S->S1, S->S2);

    // batch 4: V1, V2, Pb=U1@B'^T, Pc=A@GW^T
    {
        GemmDesc ds[4] = {
            mkdesc(U1h, U1l, Dd, Wrrh, Wrrl, Dd, S->V1, Dd, nullptr, nullptr, nullptr, nullptr, Nn, Dd, Dd),
            mkdesc(U2h, U2l, Dd, Wrrh, Wrrl, Dd, S->V2, Dd, nullptr, nullptr, nullptr, nullptr, Nn, Dd, Dd),
            mkdesc(U1h, U1l, Dd, X4h + 1024, X4l + 1024, 4096, S->Pb, Nn, nullptr, nullptr, nullptr, nullptr, Nn, Nn, Dd),
            mkdesc(X4h, X4l, 4096, GWh, GWl, Dd, S->Pc, Nn, nullptr, nullptr, nullptr, nullptr, Nn, Nn, Dd)
        };
        launch_batch<0>(ds, 4);
    }

    // batch 5 (fp16 2-term): quad GEMM with fused epilogue -> quadP
    {
        GemmDesc d = mkdesc((const bf16*)rvf16h, (const bf16*)rvf16l, Dd,
                            (const bf16*)Kq16h, nullptr, Dd,
                            nullptr, Dd, nullptr, nullptr,
                            nullptr, nullptr, E, Dd, Dd);
        d.emit = 0;
        d.xptr = rvf; d.sbjp = sbj; d.objp = obj; d.v1p = S->V1; d.v2p = S->V2;
        d.qp = S->quadP;
        launch_batch<1>(&d, 1);
    }

    // logits, softmax stats, mixing matrix
    logitsk<<<(E + 255) / 256, 256>>>(sbj, obj, E, Nn, 1.0f / sqrtf((float)Dd));
    segstats<<<dim3(Nn, 2), 256>>>(sbj, obj, E);
    wmatk<<<(E + 255) / 256, 256>>>(sbj, obj, E, Nn);
    splitk<<<256, 256>>>(S->Wmat, Wmh, Wml, (long long)Nn * Nn);

    // ctx = Wmat@vf ; ctxW = ctx@Wctx + bctx
    {
        GemmDesc d = mkdesc(Wmh, Wml, Nn, vfTh, vfTl, Nn, S->ctx, Dd, nullptr, nullptr,
                            cth, ctl, Nn, Dd, Nn);
        launch_batch<0>(&d, 1);
    }
    {
        GemmDesc d = mkdesc(cth, ctl, Dd, WctxTh, WctxTl, Dd, S->ctxW, Dd, nullptr, bctx,
                            nullptr, nullptr, Nn, Dd, Dd);
        launch_batch<0>(&d, 1);
    }

    // final update
    finalk<<<(Nn * Dd + 255) / 256, 256>>>(vf, out + (size_t)E * Dd, Nn * Dd);
}

// round 9
// speedup vs baseline: 3.7782x; 1.2588x over previous
#include <cuda_runtime.h>
#include <cuda_fp16.h>
#include <math.h>
#include <stdint.h>

#define Dd 1024
#define MAXN 1024
#define MAXE 32768

// ================= static scratch =================
struct Scratch {
    float X4[MAXN * 4 * Dd];      // [A | B' | C | G], ld=4096
    float biascat[4 * Dd];
    float M[Dd * Dd];
    float T1[Dd * Dd];
    float Kq[Dd * Dd];
    float CW[MAXN * Dd];
    float GW[MAXN * Dd];
    float U1[MAXN * Dd];
    float U2[MAXN * Dd];
    float V1[MAXN * Dd];
    float V2[MAXN * Dd];
    float Pa[MAXN * MAXN];
    float Pb[MAXN * MAXN];
    float Pc[MAXN * MAXN];
    float S1[MAXN];
    float S2[MAXN];
    float quadP[(size_t)MAXE * 8];
    float logits[MAXE];
    float maxs[MAXN], sums[MAXN], maxo[MAXN], sumo[MAXN];
    float Wmat[MAXN * MAXN];
    float ctx[MAXN * Dd];
    float ctxW[MAXN * Dd];
};
static __device__ Scratch g_s;

// fp16 hi/lo operand storage
static __device__ __half g_rvfh[(size_t)MAXE * Dd], g_rvfl[(size_t)MAXE * Dd];
static __device__ __half g_vfh[MAXN * Dd],  g_vfl[MAXN * Dd];
static __device__ __half g_vfTh[Dd * MAXN], g_vfTl[Dd * MAXN];
static __device__ __half g_WcatTh[4 * Dd * Dd], g_WcatTl[4 * Dd * Dd];
static __device__ __half g_WctxTh[Dd * Dd], g_WctxTl[Dd * Dd];
static __device__ __half g_Wrrh[Dd * Dd], g_Wrrl[Dd * Dd];
static __device__ __half g_Wsrh[Dd * Dd], g_Wsrl[Dd * Dd];
static __device__ __half g_Worh[Dd * Dd], g_Worl[Dd * Dd];
static __device__ __half g_X4h[MAXN * 4 * Dd], g_X4l[MAXN * 4 * Dd];
static __device__ __half g_Msymh[Dd * Dd], g_Msyml[Dd * Dd];
static __device__ __half g_T1h[Dd * Dd], g_T1l[Dd * Dd];
static __device__ __half g_Kqh[Dd * Dd], g_Kql[Dd * Dd];
static __device__ __half g_U1h[MAXN * Dd], g_U1l[MAXN * Dd];
static __device__ __half g_U2h[MAXN * Dd], g_U2l[MAXN * Dd];
static __device__ __half g_GWh[MAXN * Dd], g_GWl[MAXN * Dd];
static __device__ __half g_Wmath[MAXN * MAXN], g_Wmatl[MAXN * MAXN];
static __device__ __half g_ctxh[MAXN * Dd], g_ctxl[MAXN * Dd];

// ================= PTX helpers =================
__device__ __forceinline__ uint32_t smem_u32(const void* p) {
    return (uint32_t)__cvta_generic_to_shared(p);
}
__device__ __forceinline__ void ldsm4(uint32_t& r0, uint32_t& r1, uint32_t& r2, uint32_t& r3, uint32_t a) {
    asm volatile("ldmatrix.sync.aligned.m8n8.x4.shared.b16 {%0,%1,%2,%3}, [%4];"
                 : "=r"(r0), "=r"(r1), "=r"(r2), "=r"(r3) : "r"(a));
}
__device__ __forceinline__ void mma_fp(float* d, const uint32_t* a, const uint32_t* b) {
    asm volatile("mma.sync.aligned.m16n8k16.row.col.f32.f16.f16.f32 "
                 "{%0,%1,%2,%3}, {%4,%5,%6,%7}, {%8,%9}, {%0,%1,%2,%3};"
                 : "+f"(d[0]), "+f"(d[1]), "+f"(d[2]), "+f"(d[3])
                 : "r"(a[0]), "r"(a[1]), "r"(a[2]), "r"(a[3]), "r"(b[0]), "r"(b[1]));
}
__device__ __forceinline__ void cpasync16(uint32_t saddr, const void* gaddr) {
    asm volatile("cp.async.cg.shared.global [%0], [%1], 16;" :: "r"(saddr), "l"(gaddr));
}
#define CP_COMMIT() asm volatile("cp.async.commit_group;" ::: "memory")
#define CP_WAIT(N)  asm volatile("cp.async.wait_group %0;" :: "n"(N) : "memory")

// ================= batched fp16 2-term mma.sync GEMM =================
// C = cscale*(A @ B^T) (+addsrc)(+bias). A = exact hi+lo fp16, B = hi fp16 only.
// Product: (ah+al)*bh via 2 MMAs per tile. emit: 0 none, 1 fp16 hi/lo.
// Quad mode (qp != null): quadP[m*8+blkx] = sum_n (val + V1[sbj[m]] + V2[obj[m]])*x[m,n].
// BM=BN=128, BK=64, 2-stage cp.async double buffer, 2 CTAs/SM.
struct GemmDesc {
    const __half *Ah, *Al, *Bh;
    const float *addsrc, *bias;
    float* C;
    __half *Chi, *Clo;
    const float* xptr;
    const int *sbjp, *objp;
    const float *v1p, *v2p;
    float* qp;
    int lda, ldb, ldc, K, mb, nb;
    float cscale;
    int emit;
};
struct GemmBatch { GemmDesc d[4]; };

#define TILE_B    (128 * 144)              // 18432 B per matrix tile (pitch 144)
#define STAGE_B   (3 * TILE_B)             // Ah, Al, Bh = 55296
#define SMEM_TOT  (2 * STAGE_B)            // 110592 -> 2 CTAs/SM

__global__ __launch_bounds__(256, 2)
void mgemm3(GemmBatch batch)
{
    extern __shared__ char smem[];
    const GemmDesc d = batch.d[blockIdx.z];
    if ((int)blockIdx.y >= d.mb || (int)blockIdx.x >= d.nb) return;

    const int tid = threadIdx.x;
    const int lane = tid & 31, warp = tid >> 5;
    const int wm = warp & 1, wn = warp >> 1;
    const int m0 = blockIdx.y * 128, n0 = blockIdx.x * 128;
    const int l8 = lane & 7, grp = lane >> 3;
    const int lda = d.lda, ldb = d.ldb;
    const __half *Ah = d.Ah, *Al = d.Al, *Bh = d.Bh;
    const int nchunks = d.K >> 6;

    auto load_stage = [&](int stg, int chunk) {
        const uint32_t sbase = smem_u32(smem) + stg * STAGE_B;
        const int k0 = chunk << 6;
#pragma unroll
        for (int it = 0; it < 4; it++) {
            int linear = tid + it * 256;
            int row = linear >> 3, seg = (linear & 7) << 3;
            uint32_t soff = (uint32_t)(row * 144 + seg * 2);
            size_t ga = (size_t)(m0 + row) * lda + k0 + seg;
            cpasync16(sbase + soff,              Ah + ga);
            cpasync16(sbase + TILE_B + soff,     Al + ga);
            size_t gb = (size_t)(n0 + row) * ldb + k0 + seg;
            cpasync16(sbase + 2 * TILE_B + soff, Bh + gb);
        }
    };

    float acc[4][4][4] = {};

    load_stage(0, 0);
    CP_COMMIT();

    int st = 0;
    for (int i = 0; i < nchunks; i++) {
        if (i + 1 < nchunks) {
            load_stage(st ^ 1, i + 1);
            CP_COMMIT();
            CP_WAIT(1);
        } else {
            CP_WAIT(0);
        }
        __syncthreads();

        const char* base = smem + st * STAGE_B;
#pragma unroll
        for (int kk = 0; kk < 4; kk++) {
            const int kcol = kk * 16;
            uint32_t ah[4][4], al[4][4], bh[4][2];
#pragma unroll
            for (int mt = 0; mt < 4; mt++) {
                int row = wm * 64 + mt * 16 + l8 + ((grp & 1) << 3);
                int col = kcol + ((grp >> 1) << 3);
                uint32_t a0 = smem_u32(base + row * 144 + col * 2);
                ldsm4(ah[mt][0], ah[mt][1], ah[mt][2], ah[mt][3], a0);
                ldsm4(al[mt][0], al[mt][1], al[mt][2], al[mt][3], a0 + TILE_B);
            }
#pragma unroll
            for (int ntp = 0; ntp < 2; ntp++) {
                int row = wn * 32 + ntp * 16 + ((grp >> 1) << 3) + l8;
                int col = kcol + ((grp & 1) << 3);
                uint32_t b0 = smem_u32(base + 2 * TILE_B + row * 144 + col * 2);
                ldsm4(bh[2 * ntp][0], bh[2 * ntp][1], bh[2 * ntp + 1][0], bh[2 * ntp + 1][1], b0);
            }
            // split terms OUTERMOST: same-acc reuse distance = 16 MMAs
#pragma unroll
            for (int mt = 0; mt < 4; mt++)
#pragma unroll
                for (int nt = 0; nt < 4; nt++) mma_fp(acc[mt][nt], ah[mt], bh[nt]);
#pragma unroll
            for (int mt = 0; mt < 4; mt++)
#pragma unroll
                for (int nt = 0; nt < 4; nt++) mma_fp(acc[mt][nt], al[mt], bh[nt]);
        }
        __syncthreads();
        st ^= 1;
    }

    if (d.qp) {
        // fused quadratic epilogue: per-row partial of (val + V1[s] + V2[o]) . x
        float pt[4], pb[4];
#pragma unroll
        for (int mt = 0; mt < 4; mt++) {
            int mtop = m0 + wm * 64 + mt * 16 + (lane >> 2);
            int mbot = mtop + 8;
            int s1 = d.sbjp[mtop], o1 = d.objp[mtop];
            int s2 = d.sbjp[mbot], o2 = d.objp[mbot];
            float at = 0.f, ab = 0.f;
#pragma unroll
            for (int nt = 0; nt < 4; nt++) {
                int n = n0 + wn * 32 + nt * 8 + (lane & 3) * 2;
                float2 xt = *(const float2*)(d.xptr + (size_t)mtop * lda + n);
                float2 xb = *(const float2*)(d.xptr + (size_t)mbot * lda + n);
                float2 v1t = *(const float2*)(d.v1p + (size_t)s1 * Dd + n);
                float2 v2t = *(const float2*)(d.v2p + (size_t)o1 * Dd + n);
                float2 v1b = *(const float2*)(d.v1p + (size_t)s2 * Dd + n);
                float2 v2b = *(const float2*)(d.v2p + (size_t)o2 * Dd + n);
                at += (acc[mt][nt][0] + v1t.x + v2t.x) * xt.x
                    + (acc[mt][nt][1] + v1t.y + v2t.y) * xt.y;
                ab += (acc[mt][nt][2] + v1b.x + v2b.x) * xb.x
                    + (acc[mt][nt][3] + v1b.y + v2b.y) * xb.y;
            }
            at += __shfl_xor_sync(0xffffffffu, at, 1);
            at += __shfl_xor_sync(0xffffffffu, at, 2);
            ab += __shfl_xor_sync(0xffffffffu, ab, 1);
            ab += __shfl_xor_sync(0xffffffffu, ab, 2);
            pt[mt] = at; pb[mt] = ab;
        }
        __syncthreads();
        float* qs = (float*)smem;           // [128][4]
        if ((lane & 3) == 0) {
#pragma unroll
            for (int mt = 0; mt < 4; mt++) {
                int rt = wm * 64 + mt * 16 + (lane >> 2);
                qs[rt * 4 + wn] = pt[mt];
                qs[(rt + 8) * 4 + wn] = pb[mt];
            }
        }
        __syncthreads();
        if (tid < 128) {
            float q = qs[tid * 4] + qs[tid * 4 + 1] + qs[tid * 4 + 2] + qs[tid * 4 + 3];
            d.qp[(size_t)(m0 + tid) * 8 + blockIdx.x] = q;
        }
        return;
    }

    // ---- standard epilogue ----
    const int ldc = d.ldc;
#pragma unroll
    for (int mt = 0; mt < 4; mt++)
#pragma unroll
        for (int nt = 0; nt < 4; nt++) {
            int m = m0 + wm * 64 + mt * 16 + (lane >> 2);
            int n = n0 + wn * 32 + nt * 8 + (lane & 3) * 2;
#pragma unroll
            for (int hrow = 0; hrow < 2; hrow++) {
                int mm = m + hrow * 8;
                float2 v = make_float2(acc[mt][nt][hrow * 2] * d.cscale,
                                       acc[mt][nt][hrow * 2 + 1] * d.cscale);
                if (d.addsrc) {
                    float2 s = *(const float2*)(d.addsrc + (size_t)mm * ldc + n);
                    v.x += s.x; v.y += s.y;
                }
                if (d.bias) {
                    float2 b = *(const float2*)(d.bias + n);
                    v.x += b.x; v.y += b.y;
                }
                *(float2*)(d.C + (size_t)mm * ldc + n) = v;
                if (d.emit) {
                    __half h0 = __float2half_rn(v.x), h1 = __float2half_rn(v.y);
                    d.Chi[(size_t)mm * ldc + n]     = h0;
                    d.Chi[(size_t)mm * ldc + n + 1] = h1;
                    d.Clo[(size_t)mm * ldc + n]     = __float2half_rn(v.x - __half2float(h0));
                    d.Clo[(size_t)mm * ldc + n + 1] = __float2half_rn(v.y - __half2float(h1));
                }
            }
        }
}

// ================= prologue kernels =================
// rvf: one read -> passthrough copy + fp16 hi/lo split; also zero Wmat + build biascat
__global__ void rvfprep(const float4* __restrict__ src, float4* __restrict__ out,
                        __half2* __restrict__ hi, __half2* __restrict__ lo, long long n4,
                        float* __restrict__ wmat, int nn2,
                        const float* __restrict__ brel, const float* __restrict__ bsbj,
                        const float* __restrict__ bobj, float* __restrict__ biascat)
{
    long long stride = (long long)gridDim.x * blockDim.x;
    long long t0 = (long long)blockIdx.x * blockDim.x + threadIdx.x;
    for (long long i = t0; i < n4; i += stride) {
        float4 v = src[i];
        out[i] = v;
        __half hx = __float2half_rn(v.x), hy = __float2half_rn(v.y);
        __half hz = __float2half_rn(v.z), hw = __float2half_rn(v.w);
        hi[2 * i]     = __halves2half2(hx, hy);
        hi[2 * i + 1] = __halves2half2(hz, hw);
        lo[2 * i]     = __halves2half2(__float2half_rn(v.x - __half2float(hx)),
                                       __float2half_rn(v.y - __half2float(hy)));
        lo[2 * i + 1] = __halves2half2(__float2half_rn(v.z - __half2float(hz)),
                                       __float2half_rn(v.w - __half2float(hw)));
    }
    for (long long i = t0; i < nn2; i += stride) wmat[i] = 0.f;
    for (long long i = t0; i < 4 * Dd; i += stride) {
        int c = (int)i >> 10, n = (int)i & 1023;
        biascat[i] = (c == 0) ? 0.f : (c == 1 ? brel[n] : (c == 2 ? bsbj[n] : bobj[n]));
    }
}

struct SplitDesc { const float* src; __half *hi, *lo; long long n; };
struct SplitBatch { SplitDesc d[4]; };
__global__ void splitmulti(SplitBatch b)    // vectorized: float4 in, half2-packed out
{
    SplitDesc d = b.d[blockIdx.z];
    long long n4 = d.n >> 2;
    __half2* hi2 = (__half2*)d.hi;
    __half2* lo2 = (__half2*)d.lo;
    const float4* s4 = (const float4*)d.src;
    for (long long i = (long long)blockIdx.x * blockDim.x + threadIdx.x; i < n4;
         i += (long long)gridDim.x * blockDim.x) {
        float4 v = s4[i];
        __half hx = __float2half_rn(v.x), hy = __float2half_rn(v.y);
        __half hz = __float2half_rn(v.z), hw = __float2half_rn(v.w);
        hi2[2 * i]     = __halves2half2(hx, hy);
        hi2[2 * i + 1] = __halves2half2(hz, hw);
        lo2[2 * i]     = __halves2half2(__float2half_rn(v.x - __half2float(hx)),
                                        __float2half_rn(v.y - __half2float(hy)));
        lo2[2 * i + 1] = __halves2half2(__float2half_rn(v.z - __half2float(hz)),
                                        __float2half_rn(v.w - __half2float(hw)));
    }
}

__global__ void splitk(const float* __restrict__ src, __half* __restrict__ hi,
                       __half* __restrict__ lo, long long n)
{
    long long n4 = n >> 2;
    __half2* hi2 = (__half2*)hi;
    __half2* lo2 = (__half2*)lo;
    const float4* s4 = (const float4*)src;
    for (long long i = (long long)blockIdx.x * blockDim.x + threadIdx.x; i < n4;
         i += (long long)gridDim.x * blockDim.x) {
        float4 v = s4[i];
        __half hx = __float2half_rn(v.x), hy = __float2half_rn(v.y);
        __half hz = __float2half_rn(v.z), hw = __float2half_rn(v.w);
        hi2[2 * i]     = __halves2half2(hx, hy);
        hi2[2 * i + 1] = __halves2half2(hz, hw);
        lo2[2 * i]     = __halves2half2(__float2half_rn(v.x - __half2float(hx)),
                                        __float2half_rn(v.y - __half2float(hy)));
        lo2[2 * i + 1] = __halves2half2(__float2half_rn(v.z - __half2float(hz)),
                                        __float2half_rn(v.w - __half2float(hw)));
    }
}

struct TSplitDesc { const float* src; __half *hi, *lo; int R; };
struct TSplitBatch { TSplitDesc d[6]; };
__global__ void tsplitmulti(TSplitBatch b)   // src [R][1024] -> dst [1024][R] hi/lo
{
    TSplitDesc d = b.d[blockIdx.z];
    __shared__ float tile[32][33];
    int cx = blockIdx.x * 32, ry = blockIdx.y * 32;
    if (ry >= d.R) return;
    int tx = threadIdx.x, ty = threadIdx.y;  // 32 x 8
#pragma unroll
    for (int i = 0; i < 32; i += 8)
        tile[ty + i][tx] = d.src[(size_t)(ry + ty + i) * Dd + cx + tx];
    __syncthreads();
#pragma unroll
    for (int i = 0; i < 32; i += 8) {
        float v = tile[tx][ty + i];
        __half h = __float2half_rn(v);
        size_t o = (size_t)(cx + ty + i) * d.R + ry + tx;
        d.hi[o] = h;
        d.lo[o] = __float2half_rn(v - __half2float(h));
    }
}

__global__ void msymk()   // Msym = M + M^T, split to fp16 hi/lo
{
    int idx = blockIdx.x * 256 + threadIdx.x;
    if (idx < Dd * Dd) {
        int i = idx >> 10, j = idx & 1023;
        float v = g_s.M[idx] + g_s.M[j * Dd + i];
        __half h = __float2half_rn(v);
        g_Msymh[idx] = h;
        g_Msyml[idx] = __float2half_rn(v - __half2float(h));
    }
}

// ================= graph epilogue kernels =================
__global__ void rowdots(float* __restrict__ S1, float* __restrict__ S2)
{
    int n = blockIdx.x, tid = threadIdx.x;
    const float* a  = g_s.X4 + (size_t)n * 4096;
    const float* bp = a + 1024;
    float s1 = 0.f, s2 = 0.f;
    for (int d = tid; d < Dd; d += 256) {
        s1 += a[d]  * (g_s.U1[(size_t)n * Dd + d] + g_s.CW[(size_t)n * Dd + d]);
        s2 += bp[d] * (g_s.U2[(size_t)n * Dd + d] + g_s.GW[(size_t)n * Dd + d]);
    }
    __shared__ float r1[256], r2[256];
    r1[tid] = s1; r2[tid] = s2; __syncthreads();
    for (int st = 128; st > 0; st >>= 1) {
        if (tid < st) { r1[tid] += r1[tid + st]; r2[tid] += r2[tid + st]; }
        __syncthreads();
    }
    if (tid == 0) { S1[n] = 0.5f * r1[0]; S2[n] = 0.5f * r2[0]; }
}

__global__ void logitsk(const int* __restrict__ sbj, const int* __restrict__ obj,
                        int E, int Nn, float scale)
{
    int e = blockIdx.x * 256 + threadIdx.x;
    if (e >= E) return;
    const float* qp = g_s.quadP + (size_t)e * 8;
    float q = qp[0] + qp[1] + qp[2] + qp[3] + qp[4] + qp[5] + qp[6] + qp[7];
    int s = sbj[e], o = obj[e];
    size_t po = (size_t)s * Nn + o;
    g_s.logits[e] = (q + g_s.Pa[po] + g_s.Pb[po] + g_s.Pc[po] + g_s.S1[s] + g_s.S2[o]) * scale;
}

__global__ void segstats(const int* __restrict__ sbj, const int* __restrict__ obj, int E)
{
    int n = blockIdx.x, tid = threadIdx.x;
    const int* ind = (blockIdx.y == 0) ? sbj : obj;
    __shared__ float red[256];
    float m = -1e30f;
    for (int e = tid; e < E; e += 256)
        if (ind[e] == n) m = fmaxf(m, g_s.logits[e]);
    red[tid] = m; __syncthreads();
    for (int st = 128; st > 0; st >>= 1) {
        if (tid < st) red[tid] = fmaxf(red[tid], red[tid + st]);
        __syncthreads();
    }
    float Mv = red[0]; __syncthreads();
    float s = 0.f;
    for (int e = tid; e < E; e += 256)
        if (ind[e] == n) s += expf(g_s.logits[e] - Mv);
    red[tid] = s; __syncthreads();
    for (int st = 128; st > 0; st >>= 1) {
        if (tid < st) red[tid] += red[tid + st];
        __syncthreads();
    }
    if (tid == 0) {
        if (blockIdx.y == 0) { g_s.maxs[n] = Mv; g_s.sums[n] = red[0]; }
        else                 { g_s.maxo[n] = Mv; g_s.sumo[n] = red[0]; }
    }
}

__global__ void wmatk(const int* __restrict__ sbj, const int* __restrict__ obj,
                      int E, int Nn)
{
    int e = blockIdx.x * 256 + threadIdx.x;
    if (e >= E) return;
    float l = g_s.logits[e];
    int s = sbj[e], o = obj[e];
    float ws = expf(l - g_s.maxs[s]) / g_s.sums[s];
    float wo = expf(l - g_s.maxo[o]) / g_s.sumo[o];
    atomicAdd(&g_s.Wmat[(size_t)s * Nn + o], ws);
    atomicAdd(&g_s.Wmat[(size_t)o * Nn + s], wo);
}

__global__ void finalk(const float* __restrict__ vf, float* __restrict__ out, int total)
{
    int idx = blockIdx.x * 256 + threadIdx.x;
    if (idx >= total) return;
    int n = idx >> 10;
    bool inv = (g_s.sums[n] > 0.f) || (g_s.sumo[n] > 0.f);
    out[idx] = vf[idx] + (inv ? g_s.ctxW[idx] : 0.f);
}

// ================= host orchestration =================
static GemmDesc mkdesc(const __half* Ah, const __half* Al, int lda,
                       const __half* Bh, int ldb,
                       float* C, int ldc, const float* addsrc, const float* bias,
                       __half* Chi, __half* Clo, int M, int N, int K, float cscale = 1.0f)
{
    GemmDesc d{};
    d.Ah = Ah; d.Al = Al; d.Bh = Bh;
    d.addsrc = addsrc; d.bias = bias; d.C = C; d.Chi = Chi; d.Clo = Clo;
    d.lda = lda; d.ldb = ldb; d.ldc = ldc; d.K = K;
    d.mb = M / 128; d.nb = N / 128; d.cscale = cscale;
    d.emit = Chi ? 1 : 0;
    return d;
}

static void launch_batch(GemmDesc* ds, int nd)
{
    GemmBatch b{};
    int mx = 0, nx = 0;
    for (int i = 0; i < nd; i++) { b.d[i] = ds[i]; if (ds[i].mb > mx) mx = ds[i].mb; if (ds[i].nb > nx) nx = ds[i].nb; }
    for (int i = nd; i < 4; i++) { b.d[i] = ds[0]; }
    dim3 grid(nx, mx, nd);
    mgemm3<<<grid, 256, SMEM_TOT>>>(b);
}

extern "C" void kernel_launch(void* const* d_in, const int* in_sizes, int n_in,
                              void* d_out, int out_size)
{
    const float* vf   = (const float*)d_in[0];
    const float* rvf  = (const float*)d_in[1];
    const float* Wrel = (const float*)d_in[2];
    const float* brel = (const float*)d_in[3];
    const float* Wsbj = (const float*)d_in[4];
    const float* bsbj = (const float*)d_in[5];
    const float* Wobj = (const float*)d_in[6];
    const float* bobj = (const float*)d_in[7];
    const float* Wctx = (const float*)d_in[8];
    const float* bctx = (const float*)d_in[9];
    const int*   sbj  = (const int*)d_in[10];
    const int*   obj  = (const int*)d_in[11];

    const int Nn = in_sizes[0] / Dd;    // 768
    const int E  = in_sizes[10];        // 24576
    float* out = (float*)d_out;

    cudaFuncSetAttribute(mgemm3, cudaFuncAttributeMaxDynamicSharedMemorySize, SMEM_TOT);

    Scratch* S = nullptr;
    cudaGetSymbolAddress((void**)&S, g_s);
    __half *rvfh, *rvfl, *vfh, *vfl, *vfTh, *vfTl, *WcatTh, *WcatTl, *WctxTh, *WctxTl;
    __half *Wrrh, *Wrrl, *Wsrh, *Wsrl, *Worh, *Worl, *X4h, *X4l, *Msh, *Msl;
    __half *T1h, *T1l, *Kqh, *Kql, *U1h, *U1l, *U2h, *U2l, *GWh, *GWl, *Wmh, *Wml, *cth, *ctl;
    cudaGetSymbolAddress((void**)&rvfh, g_rvfh);   cudaGetSymbolAddress((void**)&rvfl, g_rvfl);
    cudaGetSymbolAddress((void**)&vfh, g_vfh);     cudaGetSymbolAddress((void**)&vfl, g_vfl);
    cudaGetSymbolAddress((void**)&vfTh, g_vfTh);   cudaGetSymbolAddress((void**)&vfTl, g_vfTl);
    cudaGetSymbolAddress((void**)&WcatTh, g_WcatTh); cudaGetSymbolAddress((void**)&WcatTl, g_WcatTl);
    cudaGetSymbolAddress((void**)&WctxTh, g_WctxTh); cudaGetSymbolAddress((void**)&WctxTl, g_WctxTl);
    cudaGetSymbolAddress((void**)&Wrrh, g_Wrrh);   cudaGetSymbolAddress((void**)&Wrrl, g_Wrrl);
    cudaGetSymbolAddress((void**)&Wsrh, g_Wsrh);   cudaGetSymbolAddress((void**)&Wsrl, g_Wsrl);
    cudaGetSymbolAddress((void**)&Worh, g_Worh);   cudaGetSymbolAddress((void**)&Worl, g_Worl);
    cudaGetSymbolAddress((void**)&X4h, g_X4h);     cudaGetSymbolAddress((void**)&X4l, g_X4l);
    cudaGetSymbolAddress((void**)&Msh, g_Msymh);   cudaGetSymbolAddress((void**)&Msl, g_Msyml);
    cudaGetSymbolAddress((void**)&T1h, g_T1h);     cudaGetSymbolAddress((void**)&T1l, g_T1l);
    cudaGetSymbolAddress((void**)&Kqh, g_Kqh);     cudaGetSymbolAddress((void**)&Kql, g_Kql);
    cudaGetSymbolAddress((void**)&U1h, g_U1h);     cudaGetSymbolAddress((void**)&U1l, g_U1l);
    cudaGetSymbolAddress((void**)&U2h, g_U2h);     cudaGetSymbolAddress((void**)&U2l, g_U2l);
    cudaGetSymbolAddress((void**)&GWh, g_GWh);     cudaGetSymbolAddress((void**)&GWl, g_GWl);
    cudaGetSymbolAddress((void**)&Wmh, g_Wmath);   cudaGetSymbolAddress((void**)&Wml, g_Wmatl);
    cudaGetSymbolAddress((void**)&cth, g_ctxh);    cudaGetSymbolAddress((void**)&ctl, g_ctxl);

    const float* Wr_r = Wrel + 2 * Dd * Dd;
    const float* Ws_r = Wsbj + Dd * Dd;
    const float* Wo_r = Wobj + Dd * Dd;

    // 1. rvf: fused passthrough copy + fp16 split + Wmat zero + biascat
    long long n4 = (long long)E * Dd / 4;
    rvfprep<<<4096, 256>>>((const float4*)rvf, (float4*)out,
                           (__half2*)rvfh, (__half2*)rvfl, n4,
                           S->Wmat, Nn * Nn, brel, bsbj, bobj, S->biascat);

    // 2. batched fp16 splits (vf + 3 weight blocks)
    {
        SplitBatch sb{};
        sb.d[0] = { vf,   vfh,  vfl,  (long long)Nn * Dd };
        sb.d[1] = { Wr_r, Wrrh, Wrrl, (long long)Dd * Dd };
        sb.d[2] = { Ws_r, Wsrh, Wsrl, (long long)Dd * Dd };
        sb.d[3] = { Wo_r, Worh, Worl, (long long)Dd * Dd };
        splitmulti<<<dim3(256, 1, 4), 256>>>(sb);
    }
    // 3. batched transposed splits (vfT, WctxT, 4 WcatT blocks)
    {
        TSplitBatch tb{};
        tb.d[0] = { vf,             vfTh,                 vfTl,                 Nn };
        tb.d[1] = { Wctx,           WctxTh,               WctxTl,               Dd };
        tb.d[2] = { Wrel,           WcatTh + 0 * Dd * Dd, WcatTl + 0 * Dd * Dd, Dd };
        tb.d[3] = { Wrel + Dd * Dd, WcatTh + 1 * Dd * Dd, WcatTl + 1 * Dd * Dd, Dd };
        tb.d[4] = { Wsbj,           WcatTh + 2 * Dd * Dd, WcatTl + 2 * Dd * Dd, Dd };
        tb.d[5] = { Wobj,           WcatTh + 3 * Dd * Dd, WcatTl + 3 * Dd * Dd, Dd };
        tsplitmulti<<<dim3(32, 32, 6), dim3(32, 8)>>>(tb);
    }

    // batch 1: X4 = vf@WcatT^T + biascat ; M = Ws_r@Wo_r^T
    {
        GemmDesc ds[2] = {
            mkdesc(vfh, vfl, Dd, WcatTh, Dd, S->X4, 4096, nullptr, S->biascat, X4h, X4l, Nn, 4096, Dd),
            mkdesc(Wsrh, Wsrl, Dd, Worh, Dd, S->M, Dd, nullptr, nullptr, nullptr, nullptr, Dd, Dd, Dd)
        };
        launch_batch(ds, 2);
    }
    msymk<<<(Dd * Dd + 255) / 256, 256>>>();

    // batch 2: CW, GW, Pa=C@G^T, T1=Wr_r@Msym
    {
        GemmDesc ds[4] = {
            mkdesc(X4h + 2048, X4l + 2048, 4096, Worh, Dd, S->CW, Dd, nullptr, nullptr, nullptr, nullptr, Nn, Dd, Dd),
            mkdesc(X4h + 3072, X4l + 3072, 4096, Wsrh, Dd, S->GW, Dd, nullptr, nullptr, GWh, GWl, Nn, Dd, Dd),
            mkdesc(X4h + 2048, X4l + 2048, 4096, X4h + 3072, 4096, S->Pa, Nn, nullptr, nullptr, nullptr, nullptr, Nn, Nn, Dd),
            mkdesc(Wrrh, Wrrl, Dd, Msh, Dd, S->T1, Dd, nullptr, nullptr, T1h, T1l, Dd, Dd, Dd)
        };
        launch_batch(ds, 4);
    }

    // batch 3: U1=A@Msym+CW, U2=B'@Msym+GW, Kq=0.5*T1@Wr_r^T
    {
        GemmDesc ds[3] = {
            mkdesc(X4h, X4l, 4096, Msh, Dd, S->U1, Dd, S->CW, nullptr, U1h, U1l, Nn, Dd, Dd),
            mkdesc(X4h + 1024, X4l + 1024, 4096, Msh, Dd, S->U2, Dd, S->GW, nullptr, U2h, U2l, Nn, Dd, Dd),
            mkdesc(T1h, T1l, Dd, Wrrh, Dd, S->Kq, Dd, nullptr, nullptr, Kqh, Kql, Dd, Dd, Dd, 0.5f)
        };
        launch_batch(ds, 3);
    }
    rowdots<<<Nn, 256>>>(S->S1, S->S2);

    // batch 4: V1, V2, Pb=U1@B'^T, Pc=A@GW^T
    {
        GemmDesc ds[4] = {
            mkdesc(U1h, U1l, Dd, Wrrh, Dd, S->V1, Dd, nullptr, nullptr, nullptr, nullptr, Nn, Dd, Dd),
            mkdesc(U2h, U2l, Dd, Wrrh, Dd, S->V2, Dd, nullptr, nullptr, nullptr, nullptr, Nn, Dd, Dd),
            mkdesc(U1h, U1l, Dd, X4h + 1024, 4096, S->Pb, Nn, nullptr, nullptr, nullptr, nullptr, Nn, Nn, Dd),
            mkdesc(X4h, X4l, 4096, GWh, Dd, S->Pc, Nn, nullptr, nullptr, nullptr, nullptr, Nn, Nn, Dd)
        };
        launch_batch(ds, 4);
    }

    // batch 5: quad GEMM (rvf @ Kq) with fused epilogue -> quadP
    {
        GemmDesc d = mkdesc(rvfh, rvfl, Dd, Kqh, Dd, nullptr, Dd, nullptr, nullptr,
                            nullptr, nullptr, E, Dd, Dd);
        d.emit = 0;
        d.xptr = rvf; d.sbjp = sbj; d.objp = obj; d.v1p = S->V1; d.v2p = S->V2;
        d.qp = S->quadP;
        launch_batch(&d, 1);
    }

    // logits, softmax stats, mixing matrix
    logitsk<<<(E + 255) / 256, 256>>>(sbj, obj, E, Nn, 1.0f / sqrtf((float)Dd));
    segstats<<<dim3(Nn, 2), 256>>>(sbj, obj, E);
    wmatk<<<(E + 255) / 256, 256>>>(sbj, obj, E, Nn);
    splitk<<<256, 256>>>(S->Wmat, Wmh, Wml, (long long)Nn * Nn);

    // ctx = Wmat@vf ; ctxW = ctx@Wctx + bctx
    {
        GemmDesc d = mkdesc(Wmh, Wml, Nn, vfTh, Nn, S->ctx, Dd, nullptr, nullptr,
                            cth, ctl, Nn, Dd, Nn);
        launch_batch(&d, 1);
    }
    {
        GemmDesc d = mkdesc(cth, ctl, Dd, WctxTh, Dd, S->ctxW, Dd, nullptr, bctx,
                            nullptr, nullptr, Nn, Dd, Dd);
        launch_batch(&d, 1);
    }

    // final update
    finalk<<<(Nn * Dd + 255) / 256, 256>>>(vf, out + (size_t)E * Dd, Nn * Dd);
}

// round 10
// speedup vs baseline: 4.0527x; 1.0727x over previous
#include <cuda_runtime.h>
#include <cuda_fp16.h>
#include <math.h>
#include <stdint.h>

#define Dd 1024
#define MAXN 1024
#define MAXE 32768

// ================= static scratch =================
struct Scratch {
    float X4[MAXN * 4 * Dd];      // [A | B' | C | G], ld=4096
    float biascat[4 * Dd];
    float M[Dd * Dd];
    float T1[Dd * Dd];
    float Kq[Dd * Dd];
    float W2[Dd * Dd];            // Wrr @ Wor
    float W3[Dd * Dd];            // Wrr @ Wsr
    float VWT[Dd * MAXN];         // (vf @ Wctx)^T
    float CW[MAXN * Dd];
    float GW[MAXN * Dd];
    float U1[MAXN * Dd];
    float U2[MAXN * Dd];
    float V1[MAXN * Dd];          // also holds V1a intermediately
    float V2[MAXN * Dd];          // also holds V2a intermediately
    float Pa[MAXN * MAXN];
    float Pb[MAXN * MAXN];
    float Pc[MAXN * MAXN];
    float S1[MAXN];
    float S2[MAXN];
    float quadP[(size_t)MAXE * 8];
    float logits[MAXE];
    float maxs[MAXN], sums[MAXN], maxo[MAXN], sumo[MAXN];
    float Wmat[MAXN * MAXN];
};
static __device__ Scratch g_s;

// fp16 hi/lo operand storage
static __device__ __half g_rvfh[(size_t)MAXE * Dd], g_rvfl[(size_t)MAXE * Dd];
static __device__ __half g_vfh[MAXN * Dd],  g_vfl[MAXN * Dd];
static __device__ __half g_WcatTh[4 * Dd * Dd], g_WcatTl[4 * Dd * Dd];
static __device__ __half g_WctxTh[Dd * Dd], g_WctxTl[Dd * Dd];
static __device__ __half g_Wrrh[Dd * Dd], g_Wrrl[Dd * Dd];
static __device__ __half g_Wsrh[Dd * Dd], g_Wsrl[Dd * Dd];
static __device__ __half g_Worh[Dd * Dd], g_Worl[Dd * Dd];
static __device__ __half g_WorTh[Dd * Dd], g_WorTl[Dd * Dd];
static __device__ __half g_WsrTh[Dd * Dd], g_WsrTl[Dd * Dd];
static __device__ __half g_X4h[MAXN * 4 * Dd], g_X4l[MAXN * 4 * Dd];
static __device__ __half g_Msymh[Dd * Dd], g_Msyml[Dd * Dd];
static __device__ __half g_T1h[Dd * Dd], g_T1l[Dd * Dd];
static __device__ __half g_Kqh[Dd * Dd], g_Kql[Dd * Dd];
static __device__ __half g_W2h[Dd * Dd], g_W2l[Dd * Dd];
static __device__ __half g_W3h[Dd * Dd], g_W3l[Dd * Dd];
static __device__ __half g_VWTh[Dd * MAXN], g_VWTl[Dd * MAXN];
static __device__ __half g_U1h[MAXN * Dd], g_U1l[MAXN * Dd];
static __device__ __half g_U2h[MAXN * Dd], g_U2l[MAXN * Dd];
static __device__ __half g_GWh[MAXN * Dd], g_GWl[MAXN * Dd];
static __device__ __half g_Wmath[MAXN * MAXN], g_Wmatl[MAXN * MAXN];

// ================= PTX helpers =================
__device__ __forceinline__ uint32_t smem_u32(const void* p) {
    return (uint32_t)__cvta_generic_to_shared(p);
}
__device__ __forceinline__ void ldsm4(uint32_t& r0, uint32_t& r1, uint32_t& r2, uint32_t& r3, uint32_t a) {
    asm volatile("ldmatrix.sync.aligned.m8n8.x4.shared.b16 {%0,%1,%2,%3}, [%4];"
                 : "=r"(r0), "=r"(r1), "=r"(r2), "=r"(r3) : "r"(a));
}
__device__ __forceinline__ void mma_fp(float* d, const uint32_t* a, const uint32_t* b) {
    asm volatile("mma.sync.aligned.m16n8k16.row.col.f32.f16.f16.f32 "
                 "{%0,%1,%2,%3}, {%4,%5,%6,%7}, {%8,%9}, {%0,%1,%2,%3};"
                 : "+f"(d[0]), "+f"(d[1]), "+f"(d[2]), "+f"(d[3])
                 : "r"(a[0]), "r"(a[1]), "r"(a[2]), "r"(a[3]), "r"(b[0]), "r"(b[1]));
}
__device__ __forceinline__ void cpasync16(uint32_t saddr, const void* gaddr) {
    asm volatile("cp.async.cg.shared.global [%0], [%1], 16;" :: "r"(saddr), "l"(gaddr));
}
#define CP_COMMIT() asm volatile("cp.async.commit_group;" ::: "memory")
#define CP_WAIT(N)  asm volatile("cp.async.wait_group %0;" :: "n"(N) : "memory")

// ================= batched fp16 2-term mma.sync GEMM =================
// C = cscale*(A @ B^T) (+addsrc)(+bias). A = exact hi+lo fp16, B = hi fp16 only.
// emit: 0 none, 1 fp16 hi/lo, 3 final-mask mode (out = vf + involved*(acc+bias)).
// Quad mode (qp != null): quadP[m*8+blkx] = sum_n (val + V1[sbj[m]] + V2[obj[m]])*x[m,n].
// BM=BN=128, BK=64, 2-stage cp.async double buffer, 2 CTAs/SM.
struct GemmDesc {
    const __half *Ah, *Al, *Bh;
    const float *addsrc, *bias;
    float* C;
    __half *Chi, *Clo;
    const float* xptr;          // quad: rvf ; final: vf
    const int *sbjp, *objp;
    const float *v1p, *v2p;     // quad: V1,V2 ; final: sums,sumo
    float* qp;
    int lda, ldb, ldc, K, mb, nb;
    float cscale;
    int emit;
};
struct GemmBatch { GemmDesc d[6]; };

#define TILE_B    (128 * 144)              // 18432 B per matrix tile (pitch 144)
#define STAGE_B   (3 * TILE_B)             // Ah, Al, Bh = 55296
#define SMEM_TOT  (2 * STAGE_B)            // 110592 -> 2 CTAs/SM

__global__ __launch_bounds__(256, 2)
void mgemm3(GemmBatch batch)
{
    extern __shared__ char smem[];
    const GemmDesc d = batch.d[blockIdx.z];
    if ((int)blockIdx.y >= d.mb || (int)blockIdx.x >= d.nb) return;

    const int tid = threadIdx.x;
    const int lane = tid & 31, warp = tid >> 5;
    const int wm = warp & 1, wn = warp >> 1;
    const int m0 = blockIdx.y * 128, n0 = blockIdx.x * 128;
    const int l8 = lane & 7, grp = lane >> 3;
    const int lda = d.lda, ldb = d.ldb;
    const __half *Ah = d.Ah, *Al = d.Al, *Bh = d.Bh;
    const int nchunks = d.K >> 6;

    auto load_stage = [&](int stg, int chunk) {
        const uint32_t sbase = smem_u32(smem) + stg * STAGE_B;
        const int k0 = chunk << 6;
#pragma unroll
        for (int it = 0; it < 4; it++) {
            int linear = tid + it * 256;
            int row = linear >> 3, seg = (linear & 7) << 3;
            uint32_t soff = (uint32_t)(row * 144 + seg * 2);
            size_t ga = (size_t)(m0 + row) * lda + k0 + seg;
            cpasync16(sbase + soff,              Ah + ga);
            cpasync16(sbase + TILE_B + soff,     Al + ga);
            size_t gb = (size_t)(n0 + row) * ldb + k0 + seg;
            cpasync16(sbase + 2 * TILE_B + soff, Bh + gb);
        }
    };

    float acc[4][4][4] = {};

    load_stage(0, 0);
    CP_COMMIT();

    int st = 0;
    for (int i = 0; i < nchunks; i++) {
        if (i + 1 < nchunks) {
            load_stage(st ^ 1, i + 1);
            CP_COMMIT();
            CP_WAIT(1);
        } else {
            CP_WAIT(0);
        }
        __syncthreads();

        const char* base = smem + st * STAGE_B;
#pragma unroll
        for (int kk = 0; kk < 4; kk++) {
            const int kcol = kk * 16;
            uint32_t ah[4][4], al[4][4], bh[4][2];
#pragma unroll
            for (int mt = 0; mt < 4; mt++) {
                int row = wm * 64 + mt * 16 + l8 + ((grp & 1) << 3);
                int col = kcol + ((grp >> 1) << 3);
                uint32_t a0 = smem_u32(base + row * 144 + col * 2);
                ldsm4(ah[mt][0], ah[mt][1], ah[mt][2], ah[mt][3], a0);
                ldsm4(al[mt][0], al[mt][1], al[mt][2], al[mt][3], a0 + TILE_B);
            }
#pragma unroll
            for (int ntp = 0; ntp < 2; ntp++) {
                int row = wn * 32 + ntp * 16 + ((grp >> 1) << 3) + l8;
                int col = kcol + ((grp & 1) << 3);
                uint32_t b0 = smem_u32(base + 2 * TILE_B + row * 144 + col * 2);
                ldsm4(bh[2 * ntp][0], bh[2 * ntp][1], bh[2 * ntp + 1][0], bh[2 * ntp + 1][1], b0);
            }
#pragma unroll
            for (int mt = 0; mt < 4; mt++)
#pragma unroll
                for (int nt = 0; nt < 4; nt++) mma_fp(acc[mt][nt], ah[mt], bh[nt]);
#pragma unroll
            for (int mt = 0; mt < 4; mt++)
#pragma unroll
                for (int nt = 0; nt < 4; nt++) mma_fp(acc[mt][nt], al[mt], bh[nt]);
        }
        __syncthreads();
        st ^= 1;
    }

    if (d.qp) {
        // fused quadratic epilogue
        float pt[4], pb[4];
#pragma unroll
        for (int mt = 0; mt < 4; mt++) {
            int mtop = m0 + wm * 64 + mt * 16 + (lane >> 2);
            int mbot = mtop + 8;
            int s1 = d.sbjp[mtop], o1 = d.objp[mtop];
            int s2 = d.sbjp[mbot], o2 = d.objp[mbot];
            float at = 0.f, ab = 0.f;
#pragma unroll
            for (int nt = 0; nt < 4; nt++) {
                int n = n0 + wn * 32 + nt * 8 + (lane & 3) * 2;
                float2 xt = *(const float2*)(d.xptr + (size_t)mtop * lda + n);
                float2 xb = *(const float2*)(d.xptr + (size_t)mbot * lda + n);
                float2 v1t = *(const float2*)(d.v1p + (size_t)s1 * Dd + n);
                float2 v2t = *(const float2*)(d.v2p + (size_t)o1 * Dd + n);
                float2 v1b = *(const float2*)(d.v1p + (size_t)s2 * Dd + n);
                float2 v2b = *(const float2*)(d.v2p + (size_t)o2 * Dd + n);
                at += (acc[mt][nt][0] + v1t.x + v2t.x) * xt.x
                    + (acc[mt][nt][1] + v1t.y + v2t.y) * xt.y;
                ab += (acc[mt][nt][2] + v1b.x + v2b.x) * xb.x
                    + (acc[mt][nt][3] + v1b.y + v2b.y) * xb.y;
            }
            at += __shfl_xor_sync(0xffffffffu, at, 1);
            at += __shfl_xor_sync(0xffffffffu, at, 2);
            ab += __shfl_xor_sync(0xffffffffu, ab, 1);
            ab += __shfl_xor_sync(0xffffffffu, ab, 2);
            pt[mt] = at; pb[mt] = ab;
        }
        __syncthreads();
        float* qs = (float*)smem;
        if ((lane & 3) == 0) {
#pragma unroll
            for (int mt = 0; mt < 4; mt++) {
                int rt = wm * 64 + mt * 16 + (lane >> 2);
                qs[rt * 4 + wn] = pt[mt];
                qs[(rt + 8) * 4 + wn] = pb[mt];
            }
        }
        __syncthreads();
        if (tid < 128) {
            float q = qs[tid * 4] + qs[tid * 4 + 1] + qs[tid * 4 + 2] + qs[tid * 4 + 3];
            d.qp[(size_t)(m0 + tid) * 8 + blockIdx.x] = q;
        }
        return;
    }

    const int ldc = d.ldc;
    if (d.emit == 3) {
        // final-mask epilogue: out = vf + involved ? (acc + bias) : 0
#pragma unroll
        for (int mt = 0; mt < 4; mt++)
#pragma unroll
            for (int nt = 0; nt < 4; nt++) {
                int m = m0 + wm * 64 + mt * 16 + (lane >> 2);
                int n = n0 + wn * 32 + nt * 8 + (lane & 3) * 2;
#pragma unroll
                for (int hrow = 0; hrow < 2; hrow++) {
                    int mm = m + hrow * 8;
                    bool inv = (d.v1p[mm] > 0.f) || (d.v2p[mm] > 0.f);
                    float2 b = *(const float2*)(d.bias + n);
                    float2 base = *(const float2*)(d.xptr + (size_t)mm * ldc + n);
                    float2 v;
                    v.x = base.x + (inv ? acc[mt][nt][hrow * 2]     + b.x : 0.f);
                    v.y = base.y + (inv ? acc[mt][nt][hrow * 2 + 1] + b.y : 0.f);
                    *(float2*)(d.C + (size_t)mm * ldc + n) = v;
                }
            }
        return;
    }

    // ---- standard epilogue ----
#pragma unroll
    for (int mt = 0; mt < 4; mt++)
#pragma unroll
        for (int nt = 0; nt < 4; nt++) {
            int m = m0 + wm * 64 + mt * 16 + (lane >> 2);
            int n = n0 + wn * 32 + nt * 8 + (lane & 3) * 2;
#pragma unroll
            for (int hrow = 0; hrow < 2; hrow++) {
                int mm = m + hrow * 8;
                float2 v = make_float2(acc[mt][nt][hrow * 2] * d.cscale,
                                       acc[mt][nt][hrow * 2 + 1] * d.cscale);
                if (d.addsrc) {
                    float2 s = *(const float2*)(d.addsrc + (size_t)mm * ldc + n);
                    v.x += s.x; v.y += s.y;
                }
                if (d.bias) {
                    float2 b = *(const float2*)(d.bias + n);
                    v.x += b.x; v.y += b.y;
                }
                *(float2*)(d.C + (size_t)mm * ldc + n) = v;
                if (d.emit == 1) {
                    __half h0 = __float2half_rn(v.x), h1 = __float2half_rn(v.y);
                    d.Chi[(size_t)mm * ldc + n]     = h0;
                    d.Chi[(size_t)mm * ldc + n + 1] = h1;
                    d.Clo[(size_t)mm * ldc + n]     = __float2half_rn(v.x - __half2float(h0));
                    d.Clo[(size_t)mm * ldc + n + 1] = __float2half_rn(v.y - __half2float(h1));
                }
            }
        }
}

// ================= prologue kernels =================
__global__ void rvfprep(const float4* __restrict__ src, float4* __restrict__ out,
                        __half2* __restrict__ hi, __half2* __restrict__ lo, long long n4,
                        float* __restrict__ wmat, int nn2,
                        const float* __restrict__ brel, const float* __restrict__ bsbj,
                        const float* __restrict__ bobj, float* __restrict__ biascat)
{
    long long stride = (long long)gridDim.x * blockDim.x;
    long long t0 = (long long)blockIdx.x * blockDim.x + threadIdx.x;
    for (long long i = t0; i < n4; i += stride) {
        float4 v = src[i];
        out[i] = v;
        __half hx = __float2half_rn(v.x), hy = __float2half_rn(v.y);
        __half hz = __float2half_rn(v.z), hw = __float2half_rn(v.w);
        hi[2 * i]     = __halves2half2(hx, hy);
        hi[2 * i + 1] = __halves2half2(hz, hw);
        lo[2 * i]     = __halves2half2(__float2half_rn(v.x - __half2float(hx)),
                                       __float2half_rn(v.y - __half2float(hy)));
        lo[2 * i + 1] = __halves2half2(__float2half_rn(v.z - __half2float(hz)),
                                       __float2half_rn(v.w - __half2float(hw)));
    }
    for (long long i = t0; i < nn2; i += stride) wmat[i] = 0.f;
    for (long long i = t0; i < 4 * Dd; i += stride) {
        int c = (int)i >> 10, n = (int)i & 1023;
        biascat[i] = (c == 0) ? 0.f : (c == 1 ? brel[n] : (c == 2 ? bsbj[n] : bobj[n]));
    }
}

struct SplitDesc { const float* src; __half *hi, *lo; long long n; };
struct SplitBatch { SplitDesc d[4]; };
__global__ void splitmulti(SplitBatch b)
{
    SplitDesc d = b.d[blockIdx.z];
    long long n4 = d.n >> 2;
    __half2* hi2 = (__half2*)d.hi;
    __half2* lo2 = (__half2*)d.lo;
    const float4* s4 = (const float4*)d.src;
    for (long long i = (long long)blockIdx.x * blockDim.x + threadIdx.x; i < n4;
         i += (long long)gridDim.x * blockDim.x) {
        float4 v = s4[i];
        __half hx = __float2half_rn(v.x), hy = __float2half_rn(v.y);
        __half hz = __float2half_rn(v.z), hw = __float2half_rn(v.w);
        hi2[2 * i]     = __halves2half2(hx, hy);
        hi2[2 * i + 1] = __halves2half2(hz, hw);
        lo2[2 * i]     = __halves2half2(__float2half_rn(v.x - __half2float(hx)),
                                        __float2half_rn(v.y - __half2float(hy)));
        lo2[2 * i + 1] = __halves2half2(__float2half_rn(v.z - __half2float(hz)),
                                        __float2half_rn(v.w - __half2float(hw)));
    }
}

__global__ void splitk(const float* __restrict__ src, __half* __restrict__ hi,
                       __half* __restrict__ lo, long long n)
{
    long long n4 = n >> 2;
    __half2* hi2 = (__half2*)hi;
    __half2* lo2 = (__half2*)lo;
    const float4* s4 = (const float4*)src;
    for (long long i = (long long)blockIdx.x * blockDim.x + threadIdx.x; i < n4;
         i += (long long)gridDim.x * blockDim.x) {
        float4 v = s4[i];
        __half hx = __float2half_rn(v.x), hy = __float2half_rn(v.y);
        __half hz = __float2half_rn(v.z), hw = __float2half_rn(v.w);
        hi2[2 * i]     = __halves2half2(hx, hy);
        hi2[2 * i + 1] = __halves2half2(hz, hw);
        lo2[2 * i]     = __halves2half2(__float2half_rn(v.x - __half2float(hx)),
                                        __float2half_rn(v.y - __half2float(hy)));
        lo2[2 * i + 1] = __halves2half2(__float2half_rn(v.z - __half2float(hz)),
                                        __float2half_rn(v.w - __half2float(hw)));
    }
}

struct TSplitDesc { const float* src; __half *hi, *lo; int R; };
struct TSplitBatch { TSplitDesc d[7]; };
__global__ void tsplitmulti(TSplitBatch b)   // src [R][1024] -> dst [1024][R] hi/lo
{
    TSplitDesc d = b.d[blockIdx.z];
    __shared__ float tile[32][33];
    int cx = blockIdx.x * 32, ry = blockIdx.y * 32;
    if (ry >= d.R) return;
    int tx = threadIdx.x, ty = threadIdx.y;  // 32 x 8
#pragma unroll
    for (int i = 0; i < 32; i += 8)
        tile[ty + i][tx] = d.src[(size_t)(ry + ty + i) * Dd + cx + tx];
    __syncthreads();
#pragma unroll
    for (int i = 0; i < 32; i += 8) {
        float v = tile[tx][ty + i];
        __half h = __float2half_rn(v);
        size_t o = (size_t)(cx + ty + i) * d.R + ry + tx;
        d.hi[o] = h;
        d.lo[o] = __float2half_rn(v - __half2float(h));
    }
}

__global__ void msymk()   // Msym = M + M^T, split to fp16 hi/lo
{
    int idx = blockIdx.x * 256 + threadIdx.x;
    if (idx < Dd * Dd) {
        int i = idx >> 10, j = idx & 1023;
        float v = g_s.M[idx] + g_s.M[j * Dd + i];
        __half h = __float2half_rn(v);
        g_Msymh[idx] = h;
        g_Msyml[idx] = __float2half_rn(v - __half2float(h));
    }
}

// ================= graph epilogue kernels =================
__global__ void rowdots(float* __restrict__ S1, float* __restrict__ S2)
{
    int n = blockIdx.x, tid = threadIdx.x;
    const float* a  = g_s.X4 + (size_t)n * 4096;
    const float* bp = a + 1024;
    float s1 = 0.f, s2 = 0.f;
    for (int d = tid; d < Dd; d += 256) {
        s1 += a[d]  * (g_s.U1[(size_t)n * Dd + d] + g_s.CW[(size_t)n * Dd + d]);
        s2 += bp[d] * (g_s.U2[(size_t)n * Dd + d] + g_s.GW[(size_t)n * Dd + d]);
    }
    __shared__ float r1[256], r2[256];
    r1[tid] = s1; r2[tid] = s2; __syncthreads();
    for (int st = 128; st > 0; st >>= 1) {
        if (tid < st) { r1[tid] += r1[tid + st]; r2[tid] += r2[tid + st]; }
        __syncthreads();
    }
    if (tid == 0) { S1[n] = 0.5f * r1[0]; S2[n] = 0.5f * r2[0]; }
}

__global__ void logitsk(const int* __restrict__ sbj, const int* __restrict__ obj,
                        int E, int Nn, float scale)
{
    int e = blockIdx.x * 256 + threadIdx.x;
    if (e >= E) return;
    const float* qp = g_s.quadP + (size_t)e * 8;
    float q = qp[0] + qp[1] + qp[2] + qp[3] + qp[4] + qp[5] + qp[6] + qp[7];
    int s = sbj[e], o = obj[e];
    size_t po = (size_t)s * Nn + o;
    g_s.logits[e] = (q + g_s.Pa[po] + g_s.Pb[po] + g_s.Pc[po] + g_s.S1[s] + g_s.S2[o]) * scale;
}

__global__ void segstats(const int* __restrict__ sbj, const int* __restrict__ obj, int E)
{
    int n = blockIdx.x, tid = threadIdx.x;
    const int* ind = (blockIdx.y == 0) ? sbj : obj;
    __shared__ float red[256];
    float m = -1e30f;
    for (int e = tid; e < E; e += 256)
        if (ind[e] == n) m = fmaxf(m, g_s.logits[e]);
    red[tid] = m; __syncthreads();
    for (int st = 128; st > 0; st >>= 1) {
        if (tid < st) red[tid] = fmaxf(red[tid], red[tid + st]);
        __syncthreads();
    }
    float Mv = red[0]; __syncthreads();
    float s = 0.f;
    for (int e = tid; e < E; e += 256)
        if (ind[e] == n) s += expf(g_s.logits[e] - Mv);
    red[tid] = s; __syncthreads();
    for (int st = 128; st > 0; st >>= 1) {
        if (tid < st) red[tid] += red[tid + st];
        __syncthreads();
    }
    if (tid == 0) {
        if (blockIdx.y == 0) { g_s.maxs[n] = Mv; g_s.sums[n] = red[0]; }
        else                 { g_s.maxo[n] = Mv; g_s.sumo[n] = red[0]; }
    }
}

__global__ void wmatk(const int* __restrict__ sbj, const int* __restrict__ obj,
                      int E, int Nn)
{
    int e = blockIdx.x * 256 + threadIdx.x;
    if (e >= E) return;
    float l = g_s.logits[e];
    int s = sbj[e], o = obj[e];
    float ws = expf(l - g_s.maxs[s]) / g_s.sums[s];
    float wo = expf(l - g_s.maxo[o]) / g_s.sumo[o];
    atomicAdd(&g_s.Wmat[(size_t)s * Nn + o], ws);
    atomicAdd(&g_s.Wmat[(size_t)o * Nn + s], wo);
}

// ================= host orchestration =================
static GemmDesc mkdesc(const __half* Ah, const __half* Al, int lda,
                       const __half* Bh, int ldb,
                       float* C, int ldc, const float* addsrc, const float* bias,
                       __half* Chi, __half* Clo, int M, int N, int K, float cscale = 1.0f)
{
    GemmDesc d{};
    d.Ah = Ah; d.Al = Al; d.Bh = Bh;
    d.addsrc = addsrc; d.bias = bias; d.C = C; d.Chi = Chi; d.Clo = Clo;
    d.lda = lda; d.ldb = ldb; d.ldc = ldc; d.K = K;
    d.mb = M / 128; d.nb = N / 128; d.cscale = cscale;
    d.emit = Chi ? 1 : 0;
    return d;
}

static void launch_batch(GemmDesc* ds, int nd)
{
    GemmBatch b{};
    int mx = 0, nx = 0;
    for (int i = 0; i < nd; i++) { b.d[i] = ds[i]; if (ds[i].mb > mx) mx = ds[i].mb; if (ds[i].nb > nx) nx = ds[i].nb; }
    for (int i = nd; i < 6; i++) { b.d[i] = ds[0]; }
    dim3 grid(nx, mx, nd);
    mgemm3<<<grid, 256, SMEM_TOT>>>(b);
}

extern "C" void kernel_launch(void* const* d_in, const int* in_sizes, int n_in,
                              void* d_out, int out_size)
{
    const float* vf   = (const float*)d_in[0];
    const float* rvf  = (const float*)d_in[1];
    const float* Wrel = (const float*)d_in[2];
    const float* brel = (const float*)d_in[3];
    const float* Wsbj = (const float*)d_in[4];
    const float* bsbj = (const float*)d_in[5];
    const float* Wobj = (const float*)d_in[6];
    const float* bobj = (const float*)d_in[7];
    const float* Wctx = (const float*)d_in[8];
    const float* bctx = (const float*)d_in[9];
    const int*   sbj  = (const int*)d_in[10];
    const int*   obj  = (const int*)d_in[11];

    const int Nn = in_sizes[0] / Dd;    // 768
    const int E  = in_sizes[10];        // 24576
    float* out = (float*)d_out;

    cudaFuncSetAttribute(mgemm3, cudaFuncAttributeMaxDynamicSharedMemorySize, SMEM_TOT);

    Scratch* S = nullptr;
    cudaGetSymbolAddress((void**)&S, g_s);
    __half *rvfh, *rvfl, *vfh, *vfl, *WcatTh, *WcatTl, *WctxTh, *WctxTl;
    __half *Wrrh, *Wrrl, *Wsrh, *Wsrl, *Worh, *Worl, *WorTh, *WorTl, *WsrTh, *WsrTl;
    __half *X4h, *X4l, *Msh, *Msl, *T1h, *T1l, *Kqh, *Kql;
    __half *W2h, *W2l, *W3h, *W3l, *VWTh, *VWTl;
    __half *U1h, *U1l, *U2h, *U2l, *GWh, *GWl, *Wmh, *Wml;
    cudaGetSymbolAddress((void**)&rvfh, g_rvfh);   cudaGetSymbolAddress((void**)&rvfl, g_rvfl);
    cudaGetSymbolAddress((void**)&vfh, g_vfh);     cudaGetSymbolAddress((void**)&vfl, g_vfl);
    cudaGetSymbolAddress((void**)&WcatTh, g_WcatTh); cudaGetSymbolAddress((void**)&WcatTl, g_WcatTl);
    cudaGetSymbolAddress((void**)&WctxTh, g_WctxTh); cudaGetSymbolAddress((void**)&WctxTl, g_WctxTl);
    cudaGetSymbolAddress((void**)&Wrrh, g_Wrrh);   cudaGetSymbolAddress((void**)&Wrrl, g_Wrrl);
    cudaGetSymbolAddress((void**)&Wsrh, g_Wsrh);   cudaGetSymbolAddress((void**)&Wsrl, g_Wsrl);
    cudaGetSymbolAddress((void**)&Worh, g_Worh);   cudaGetSymbolAddress((void**)&Worl, g_Worl);
    cudaGetSymbolAddress((void**)&WorTh, g_WorTh); cudaGetSymbolAddress((void**)&WorTl, g_WorTl);
    cudaGetSymbolAddress((void**)&WsrTh, g_WsrTh); cudaGetSymbolAddress((void**)&WsrTl, g_WsrTl);
    cudaGetSymbolAddress((void**)&X4h, g_X4h);     cudaGetSymbolAddress((void**)&X4l, g_X4l);
    cudaGetSymbolAddress((void**)&Msh, g_Msymh);   cudaGetSymbolAddress((void**)&Msl, g_Msyml);
    cudaGetSymbolAddress((void**)&T1h, g_T1h);     cudaGetSymbolAddress((void**)&T1l, g_T1l);
    cudaGetSymbolAddress((void**)&Kqh, g_Kqh);     cudaGetSymbolAddress((void**)&Kql, g_Kql);
    cudaGetSymbolAddress((void**)&W2h, g_W2h);     cudaGetSymbolAddress((void**)&W2l, g_W2l);
    cudaGetSymbolAddress((void**)&W3h, g_W3h);     cudaGetSymbolAddress((void**)&W3l, g_W3l);
    cudaGetSymbolAddress((void**)&VWTh, g_VWTh);   cudaGetSymbolAddress((void**)&VWTl, g_VWTl);
    cudaGetSymbolAddress((void**)&U1h, g_U1h);     cudaGetSymbolAddress((void**)&U1l, g_U1l);
    cudaGetSymbolAddress((void**)&U2h, g_U2h);     cudaGetSymbolAddress((void**)&U2l, g_U2l);
    cudaGetSymbolAddress((void**)&GWh, g_GWh);     cudaGetSymbolAddress((void**)&GWl, g_GWl);
    cudaGetSymbolAddress((void**)&Wmh, g_Wmath);   cudaGetSymbolAddress((void**)&Wml, g_Wmatl);

    const float* Wr_r = Wrel + 2 * Dd * Dd;
    const float* Ws_r = Wsbj + Dd * Dd;
    const float* Wo_r = Wobj + Dd * Dd;

    // P0: rvf copy + fp16 split + Wmat zero + biascat
    long long n4 = (long long)E * Dd / 4;
    rvfprep<<<4096, 256>>>((const float4*)rvf, (float4*)out,
                           (__half2*)rvfh, (__half2*)rvfl, n4,
                           S->Wmat, Nn * Nn, brel, bsbj, bobj, S->biascat);

    // P1: flat splits (vf, Wrr, Wsr, Wor)
    {
        SplitBatch sb{};
        sb.d[0] = { vf,   vfh,  vfl,  (long long)Nn * Dd };
        sb.d[1] = { Wr_r, Wrrh, Wrrl, (long long)Dd * Dd };
        sb.d[2] = { Ws_r, Wsrh, Wsrl, (long long)Dd * Dd };
        sb.d[3] = { Wo_r, Worh, Worl, (long long)Dd * Dd };
        splitmulti<<<dim3(256, 1, 4), 256>>>(sb);
    }
    // P2: transposed splits (WctxT, WcatT x4, WorT, WsrT)
    {
        TSplitBatch tb{};
        tb.d[0] = { Wctx,           WctxTh,               WctxTl,               Dd };
        tb.d[1] = { Wrel,           WcatTh + 0 * Dd * Dd, WcatTl + 0 * Dd * Dd, Dd };
        tb.d[2] = { Wrel + Dd * Dd, WcatTh + 1 * Dd * Dd, WcatTl + 1 * Dd * Dd, Dd };
        tb.d[3] = { Wsbj,           WcatTh + 2 * Dd * Dd, WcatTl + 2 * Dd * Dd, Dd };
        tb.d[4] = { Wobj,           WcatTh + 3 * Dd * Dd, WcatTl + 3 * Dd * Dd, Dd };
        tb.d[5] = { Wo_r,           WorTh,                WorTl,                Dd };
        tb.d[6] = { Ws_r,           WsrTh,                WsrTl,                Dd };
        tsplitmulti<<<dim3(32, 32, 7), dim3(32, 8)>>>(tb);
    }

    // B1: X4, M, W2'=Wrr@Wor, W3'=Wrr@Wsr, VWT=Wctx^T·vf^T
    {
        GemmDesc ds[5] = {
            mkdesc(vfh, vfl, Dd, WcatTh, Dd, S->X4, 4096, nullptr, S->biascat, X4h, X4l, Nn, 4096, Dd),
            mkdesc(Wsrh, Wsrl, Dd, Worh, Dd, S->M, Dd, nullptr, nullptr, nullptr, nullptr, Dd, Dd, Dd),
            mkdesc(Wrrh, Wrrl, Dd, WorTh, Dd, S->W2, Dd, nullptr, nullptr, W2h, W2l, Dd, Dd, Dd),
            mkdesc(Wrrh, Wrrl, Dd, WsrTh, Dd, S->W3, Dd, nullptr, nullptr, W3h, W3l, Dd, Dd, Dd),
            mkdesc(WctxTh, WctxTl, Dd, vfh, Dd, S->VWT, Nn, nullptr, nullptr, VWTh, VWTl, Dd, Nn, Dd)
        };
        launch_batch(ds, 5);
    }
    msymk<<<(Dd * Dd + 255) / 256, 256>>>();

    // B2: T1=Wrr@Msym, CW, GW, Pa=C@G^T, V1a=C@W2'^T, V2a=G@W3'^T
    {
        GemmDesc ds[6] = {
            mkdesc(Wrrh, Wrrl, Dd, Msh, Dd, S->T1, Dd, nullptr, nullptr, T1h, T1l, Dd, Dd, Dd),
            mkdesc(X4h + 2048, X4l + 2048, 4096, Worh, Dd, S->CW, Dd, nullptr, nullptr, nullptr, nullptr, Nn, Dd, Dd),
            mkdesc(X4h + 3072, X4l + 3072, 4096, Wsrh, Dd, S->GW, Dd, nullptr, nullptr, GWh, GWl, Nn, Dd, Dd),
            mkdesc(X4h + 2048, X4l + 2048, 4096, X4h + 3072, 4096, S->Pa, Nn, nullptr, nullptr, nullptr, nullptr, Nn, Nn, Dd),
            mkdesc(X4h + 2048, X4l + 2048, 4096, W2h, Dd, S->V1, Dd, nullptr, nullptr, nullptr, nullptr, Nn, Dd, Dd),
            mkdesc(X4h + 3072, X4l + 3072, 4096, W3h, Dd, S->V2, Dd, nullptr, nullptr, nullptr, nullptr, Nn, Dd, Dd)
        };
        launch_batch(ds, 6);
    }

    // B3: U1=A@Msym+CW, U2=B'@Msym+GW, Kq=0.5*T1@Wrr^T, V1=A@T1^T+V1a, V2=B'@T1^T+V2a
    {
        GemmDesc ds[5] = {
            mkdesc(X4h, X4l, 4096, Msh, Dd, S->U1, Dd, S->CW, nullptr, U1h, U1l, Nn, Dd, Dd),
            mkdesc(X4h + 1024, X4l + 1024, 4096, Msh, Dd, S->U2, Dd, S->GW, nullptr, U2h, U2l, Nn, Dd, Dd),
            mkdesc(T1h, T1l, Dd, Wrrh, Dd, S->Kq, Dd, nullptr, nullptr, Kqh, Kql, Dd, Dd, Dd, 0.5f),
            mkdesc(X4h, X4l, 4096, T1h, Dd, S->V1, Dd, S->V1, nullptr, nullptr, nullptr, Nn, Dd, Dd),
            mkdesc(X4h + 1024, X4l + 1024, 4096, T1h, Dd, S->V2, Dd, S->V2, nullptr, nullptr, nullptr, Nn, Dd, Dd)
        };
        launch_batch(ds, 5);
    }
    rowdots<<<Nn, 256>>>(S->S1, S->S2);

    // B4: quad GEMM (rvf @ Kq, fused epilogue), Pb=U1@B'^T, Pc=A@GW^T
    {
        GemmDesc ds[3];
        ds[0] = mkdesc(rvfh, rvfl, Dd, Kqh, Dd, nullptr, Dd, nullptr, nullptr,
                       nullptr, nullptr, E, Dd, Dd);
        ds[0].emit = 0;
        ds[0].xptr = rvf; ds[0].sbjp = sbj; ds[0].objp = obj;
        ds[0].v1p = S->V1; ds[0].v2p = S->V2; ds[0].qp = S->quadP;
        ds[1] = mkdesc(U1h, U1l, Dd, X4h + 1024, 4096, S->Pb, Nn, nullptr, nullptr, nullptr, nullptr, Nn, Nn, Dd);
        ds[2] = mkdesc(X4h, X4l, 4096, GWh, Dd, S->Pc, Nn, nullptr, nullptr, nullptr, nullptr, Nn, Nn, Dd);
        launch_batch(ds, 3);
    }

    // logits, softmax stats, mixing matrix
    logitsk<<<(E + 255) / 256, 256>>>(sbj, obj, E, Nn, 1.0f / sqrtf((float)Dd));
    segstats<<<dim3(Nn, 2), 256>>>(sbj, obj, E);
    wmatk<<<(E + 255) / 256, 256>>>(sbj, obj, E, Nn);
    splitk<<<256, 256>>>(S->Wmat, Wmh, Wml, (long long)Nn * Nn);

    // B5: ctxW = Wmat @ VWT^T + bctx, fused final-mask epilogue -> out
    {
        GemmDesc d = mkdesc(Wmh, Wml, Nn, VWTh, Nn, out + (size_t)E * Dd, Dd,
                            nullptr, bctx, nullptr, nullptr, Nn, Dd, Nn);
        d.emit = 3;
        d.xptr = vf; d.v1p = S->sums; d.v2p = S->sumo;
        launch_batch(&d, 1);
    }
}

// round 11
// speedup vs baseline: 4.3382x; 1.0704x over previous
#include <cuda_runtime.h>
#include <cuda_fp16.h>
#include <math.h>
#include <stdint.h>

#define Dd 1024
#define MAXN 1024
#define MAXE 32768

// ================= static scratch =================
struct Scratch {
    float X4[MAXN * 4 * Dd];      // [A | B' | C | G], ld=4096
    float biascat[4 * Dd];
    float M[Dd * Dd];
    float T1[Dd * Dd];
    float Kq[Dd * Dd];
    float W2[Dd * Dd];            // Wrr @ Wor
    float W3[Dd * Dd];            // Wrr @ Wsr
    float VWT[Dd * MAXN];         // (vf @ Wctx)^T
    float CW[MAXN * Dd];
    float GW[MAXN * Dd];
    float U1[MAXN * Dd];
    float U2[MAXN * Dd];
    float V1[MAXN * Dd];
    float V2[MAXN * Dd];
    float Pa[MAXN * MAXN];
    float Pb[MAXN * MAXN];
    float Pc[MAXN * MAXN];
    float S1[MAXN];
    float S2[MAXN];
    float quadP[(size_t)MAXE * 8];
    float logits[MAXE];
    float maxs[MAXN], sums[MAXN], maxo[MAXN], sumo[MAXN];
    float Wmat[MAXN * MAXN];
};
static __device__ Scratch g_s;

// fp16 hi/lo operand storage
static __device__ __half g_rvfh[(size_t)MAXE * Dd];
static __device__ __half g_vfh[MAXN * Dd],  g_vfl[MAXN * Dd];
static __device__ __half g_WcatTh[4 * Dd * Dd], g_WcatTl[4 * Dd * Dd];
static __device__ __half g_WctxTh[Dd * Dd], g_WctxTl[Dd * Dd];
static __device__ __half g_Wrrh[Dd * Dd], g_Wrrl[Dd * Dd];
static __device__ __half g_Wsrh[Dd * Dd], g_Wsrl[Dd * Dd];
static __device__ __half g_Worh[Dd * Dd], g_Worl[Dd * Dd];
static __device__ __half g_WorTh[Dd * Dd], g_WorTl[Dd * Dd];
static __device__ __half g_WsrTh[Dd * Dd], g_WsrTl[Dd * Dd];
static __device__ __half g_X4h[MAXN * 4 * Dd], g_X4l[MAXN * 4 * Dd];
static __device__ __half g_Msymh[Dd * Dd], g_Msyml[Dd * Dd];
static __device__ __half g_T1h[Dd * Dd], g_T1l[Dd * Dd];
static __device__ __half g_Kqh[Dd * Dd], g_Kql[Dd * Dd];
static __device__ __half g_W2h[Dd * Dd], g_W2l[Dd * Dd];
static __device__ __half g_W3h[Dd * Dd], g_W3l[Dd * Dd];
static __device__ __half g_VWTh[Dd * MAXN], g_VWTl[Dd * MAXN];
static __device__ __half g_U1h[MAXN * Dd], g_U1l[MAXN * Dd];
static __device__ __half g_U2h[MAXN * Dd], g_U2l[MAXN * Dd];
static __device__ __half g_GWh[MAXN * Dd], g_GWl[MAXN * Dd];
static __device__ __half g_Wmath[MAXN * MAXN], g_Wmatl[MAXN * MAXN];

// ================= PTX helpers =================
__device__ __forceinline__ uint32_t smem_u32(const void* p) {
    return (uint32_t)__cvta_generic_to_shared(p);
}
__device__ __forceinline__ void ldsm4(uint32_t& r0, uint32_t& r1, uint32_t& r2, uint32_t& r3, uint32_t a) {
    asm volatile("ldmatrix.sync.aligned.m8n8.x4.shared.b16 {%0,%1,%2,%3}, [%4];"
                 : "=r"(r0), "=r"(r1), "=r"(r2), "=r"(r3) : "r"(a));
}
__device__ __forceinline__ void mma_fp(float* d, const uint32_t* a, const uint32_t* b) {
    asm volatile("mma.sync.aligned.m16n8k16.row.col.f32.f16.f16.f32 "
                 "{%0,%1,%2,%3}, {%4,%5,%6,%7}, {%8,%9}, {%0,%1,%2,%3};"
                 : "+f"(d[0]), "+f"(d[1]), "+f"(d[2]), "+f"(d[3])
                 : "r"(a[0]), "r"(a[1]), "r"(a[2]), "r"(a[3]), "r"(b[0]), "r"(b[1]));
}
__device__ __forceinline__ void cpasync16(uint32_t saddr, const void* gaddr) {
    asm volatile("cp.async.cg.shared.global [%0], [%1], 16;" :: "r"(saddr), "l"(gaddr));
}
#define CP_COMMIT() asm volatile("cp.async.commit_group;" ::: "memory")
#define CP_WAIT(N)  asm volatile("cp.async.wait_group %0;" :: "n"(N) : "memory")

// ================= batched fp16 mma.sync GEMM =================
// C = cscale*(A @ B^T) (+addsrc)(+bias). A = hi (+lo if aterms==2), B = hi only.
// emit: 0 none, 1 fp16 hi/lo, 3 final-mask mode (out = vf + involved*(acc+bias)).
// Quad mode (qp != null, aterms==1, B symmetric):
//   quadP[m*8+blkx] = sum_n [ acc*(2x - xh) + (V1[s]+V2[o])*x ]
//   which for acc = xh@K gives x·K·x + x·(V1+V2) up to O(2^-22).
struct GemmDesc {
    const __half *Ah, *Al, *Bh;
    const float *addsrc, *bias;
    float* C;
    __half *Chi, *Clo;
    const float* xptr;          // quad: rvf fp32 ; final: vf
    const int *sbjp, *objp;
    const float *v1p, *v2p;     // quad: V1,V2 ; final: sums,sumo
    float* qp;
    int lda, ldb, ldc, K, mb, nb;
    float cscale;
    int emit;
    int aterms;                 // 1 or 2
};
struct GemmBatch { GemmDesc d[6]; };

#define TILE_B    (128 * 144)              // 18432 B per matrix tile (pitch 144)
#define STAGE_B   (3 * TILE_B)             // Ah, Al, Bh = 55296
#define SMEM_TOT  (2 * STAGE_B)            // 110592 -> 2 CTAs/SM

__global__ __launch_bounds__(256, 2)
void mgemm3(GemmBatch batch)
{
    extern __shared__ char smem[];
    const GemmDesc d = batch.d[blockIdx.z];
    if ((int)blockIdx.y >= d.mb || (int)blockIdx.x >= d.nb) return;

    const int tid = threadIdx.x;
    const int lane = tid & 31, warp = tid >> 5;
    const int wm = warp & 1, wn = warp >> 1;
    const int m0 = blockIdx.y * 128, n0 = blockIdx.x * 128;
    const int l8 = lane & 7, grp = lane >> 3;
    const int lda = d.lda, ldb = d.ldb;
    const int aterms = d.aterms;
    const __half *Ah = d.Ah, *Al = d.Al, *Bh = d.Bh;
    const int nchunks = d.K >> 6;

    auto load_stage = [&](int stg, int chunk) {
        const uint32_t sbase = smem_u32(smem) + stg * STAGE_B;
        const int k0 = chunk << 6;
#pragma unroll
        for (int it = 0; it < 4; it++) {
            int linear = tid + it * 256;
            int row = linear >> 3, seg = (linear & 7) << 3;
            uint32_t soff = (uint32_t)(row * 144 + seg * 2);
            size_t ga = (size_t)(m0 + row) * lda + k0 + seg;
            cpasync16(sbase + soff, Ah + ga);
            if (aterms == 2) cpasync16(sbase + TILE_B + soff, Al + ga);
            size_t gb = (size_t)(n0 + row) * ldb + k0 + seg;
            cpasync16(sbase + 2 * TILE_B + soff, Bh + gb);
        }
    };

    float acc[4][4][4] = {};

    load_stage(0, 0);
    CP_COMMIT();

    int st = 0;
    for (int i = 0; i < nchunks; i++) {
        if (i + 1 < nchunks) {
            load_stage(st ^ 1, i + 1);
            CP_COMMIT();
            CP_WAIT(1);
        } else {
            CP_WAIT(0);
        }
        __syncthreads();

        const char* base = smem + st * STAGE_B;
#pragma unroll
        for (int kk = 0; kk < 4; kk++) {
            const int kcol = kk * 16;
            uint32_t ah[4][4], al[4][4], bh[4][2];
#pragma unroll
            for (int mt = 0; mt < 4; mt++) {
                int row = wm * 64 + mt * 16 + l8 + ((grp & 1) << 3);
                int col = kcol + ((grp >> 1) << 3);
                uint32_t a0 = smem_u32(base + row * 144 + col * 2);
                ldsm4(ah[mt][0], ah[mt][1], ah[mt][2], ah[mt][3], a0);
                if (aterms == 2)
                    ldsm4(al[mt][0], al[mt][1], al[mt][2], al[mt][3], a0 + TILE_B);
            }
#pragma unroll
            for (int ntp = 0; ntp < 2; ntp++) {
                int row = wn * 32 + ntp * 16 + ((grp >> 1) << 3) + l8;
                int col = kcol + ((grp & 1) << 3);
                uint32_t b0 = smem_u32(base + 2 * TILE_B + row * 144 + col * 2);
                ldsm4(bh[2 * ntp][0], bh[2 * ntp][1], bh[2 * ntp + 1][0], bh[2 * ntp + 1][1], b0);
            }
#pragma unroll
            for (int mt = 0; mt < 4; mt++)
#pragma unroll
                for (int nt = 0; nt < 4; nt++) mma_fp(acc[mt][nt], ah[mt], bh[nt]);
            if (aterms == 2) {
#pragma unroll
                for (int mt = 0; mt < 4; mt++)
#pragma unroll
                    for (int nt = 0; nt < 4; nt++) mma_fp(acc[mt][nt], al[mt], bh[nt]);
            }
        }
        __syncthreads();
        st ^= 1;
    }

    if (d.qp) {
        // fused symmetric-quad epilogue: acc*(2x - xh) + (V1[s]+V2[o])*x
        float pt[4], pb[4];
#pragma unroll
        for (int mt = 0; mt < 4; mt++) {
            int mtop = m0 + wm * 64 + mt * 16 + (lane >> 2);
            int mbot = mtop + 8;
            int s1 = d.sbjp[mtop], o1 = d.objp[mtop];
            int s2 = d.sbjp[mbot], o2 = d.objp[mbot];
            float at = 0.f, ab = 0.f;
#pragma unroll
            for (int nt = 0; nt < 4; nt++) {
                int n = n0 + wn * 32 + nt * 8 + (lane & 3) * 2;
                float2 xt = *(const float2*)(d.xptr + (size_t)mtop * lda + n);
                float2 xb = *(const float2*)(d.xptr + (size_t)mbot * lda + n);
                float2 xht = __half22float2(*(const __half2*)(d.Ah + (size_t)mtop * lda + n));
                float2 xhb = __half22float2(*(const __half2*)(d.Ah + (size_t)mbot * lda + n));
                float2 v1t = *(const float2*)(d.v1p + (size_t)s1 * Dd + n);
                float2 v2t = *(const float2*)(d.v2p + (size_t)o1 * Dd + n);
                float2 v1b = *(const float2*)(d.v1p + (size_t)s2 * Dd + n);
                float2 v2b = *(const float2*)(d.v2p + (size_t)o2 * Dd + n);
                at += acc[mt][nt][0] * (2.f * xt.x - xht.x) + (v1t.x + v2t.x) * xt.x
                    + acc[mt][nt][1] * (2.f * xt.y - xht.y) + (v1t.y + v2t.y) * xt.y;
                ab += acc[mt][nt][2] * (2.f * xb.x - xhb.x) + (v1b.x + v2b.x) * xb.x
                    + acc[mt][nt][3] * (2.f * xb.y - xhb.y) + (v1b.y + v2b.y) * xb.y;
            }
            at += __shfl_xor_sync(0xffffffffu, at, 1);
            at += __shfl_xor_sync(0xffffffffu, at, 2);
            ab += __shfl_xor_sync(0xffffffffu, ab, 1);
            ab += __shfl_xor_sync(0xffffffffu, ab, 2);
            pt[mt] = at; pb[mt] = ab;
        }
        __syncthreads();
        float* qs = (float*)smem;
        if ((lane & 3) == 0) {
#pragma unroll
            for (int mt = 0; mt < 4; mt++) {
                int rt = wm * 64 + mt * 16 + (lane >> 2);
                qs[rt * 4 + wn] = pt[mt];
                qs[(rt + 8) * 4 + wn] = pb[mt];
            }
        }
        __syncthreads();
        if (tid < 128) {
            float q = qs[tid * 4] + qs[tid * 4 + 1] + qs[tid * 4 + 2] + qs[tid * 4 + 3];
            d.qp[(size_t)(m0 + tid) * 8 + blockIdx.x] = q;
        }
        return;
    }

    const int ldc = d.ldc;
    if (d.emit == 3) {
        // final-mask epilogue: out = vf + involved ? (acc + bias) : 0
#pragma unroll
        for (int mt = 0; mt < 4; mt++)
#pragma unroll
            for (int nt = 0; nt < 4; nt++) {
                int m = m0 + wm * 64 + mt * 16 + (lane >> 2);
                int n = n0 + wn * 32 + nt * 8 + (lane & 3) * 2;
#pragma unroll
                for (int hrow = 0; hrow < 2; hrow++) {
                    int mm = m + hrow * 8;
                    bool inv = (d.v1p[mm] > 0.f) || (d.v2p[mm] > 0.f);
                    float2 b = *(const float2*)(d.bias + n);
                    float2 base = *(const float2*)(d.xptr + (size_t)mm * ldc + n);
                    float2 v;
                    v.x = base.x + (inv ? acc[mt][nt][hrow * 2]     + b.x : 0.f);
                    v.y = base.y + (inv ? acc[mt][nt][hrow * 2 + 1] + b.y : 0.f);
                    *(float2*)(d.C + (size_t)mm * ldc + n) = v;
                }
            }
        return;
    }

    // ---- standard epilogue ----
#pragma unroll
    for (int mt = 0; mt < 4; mt++)
#pragma unroll
        for (int nt = 0; nt < 4; nt++) {
            int m = m0 + wm * 64 + mt * 16 + (lane >> 2);
            int n = n0 + wn * 32 + nt * 8 + (lane & 3) * 2;
#pragma unroll
            for (int hrow = 0; hrow < 2; hrow++) {
                int mm = m + hrow * 8;
                float2 v = make_float2(acc[mt][nt][hrow * 2] * d.cscale,
                                       acc[mt][nt][hrow * 2 + 1] * d.cscale);
                if (d.addsrc) {
                    float2 s = *(const float2*)(d.addsrc + (size_t)mm * ldc + n);
                    v.x += s.x; v.y += s.y;
                }
                if (d.bias) {
                    float2 b = *(const float2*)(d.bias + n);
                    v.x += b.x; v.y += b.y;
                }
                *(float2*)(d.C + (size_t)mm * ldc + n) = v;
                if (d.emit == 1) {
                    __half h0 = __float2half_rn(v.x), h1 = __float2half_rn(v.y);
                    d.Chi[(size_t)mm * ldc + n]     = h0;
                    d.Chi[(size_t)mm * ldc + n + 1] = h1;
                    d.Clo[(size_t)mm * ldc + n]     = __float2half_rn(v.x - __half2float(h0));
                    d.Clo[(size_t)mm * ldc + n + 1] = __float2half_rn(v.y - __half2float(h1));
                }
            }
        }
}

// ================= prologue kernels =================
__global__ void rvfprep(const float4* __restrict__ src, float4* __restrict__ out,
                        __half2* __restrict__ hi, long long n4,
                        float* __restrict__ wmat, int nn2,
                        const float* __restrict__ brel, const float* __restrict__ bsbj,
                        const float* __restrict__ bobj, float* __restrict__ biascat)
{
    long long stride = (long long)gridDim.x * blockDim.x;
    long long t0 = (long long)blockIdx.x * blockDim.x + threadIdx.x;
    for (long long i = t0; i < n4; i += stride) {
        float4 v = src[i];
        out[i] = v;
        hi[2 * i]     = __halves2half2(__float2half_rn(v.x), __float2half_rn(v.y));
        hi[2 * i + 1] = __halves2half2(__float2half_rn(v.z), __float2half_rn(v.w));
    }
    for (long long i = t0; i < nn2; i += stride) wmat[i] = 0.f;
    for (long long i = t0; i < 4 * Dd; i += stride) {
        int c = (int)i >> 10, n = (int)i & 1023;
        biascat[i] = (c == 0) ? 0.f : (c == 1 ? brel[n] : (c == 2 ? bsbj[n] : bobj[n]));
    }
}

struct SplitDesc { const float* src; __half *hi, *lo; long long n; };
struct SplitBatch { SplitDesc d[4]; };
__global__ void splitmulti(SplitBatch b)
{
    SplitDesc d = b.d[blockIdx.z];
    long long n4 = d.n >> 2;
    __half2* hi2 = (__half2*)d.hi;
    __half2* lo2 = (__half2*)d.lo;
    const float4* s4 = (const float4*)d.src;
    for (long long i = (long long)blockIdx.x * blockDim.x + threadIdx.x; i < n4;
         i += (long long)gridDim.x * blockDim.x) {
        float4 v = s4[i];
        __half hx = __float2half_rn(v.x), hy = __float2half_rn(v.y);
        __half hz = __float2half_rn(v.z), hw = __float2half_rn(v.w);
        hi2[2 * i]     = __halves2half2(hx, hy);
        hi2[2 * i + 1] = __halves2half2(hz, hw);
        lo2[2 * i]     = __halves2half2(__float2half_rn(v.x - __half2float(hx)),
                                        __float2half_rn(v.y - __half2float(hy)));
        lo2[2 * i + 1] = __halves2half2(__float2half_rn(v.z - __half2float(hz)),
                                        __float2half_rn(v.w - __half2float(hw)));
    }
}

__global__ void splitk(const float* __restrict__ src, __half* __restrict__ hi,
                       __half* __restrict__ lo, long long n)
{
    long long n4 = n >> 2;
    __half2* hi2 = (__half2*)hi;
    __half2* lo2 = (__half2*)lo;
    const float4* s4 = (const float4*)src;
    for (long long i = (long long)blockIdx.x * blockDim.x + threadIdx.x; i < n4;
         i += (long long)gridDim.x * blockDim.x) {
        float4 v = s4[i];
        __half hx = __float2half_rn(v.x), hy = __float2half_rn(v.y);
        __half hz = __float2half_rn(v.z), hw = __float2half_rn(v.w);
        hi2[2 * i]     = __halves2half2(hx, hy);
        hi2[2 * i + 1] = __halves2half2(hz, hw);
        lo2[2 * i]     = __halves2half2(__float2half_rn(v.x - __half2float(hx)),
                                        __float2half_rn(v.y - __half2float(hy)));
        lo2[2 * i + 1] = __halves2half2(__float2half_rn(v.z - __half2float(hz)),
                                        __float2half_rn(v.w - __half2float(hw)));
    }
}

struct TSplitDesc { const float* src; __half *hi, *lo; int R; };
struct TSplitBatch { TSplitDesc d[7]; };
__global__ void tsplitmulti(TSplitBatch b)   // src [R][1024] -> dst [1024][R] hi/lo
{
    TSplitDesc d = b.d[blockIdx.z];
    __shared__ float tile[32][33];
    int cx = blockIdx.x * 32, ry = blockIdx.y * 32;
    if (ry >= d.R) return;
    int tx = threadIdx.x, ty = threadIdx.y;  // 32 x 8
#pragma unroll
    for (int i = 0; i < 32; i += 8)
        tile[ty + i][tx] = d.src[(size_t)(ry + ty + i) * Dd + cx + tx];
    __syncthreads();
#pragma unroll
    for (int i = 0; i < 32; i += 8) {
        float v = tile[tx][ty + i];
        __half h = __float2half_rn(v);
        size_t o = (size_t)(cx + ty + i) * d.R + ry + tx;
        d.hi[o] = h;
        d.lo[o] = __float2half_rn(v - __half2float(h));
    }
}

__global__ void msymk()   // Msym = M + M^T, split to fp16 hi/lo
{
    int idx = blockIdx.x * 256 + threadIdx.x;
    if (idx < Dd * Dd) {
        int i = idx >> 10, j = idx & 1023;
        float v = g_s.M[idx] + g_s.M[j * Dd + i];
        __half h = __float2half_rn(v);
        g_Msymh[idx] = h;
        g_Msyml[idx] = __float2half_rn(v - __half2float(h));
    }
}

// ================= graph epilogue kernels =================
__global__ void rowdots(float* __restrict__ S1, float* __restrict__ S2)
{
    int n = blockIdx.x, tid = threadIdx.x;
    const float* a  = g_s.X4 + (size_t)n * 4096;
    const float* bp = a + 1024;
    float s1 = 0.f, s2 = 0.f;
    for (int d = tid; d < Dd; d += 256) {
        s1 += a[d]  * (g_s.U1[(size_t)n * Dd + d] + g_s.CW[(size_t)n * Dd + d]);
        s2 += bp[d] * (g_s.U2[(size_t)n * Dd + d] + g_s.GW[(size_t)n * Dd + d]);
    }
    __shared__ float r1[256], r2[256];
    r1[tid] = s1; r2[tid] = s2; __syncthreads();
    for (int st = 128; st > 0; st >>= 1) {
        if (tid < st) { r1[tid] += r1[tid + st]; r2[tid] += r2[tid + st]; }
        __syncthreads();
    }
    if (tid == 0) { S1[n] = 0.5f * r1[0]; S2[n] = 0.5f * r2[0]; }
}

__global__ void logitsk(const int* __restrict__ sbj, const int* __restrict__ obj,
                        int E, int Nn, float scale)
{
    int e = blockIdx.x * 256 + threadIdx.x;
    if (e >= E) return;
    const float* qp = g_s.quadP + (size_t)e * 8;
    float q = qp[0] + qp[1] + qp[2] + qp[3] + qp[4] + qp[5] + qp[6] + qp[7];
    int s = sbj[e], o = obj[e];
    size_t po = (size_t)s * Nn + o;
    g_s.logits[e] = (q + g_s.Pa[po] + g_s.Pb[po] + g_s.Pc[po] + g_s.S1[s] + g_s.S2[o]) * scale;
}

// single-pass online-softmax segment stats for BOTH segmentations.
// one block per node; deterministic (fixed stride order + fixed tree merge).
__global__ void segstats(const int* __restrict__ sbj, const int* __restrict__ obj, int E)
{
    int n = blockIdx.x, tid = threadIdx.x;
    float ms = -1e30f, ss = 0.f, mo = -1e30f, so = 0.f;
    for (int e = tid; e < E; e += 256) {
        float l = g_s.logits[e];
        if (sbj[e] == n) {
            if (l > ms) { ss = ss * expf(ms - l) + 1.f; ms = l; }
            else        { ss += expf(l - ms); }
        }
        if (obj[e] == n) {
            if (l > mo) { so = so * expf(mo - l) + 1.f; mo = l; }
            else        { so += expf(l - mo); }
        }
    }
    __shared__ float rm1[256], rs1[256], rm2[256], rs2[256];
    rm1[tid] = ms; rs1[tid] = ss; rm2[tid] = mo; rs2[tid] = so;
    __syncthreads();
    for (int st = 128; st > 0; st >>= 1) {
        if (tid < st) {
            float m1 = rm1[tid], s1 = rs1[tid], m2 = rm1[tid + st], s2 = rs1[tid + st];
            float M = fmaxf(m1, m2);
            rs1[tid] = s1 * expf(m1 - M) + s2 * expf(m2 - M);
            rm1[tid] = M;
            m1 = rm2[tid]; s1 = rs2[tid]; m2 = rm2[tid + st]; s2 = rs2[tid + st];
            M = fmaxf(m1, m2);
            rs2[tid] = s1 * expf(m1 - M) + s2 * expf(m2 - M);
            rm2[tid] = M;
        }
        __syncthreads();
    }
    if (tid == 0) {
        g_s.maxs[n] = rm1[0]; g_s.sums[n] = rs1[0];
        g_s.maxo[n] = rm2[0]; g_s.sumo[n] = rs2[0];
    }
}

__global__ void wmatk(const int* __restrict__ sbj, const int* __restrict__ obj,
                      int E, int Nn)
{
    int e = blockIdx.x * 256 + threadIdx.x;
    if (e >= E) return;
    float l = g_s.logits[e];
    int s = sbj[e], o = obj[e];
    float ws = expf(l - g_s.maxs[s]) / g_s.sums[s];
    float wo = expf(l - g_s.maxo[o]) / g_s.sumo[o];
    atomicAdd(&g_s.Wmat[(size_t)s * Nn + o], ws);
    atomicAdd(&g_s.Wmat[(size_t)o * Nn + s], wo);
}

// ================= host orchestration =================
static GemmDesc mkdesc(const __half* Ah, const __half* Al, int lda,
                       const __half* Bh, int ldb,
                       float* C, int ldc, const float* addsrc, const float* bias,
                       __half* Chi, __half* Clo, int M, int N, int K, float cscale = 1.0f)
{
    GemmDesc d{};
    d.Ah = Ah; d.Al = Al; d.Bh = Bh;
    d.addsrc = addsrc; d.bias = bias; d.C = C; d.Chi = Chi; d.Clo = Clo;
    d.lda = lda; d.ldb = ldb; d.ldc = ldc; d.K = K;
    d.mb = M / 128; d.nb = N / 128; d.cscale = cscale;
    d.emit = Chi ? 1 : 0;
    d.aterms = 2;
    return d;
}

static void launch_batch(GemmDesc* ds, int nd)
{
    GemmBatch b{};
    int mx = 0, nx = 0;
    for (int i = 0; i < nd; i++) { b.d[i] = ds[i]; if (ds[i].mb > mx) mx = ds[i].mb; if (ds[i].nb > nx) nx = ds[i].nb; }
    for (int i = nd; i < 6; i++) { b.d[i] = ds[0]; }
    dim3 grid(nx, mx, nd);
    mgemm3<<<grid, 256, SMEM_TOT>>>(b);
}

extern "C" void kernel_launch(void* const* d_in, const int* in_sizes, int n_in,
                              void* d_out, int out_size)
{
    const float* vf   = (const float*)d_in[0];
    const float* rvf  = (const float*)d_in[1];
    const float* Wrel = (const float*)d_in[2];
    const float* brel = (const float*)d_in[3];
    const float* Wsbj = (const float*)d_in[4];
    const float* bsbj = (const float*)d_in[5];
    const float* Wobj = (const float*)d_in[6];
    const float* bobj = (const float*)d_in[7];
    const float* Wctx = (const float*)d_in[8];
    const float* bctx = (const float*)d_in[9];
    const int*   sbj  = (const int*)d_in[10];
    const int*   obj  = (const int*)d_in[11];

    const int Nn = in_sizes[0] / Dd;    // 768
    const int E  = in_sizes[10];        // 24576
    float* out = (float*)d_out;

    cudaFuncSetAttribute(mgemm3, cudaFuncAttributeMaxDynamicSharedMemorySize, SMEM_TOT);

    Scratch* S = nullptr;
    cudaGetSymbolAddress((void**)&S, g_s);
    __half *rvfh, *vfh, *vfl, *WcatTh, *WcatTl, *WctxTh, *WctxTl;
    __half *Wrrh, *Wrrl, *Wsrh, *Wsrl, *Worh, *Worl, *WorTh, *WorTl, *WsrTh, *WsrTl;
    __half *X4h, *X4l, *Msh, *Msl, *T1h, *T1l, *Kqh, *Kql;
    __half *W2h, *W2l, *W3h, *W3l, *VWTh, *VWTl;
    __half *U1h, *U1l, *U2h, *U2l, *GWh, *GWl, *Wmh, *Wml;
    cudaGetSymbolAddress((void**)&rvfh, g_rvfh);
    cudaGetSymbolAddress((void**)&vfh, g_vfh);     cudaGetSymbolAddress((void**)&vfl, g_vfl);
    cudaGetSymbolAddress((void**)&WcatTh, g_WcatTh); cudaGetSymbolAddress((void**)&WcatTl, g_WcatTl);
    cudaGetSymbolAddress((void**)&WctxTh, g_WctxTh); cudaGetSymbolAddress((void**)&WctxTl, g_WctxTl);
    cudaGetSymbolAddress((void**)&Wrrh, g_Wrrh);   cudaGetSymbolAddress((void**)&Wrrl, g_Wrrl);
    cudaGetSymbolAddress((void**)&Wsrh, g_Wsrh);   cudaGetSymbolAddress((void**)&Wsrl, g_Wsrl);
    cudaGetSymbolAddress((void**)&Worh, g_Worh);   cudaGetSymbolAddress((void**)&Worl, g_Worl);
    cudaGetSymbolAddress((void**)&WorTh, g_WorTh); cudaGetSymbolAddress((void**)&WorTl, g_WorTl);
    cudaGetSymbolAddress((void**)&WsrTh, g_WsrTh); cudaGetSymbolAddress((void**)&WsrTl, g_WsrTl);
    cudaGetSymbolAddress((void**)&X4h, g_X4h);     cudaGetSymbolAddress((void**)&X4l, g_X4l);
    cudaGetSymbolAddress((void**)&Msh, g_Msymh);   cudaGetSymbolAddress((void**)&Msl, g_Msyml);
    cudaGetSymbolAddress((void**)&T1h, g_T1h);     cudaGetSymbolAddress((void**)&T1l, g_T1l);
    cudaGetSymbolAddress((void**)&Kqh, g_Kqh);     cudaGetSymbolAddress((void**)&Kql, g_Kql);
    cudaGetSymbolAddress((void**)&W2h, g_W2h);     cudaGetSymbolAddress((void**)&W2l, g_W2l);
    cudaGetSymbolAddress((void**)&W3h, g_W3h);     cudaGetSymbolAddress((void**)&W3l, g_W3l);
    cudaGetSymbolAddress((void**)&VWTh, g_VWTh);   cudaGetSymbolAddress((void**)&VWTl, g_VWTl);
    cudaGetSymbolAddress((void**)&U1h, g_U1h);     cudaGetSymbolAddress((void**)&U1l, g_U1l);
    cudaGetSymbolAddress((void**)&U2h, g_U2h);     cudaGetSymbolAddress((void**)&U2l, g_U2l);
    cudaGetSymbolAddress((void**)&GWh, g_GWh);     cudaGetSymbolAddress((void**)&GWl, g_GWl);
    cudaGetSymbolAddress((void**)&Wmh, g_Wmath);   cudaGetSymbolAddress((void**)&Wml, g_Wmatl);

    const float* Wr_r = Wrel + 2 * Dd * Dd;
    const float* Ws_r = Wsbj + Dd * Dd;
    const float* Wo_r = Wobj + Dd * Dd;

    // P0: rvf copy + fp16 hi split + Wmat zero + biascat
    long long n4 = (long long)E * Dd / 4;
    rvfprep<<<4096, 256>>>((const float4*)rvf, (float4*)out,
                           (__half2*)rvfh, n4,
                           S->Wmat, Nn * Nn, brel, bsbj, bobj, S->biascat);

    // P1: flat splits (vf, Wrr, Wsr, Wor)
    {
        SplitBatch sb{};
        sb.d[0] = { vf,   vfh,  vfl,  (long long)Nn * Dd };
        sb.d[1] = { Wr_r, Wrrh, Wrrl, (long long)Dd * Dd };
        sb.d[2] = { Ws_r, Wsrh, Wsrl, (long long)Dd * Dd };
        sb.d[3] = { Wo_r, Worh, Worl, (long long)Dd * Dd };
        splitmulti<<<dim3(256, 1, 4), 256>>>(sb);
    }
    // P2: transposed splits (WctxT, WcatT x4, WorT, WsrT)
    {
        TSplitBatch tb{};
        tb.d[0] = { Wctx,           WctxTh,               WctxTl,               Dd };
        tb.d[1] = { Wrel,           WcatTh + 0 * Dd * Dd, WcatTl + 0 * Dd * Dd, Dd };
        tb.d[2] = { Wrel + Dd * Dd, WcatTh + 1 * Dd * Dd, WcatTl + 1 * Dd * Dd, Dd };
        tb.d[3] = { Wsbj,           WcatTh + 2 * Dd * Dd, WcatTl + 2 * Dd * Dd, Dd };
        tb.d[4] = { Wobj,           WcatTh + 3 * Dd * Dd, WcatTl + 3 * Dd * Dd, Dd };
        tb.d[5] = { Wo_r,           WorTh,                WorTl,                Dd };
        tb.d[6] = { Ws_r,           WsrTh,                WsrTl,                Dd };
        tsplitmulti<<<dim3(32, 32, 7), dim3(32, 8)>>>(tb);
    }

    // B1: X4, M, W2'=Wrr@Wor, W3'=Wrr@Wsr, VWT=Wctx^T·vf^T
    {
        GemmDesc ds[5] = {
            mkdesc(vfh, vfl, Dd, WcatTh, Dd, S->X4, 4096, nullptr, S->biascat, X4h, X4l, Nn, 4096, Dd),
            mkdesc(Wsrh, Wsrl, Dd, Worh, Dd, S->M, Dd, nullptr, nullptr, nullptr, nullptr, Dd, Dd, Dd),
            mkdesc(Wrrh, Wrrl, Dd, WorTh, Dd, S->W2, Dd, nullptr, nullptr, W2h, W2l, Dd, Dd, Dd),
            mkdesc(Wrrh, Wrrl, Dd, WsrTh, Dd, S->W3, Dd, nullptr, nullptr, W3h, W3l, Dd, Dd, Dd),
            mkdesc(WctxTh, WctxTl, Dd, vfh, Dd, S->VWT, Nn, nullptr, nullptr, VWTh, VWTl, Dd, Nn, Dd)
        };
        launch_batch(ds, 5);
    }
    msymk<<<(Dd * Dd + 255) / 256, 256>>>();

    // B2: T1=Wrr@Msym, CW, GW, Pa=C@G^T, V1a=C@W2'^T, V2a=G@W3'^T
    {
        GemmDesc ds[6] = {
            mkdesc(Wrrh, Wrrl, Dd, Msh, Dd, S->T1, Dd, nullptr, nullptr, T1h, T1l, Dd, Dd, Dd),
            mkdesc(X4h + 2048, X4l + 2048, 4096, Worh, Dd, S->CW, Dd, nullptr, nullptr, nullptr, nullptr, Nn, Dd, Dd),
            mkdesc(X4h + 3072, X4l + 3072, 4096, Wsrh, Dd, S->GW, Dd, nullptr, nullptr, GWh, GWl, Nn, Dd, Dd),
            mkdesc(X4h + 2048, X4l + 2048, 4096, X4h + 3072, 4096, S->Pa, Nn, nullptr, nullptr, nullptr, nullptr, Nn, Nn, Dd),
            mkdesc(X4h + 2048, X4l + 2048, 4096, W2h, Dd, S->V1, Dd, nullptr, nullptr, nullptr, nullptr, Nn, Dd, Dd),
            mkdesc(X4h + 3072, X4l + 3072, 4096, W3h, Dd, S->V2, Dd, nullptr, nullptr, nullptr, nullptr, Nn, Dd, Dd)
        };
        launch_batch(ds, 6);
    }

    // B3: U1=A@Msym+CW, U2=B'@Msym+GW, Kq=0.5*T1@Wrr^T, V1=A@T1^T+V1a, V2=B'@T1^T+V2a
    {
        GemmDesc ds[5] = {
            mkdesc(X4h, X4l, 4096, Msh, Dd, S->U1, Dd, S->CW, nullptr, U1h, U1l, Nn, Dd, Dd),
            mkdesc(X4h + 1024, X4l + 1024, 4096, Msh, Dd, S->U2, Dd, S->GW, nullptr, U2h, U2l, Nn, Dd, Dd),
            mkdesc(T1h, T1l, Dd, Wrrh, Dd, S->Kq, Dd, nullptr, nullptr, Kqh, Kql, Dd, Dd, Dd, 0.5f),
            mkdesc(X4h, X4l, 4096, T1h, Dd, S->V1, Dd, S->V1, nullptr, nullptr, nullptr, Nn, Dd, Dd),
            mkdesc(X4h + 1024, X4l + 1024, 4096, T1h, Dd, S->V2, Dd, S->V2, nullptr, nullptr, nullptr, Nn, Dd, Dd)
        };
        launch_batch(ds, 5);
    }
    rowdots<<<Nn, 256>>>(S->S1, S->S2);

    // B4: quad GEMM (xh @ Kq, single A-term, symmetric-quad epilogue), Pb, Pc
    {
        GemmDesc ds[3];
        ds[0] = mkdesc(rvfh, rvfh, Dd, Kqh, Dd, nullptr, Dd, nullptr, nullptr,
                       nullptr, nullptr, E, Dd, Dd);
        ds[0].emit = 0;
        ds[0].aterms = 1;
        ds[0].xptr = rvf; ds[0].sbjp = sbj; ds[0].objp = obj;
        ds[0].v1p = S->V1; ds[0].v2p = S->V2; ds[0].qp = S->quadP;
        ds[1] = mkdesc(U1h, U1l, Dd, X4h + 1024, 4096, S->Pb, Nn, nullptr, nullptr, nullptr, nullptr, Nn, Nn, Dd);
        ds[2] = mkdesc(X4h, X4l, 4096, GWh, Dd, S->Pc, Nn, nullptr, nullptr, nullptr, nullptr, Nn, Nn, Dd);
        launch_batch(ds, 3);
    }

    // logits, softmax stats, mixing matrix
    logitsk<<<(E + 255) / 256, 256>>>(sbj, obj, E, Nn, 1.0f / sqrtf((float)Dd));
    segstats<<<Nn, 256>>>(sbj, obj, E);
    wmatk<<<(E + 255) / 256, 256>>>(sbj, obj, E, Nn);
    splitk<<<256, 256>>>(S->Wmat, Wmh, Wml, (long long)Nn * Nn);

    // B5: ctxW = Wmat @ VWT^T + bctx, fused final-mask epilogue -> out
    {
        GemmDesc d = mkdesc(Wmh, Wml, Nn, VWTh, Nn, out + (size_t)E * Dd, Dd,
                            nullptr, bctx, nullptr, nullptr, Nn, Dd, Nn);
        d.emit = 3;
        d.xptr = vf; d.v1p = S->sums; d.v2p = S->sumo;
        launch_batch(&d, 1);
    }
}

// round 12
// speedup vs baseline: 6.1573x; 1.4193x over previous
#include <cuda_runtime.h>
#include <cuda_fp16.h>
#include <math.h>
#include <stdint.h>

#define Dd 1024
#define MAXN 1024
#define MAXE 32768

// ================= static scratch =================
struct Scratch {
    float X4[MAXN * 4 * Dd];      // [A | B' | C | G], ld=4096
    float biascat[4 * Dd];
    float M[Dd * Dd];
    float T1[Dd * Dd];
    float Kq[Dd * Dd];
    float W2[Dd * Dd];            // Wrr @ Wor
    float W3[Dd * Dd];            // Wrr @ Wsr
    float VWT[Dd * MAXN];         // (vf @ Wctx)^T
    float CW[MAXN * Dd];
    float GW[MAXN * Dd];
    float U1[MAXN * Dd];
    float U2[MAXN * Dd];
    float V1[MAXN * Dd];
    float V2[MAXN * Dd];
    float Pa[MAXN * MAXN];
    float Pb[MAXN * MAXN];
    float Pc[MAXN * MAXN];
    float S1[MAXN];
    float S2[MAXN];
    float quadP[(size_t)MAXE * 8];
    float logits[MAXE];
    float maxs[MAXN], sums[MAXN], maxo[MAXN], sumo[MAXN];
    float Wmat[MAXN * MAXN];
};
static __device__ Scratch g_s;

// fp16 (hi-only) operand storage
static __device__ __half g_rvfh[(size_t)MAXE * Dd];
static __device__ __half g_vfh[MAXN * Dd];
static __device__ __half g_WcatTh[4 * Dd * Dd];
static __device__ __half g_WctxTh[Dd * Dd];
static __device__ __half g_Wrrh[Dd * Dd];
static __device__ __half g_Wsrh[Dd * Dd];
static __device__ __half g_Worh[Dd * Dd];
static __device__ __half g_WorTh[Dd * Dd];
static __device__ __half g_WsrTh[Dd * Dd];
static __device__ __half g_X4h[MAXN * 4 * Dd];
static __device__ __half g_Msymh[Dd * Dd];
static __device__ __half g_T1h[Dd * Dd];
static __device__ __half g_Kqh[Dd * Dd];
static __device__ __half g_W2h[Dd * Dd];
static __device__ __half g_W3h[Dd * Dd];
static __device__ __half g_VWTh[Dd * MAXN];
static __device__ __half g_U1h[MAXN * Dd];
static __device__ __half g_U2h[MAXN * Dd];
static __device__ __half g_GWh[MAXN * Dd];
static __device__ __half g_Wmath[MAXN * MAXN];

// ================= PTX helpers =================
__device__ __forceinline__ uint32_t smem_u32(const void* p) {
    return (uint32_t)__cvta_generic_to_shared(p);
}
__device__ __forceinline__ void ldsm4(uint32_t& r0, uint32_t& r1, uint32_t& r2, uint32_t& r3, uint32_t a) {
    asm volatile("ldmatrix.sync.aligned.m8n8.x4.shared.b16 {%0,%1,%2,%3}, [%4];"
                 : "=r"(r0), "=r"(r1), "=r"(r2), "=r"(r3) : "r"(a));
}
__device__ __forceinline__ void mma_fp(float* d, const uint32_t* a, const uint32_t* b) {
    asm volatile("mma.sync.aligned.m16n8k16.row.col.f32.f16.f16.f32 "
                 "{%0,%1,%2,%3}, {%4,%5,%6,%7}, {%8,%9}, {%0,%1,%2,%3};"
                 : "+f"(d[0]), "+f"(d[1]), "+f"(d[2]), "+f"(d[3])
                 : "r"(a[0]), "r"(a[1]), "r"(a[2]), "r"(a[3]), "r"(b[0]), "r"(b[1]));
}
__device__ __forceinline__ void cpasync16(uint32_t saddr, const void* gaddr) {
    asm volatile("cp.async.cg.shared.global [%0], [%1], 16;" :: "r"(saddr), "l"(gaddr));
}
#define CP_COMMIT() asm volatile("cp.async.commit_group;" ::: "memory")
#define CP_WAIT(N)  asm volatile("cp.async.wait_group %0;" :: "n"(N) : "memory")

// ================= batched fp16 1-term mma.sync GEMM =================
// C = cscale*(Ah @ Bh^T) (+addsrc)(+bias). Both operands hi fp16.
// emit: 0 none, 1 fp16 hi, 3 final-mask mode (out = vf + involved*(acc+bias)).
// Quad mode (qp != null, B symmetric, A = xh fp16 of fp32 x at xptr):
//   quadP[m*8+blkx] = sum_n [ acc*(2x - xh) + (V1[s]+V2[o])*x ]   (= x·K·x + x·(V1+V2) to O(2^-22))
struct GemmDesc {
    const __half *Ah, *Bh;
    const float *addsrc, *bias;
    float* C;
    __half *Chi;
    const float* xptr;          // quad: rvf fp32 ; final: vf
    const int *sbjp, *objp;
    const float *v1p, *v2p;     // quad: V1,V2 ; final: sums,sumo
    float* qp;
    int lda, ldb, ldc, K, mb, nb;
    float cscale;
    int emit;
};
struct GemmBatch { GemmDesc d[6]; };

#define TILE_B    (128 * 144)              // 18432 B per matrix tile (pitch 144)
#define STAGE_B   (2 * TILE_B)             // Ah, Bh = 36864
#define SMEM_TOT  (2 * STAGE_B)            // 73728 -> 2 CTAs/SM (smem-light)

__global__ __launch_bounds__(256, 2)
void mgemm3(GemmBatch batch)
{
    extern __shared__ char smem[];
    const GemmDesc d = batch.d[blockIdx.z];
    if ((int)blockIdx.y >= d.mb || (int)blockIdx.x >= d.nb) return;

    const int tid = threadIdx.x;
    const int lane = tid & 31, warp = tid >> 5;
    const int wm = warp & 1, wn = warp >> 1;
    const int m0 = blockIdx.y * 128, n0 = blockIdx.x * 128;
    const int l8 = lane & 7, grp = lane >> 3;
    const int lda = d.lda, ldb = d.ldb;
    const __half *Ah = d.Ah, *Bh = d.Bh;
    const int nchunks = d.K >> 6;

    auto load_stage = [&](int stg, int chunk) {
        const uint32_t sbase = smem_u32(smem) + stg * STAGE_B;
        const int k0 = chunk << 6;
#pragma unroll
        for (int it = 0; it < 4; it++) {
            int linear = tid + it * 256;
            int row = linear >> 3, seg = (linear & 7) << 3;
            uint32_t soff = (uint32_t)(row * 144 + seg * 2);
            cpasync16(sbase + soff,          Ah + (size_t)(m0 + row) * lda + k0 + seg);
            cpasync16(sbase + TILE_B + soff, Bh + (size_t)(n0 + row) * ldb + k0 + seg);
        }
    };

    float acc[4][4][4] = {};

    load_stage(0, 0);
    CP_COMMIT();

    int st = 0;
    for (int i = 0; i < nchunks; i++) {
        if (i + 1 < nchunks) {
            load_stage(st ^ 1, i + 1);
            CP_COMMIT();
            CP_WAIT(1);
        } else {
            CP_WAIT(0);
        }
        __syncthreads();

        const char* base = smem + st * STAGE_B;
#pragma unroll
        for (int kk = 0; kk < 4; kk++) {
            const int kcol = kk * 16;
            uint32_t ah[4][4], bh[4][2];
#pragma unroll
            for (int mt = 0; mt < 4; mt++) {
                int row = wm * 64 + mt * 16 + l8 + ((grp & 1) << 3);
                int col = kcol + ((grp >> 1) << 3);
                ldsm4(ah[mt][0], ah[mt][1], ah[mt][2], ah[mt][3],
                      smem_u32(base + row * 144 + col * 2));
            }
#pragma unroll
            for (int ntp = 0; ntp < 2; ntp++) {
                int row = wn * 32 + ntp * 16 + ((grp >> 1) << 3) + l8;
                int col = kcol + ((grp & 1) << 3);
                ldsm4(bh[2 * ntp][0], bh[2 * ntp][1], bh[2 * ntp + 1][0], bh[2 * ntp + 1][1],
                      smem_u32(base + TILE_B + row * 144 + col * 2));
            }
#pragma unroll
            for (int mt = 0; mt < 4; mt++)
#pragma unroll
                for (int nt = 0; nt < 4; nt++) mma_fp(acc[mt][nt], ah[mt], bh[nt]);
        }
        __syncthreads();
        st ^= 1;
    }

    if (d.qp) {
        // fused symmetric-quad epilogue: acc*(2x - xh) + (V1[s]+V2[o])*x
        float pt[4], pb[4];
#pragma unroll
        for (int mt = 0; mt < 4; mt++) {
            int mtop = m0 + wm * 64 + mt * 16 + (lane >> 2);
            int mbot = mtop + 8;
            int s1 = d.sbjp[mtop], o1 = d.objp[mtop];
            int s2 = d.sbjp[mbot], o2 = d.objp[mbot];
            float at = 0.f, ab = 0.f;
#pragma unroll
            for (int nt = 0; nt < 4; nt++) {
                int n = n0 + wn * 32 + nt * 8 + (lane & 3) * 2;
                float2 xt = *(const float2*)(d.xptr + (size_t)mtop * lda + n);
                float2 xb = *(const float2*)(d.xptr + (size_t)mbot * lda + n);
                float2 xht = __half22float2(*(const __half2*)(d.Ah + (size_t)mtop * lda + n));
                float2 xhb = __half22float2(*(const __half2*)(d.Ah + (size_t)mbot * lda + n));
                float2 v1t = *(const float2*)(d.v1p + (size_t)s1 * Dd + n);
                float2 v2t = *(const float2*)(d.v2p + (size_t)o1 * Dd + n);
                float2 v1b = *(const float2*)(d.v1p + (size_t)s2 * Dd + n);
                float2 v2b = *(const float2*)(d.v2p + (size_t)o2 * Dd + n);
                at += acc[mt][nt][0] * (2.f * xt.x - xht.x) + (v1t.x + v2t.x) * xt.x
                    + acc[mt][nt][1] * (2.f * xt.y - xht.y) + (v1t.y + v2t.y) * xt.y;
                ab += acc[mt][nt][2] * (2.f * xb.x - xhb.x) + (v1b.x + v2b.x) * xb.x
                    + acc[mt][nt][3] * (2.f * xb.y - xhb.y) + (v1b.y + v2b.y) * xb.y;
            }
            at += __shfl_xor_sync(0xffffffffu, at, 1);
            at += __shfl_xor_sync(0xffffffffu, at, 2);
            ab += __shfl_xor_sync(0xffffffffu, ab, 1);
            ab += __shfl_xor_sync(0xffffffffu, ab, 2);
            pt[mt] = at; pb[mt] = ab;
        }
        __syncthreads();
        float* qs = (float*)smem;
        if ((lane & 3) == 0) {
#pragma unroll
            for (int mt = 0; mt < 4; mt++) {
                int rt = wm * 64 + mt * 16 + (lane >> 2);
                qs[rt * 4 + wn] = pt[mt];
                qs[(rt + 8) * 4 + wn] = pb[mt];
            }
        }
        __syncthreads();
        if (tid < 128) {
            float q = qs[tid * 4] + qs[tid * 4 + 1] + qs[tid * 4 + 2] + qs[tid * 4 + 3];
            d.qp[(size_t)(m0 + tid) * 8 + blockIdx.x] = q;
        }
        return;
    }

    const int ldc = d.ldc;
    if (d.emit == 3) {
        // final-mask epilogue: out = vf + involved ? (acc + bias) : 0
#pragma unroll
        for (int mt = 0; mt < 4; mt++)
#pragma unroll
            for (int nt = 0; nt < 4; nt++) {
                int m = m0 + wm * 64 + mt * 16 + (lane >> 2);
                int n = n0 + wn * 32 + nt * 8 + (lane & 3) * 2;
#pragma unroll
                for (int hrow = 0; hrow < 2; hrow++) {
                    int mm = m + hrow * 8;
                    bool inv = (d.v1p[mm] > 0.f) || (d.v2p[mm] > 0.f);
                    float2 b = *(const float2*)(d.bias + n);
                    float2 base = *(const float2*)(d.xptr + (size_t)mm * ldc + n);
                    float2 v;
                    v.x = base.x + (inv ? acc[mt][nt][hrow * 2]     + b.x : 0.f);
                    v.y = base.y + (inv ? acc[mt][nt][hrow * 2 + 1] + b.y : 0.f);
                    *(float2*)(d.C + (size_t)mm * ldc + n) = v;
                }
            }
        return;
    }

    // ---- standard epilogue ----
#pragma unroll
    for (int mt = 0; mt < 4; mt++)
#pragma unroll
        for (int nt = 0; nt < 4; nt++) {
            int m = m0 + wm * 64 + mt * 16 + (lane >> 2);
            int n = n0 + wn * 32 + nt * 8 + (lane & 3) * 2;
#pragma unroll
            for (int hrow = 0; hrow < 2; hrow++) {
                int mm = m + hrow * 8;
                float2 v = make_float2(acc[mt][nt][hrow * 2] * d.cscale,
                                       acc[mt][nt][hrow * 2 + 1] * d.cscale);
                if (d.addsrc) {
                    float2 s = *(const float2*)(d.addsrc + (size_t)mm * ldc + n);
                    v.x += s.x; v.y += s.y;
                }
                if (d.bias) {
                    float2 b = *(const float2*)(d.bias + n);
                    v.x += b.x; v.y += b.y;
                }
                *(float2*)(d.C + (size_t)mm * ldc + n) = v;
                if (d.emit == 1) {
                    *(__half2*)(d.Chi + (size_t)mm * ldc + n) =
                        __halves2half2(__float2half_rn(v.x), __float2half_rn(v.y));
                }
            }
        }
}

// ================= prologue kernels =================
__global__ void rvfprep(const float4* __restrict__ src, float4* __restrict__ out,
                        __half2* __restrict__ hi, long long n4,
                        float* __restrict__ wmat, int nn2,
                        const float* __restrict__ brel, const float* __restrict__ bsbj,
                        const float* __restrict__ bobj, float* __restrict__ biascat)
{
    long long stride = (long long)gridDim.x * blockDim.x;
    long long t0 = (long long)blockIdx.x * blockDim.x + threadIdx.x;
    for (long long i = t0; i < n4; i += stride) {
        float4 v = src[i];
        out[i] = v;
        hi[2 * i]     = __halves2half2(__float2half_rn(v.x), __float2half_rn(v.y));
        hi[2 * i + 1] = __halves2half2(__float2half_rn(v.z), __float2half_rn(v.w));
    }
    for (long long i = t0; i < nn2; i += stride) wmat[i] = 0.f;
    for (long long i = t0; i < 4 * Dd; i += stride) {
        int c = (int)i >> 10, n = (int)i & 1023;
        biascat[i] = (c == 0) ? 0.f : (c == 1 ? brel[n] : (c == 2 ? bsbj[n] : bobj[n]));
    }
}

struct ToHalfDesc { const float* src; __half* hi; long long n; };
struct ToHalfBatch { ToHalfDesc d[4]; };
__global__ void tohalfmulti(ToHalfBatch b)
{
    ToHalfDesc d = b.d[blockIdx.z];
    long long n4 = d.n >> 2;
    __half2* hi2 = (__half2*)d.hi;
    const float4* s4 = (const float4*)d.src;
    for (long long i = (long long)blockIdx.x * blockDim.x + threadIdx.x; i < n4;
         i += (long long)gridDim.x * blockDim.x) {
        float4 v = s4[i];
        hi2[2 * i]     = __halves2half2(__float2half_rn(v.x), __float2half_rn(v.y));
        hi2[2 * i + 1] = __halves2half2(__float2half_rn(v.z), __float2half_rn(v.w));
    }
}

__global__ void tohalfk(const float* __restrict__ src, __half* __restrict__ hi, long long n)
{
    long long n4 = n >> 2;
    __half2* hi2 = (__half2*)hi;
    const float4* s4 = (const float4*)src;
    for (long long i = (long long)blockIdx.x * blockDim.x + threadIdx.x; i < n4;
         i += (long long)gridDim.x * blockDim.x) {
        float4 v = s4[i];
        hi2[2 * i]     = __halves2half2(__float2half_rn(v.x), __float2half_rn(v.y));
        hi2[2 * i + 1] = __halves2half2(__float2half_rn(v.z), __float2half_rn(v.w));
    }
}

struct THalfDesc { const float* src; __half* hi; int R; };
struct THalfBatch { THalfDesc d[7]; };
__global__ void thalfmulti(THalfBatch b)   // src [R][1024] -> dst [1024][R] hi
{
    THalfDesc d = b.d[blockIdx.z];
    __shared__ float tile[32][33];
    int cx = blockIdx.x * 32, ry = blockIdx.y * 32;
    if (ry >= d.R) return;
    int tx = threadIdx.x, ty = threadIdx.y;  // 32 x 8
#pragma unroll
    for (int i = 0; i < 32; i += 8)
        tile[ty + i][tx] = d.src[(size_t)(ry + ty + i) * Dd + cx + tx];
    __syncthreads();
#pragma unroll
    for (int i = 0; i < 32; i += 8) {
        float v = tile[tx][ty + i];
        d.hi[(size_t)(cx + ty + i) * d.R + ry + tx] = __float2half_rn(v);
    }
}

__global__ void msymk()   // Msym = M + M^T -> fp16 hi
{
    int idx = blockIdx.x * 256 + threadIdx.x;
    if (idx < Dd * Dd) {
        int i = idx >> 10, j = idx & 1023;
        g_Msymh[idx] = __float2half_rn(g_s.M[idx] + g_s.M[j * Dd + i]);
    }
}

// ================= graph epilogue kernels =================
__global__ void rowdots(float* __restrict__ S1, float* __restrict__ S2)
{
    int n = blockIdx.x, tid = threadIdx.x;
    const float* a  = g_s.X4 + (size_t)n * 4096;
    const float* bp = a + 1024;
    float s1 = 0.f, s2 = 0.f;
    for (int d = tid; d < Dd; d += 256) {
        s1 += a[d]  * (g_s.U1[(size_t)n * Dd + d] + g_s.CW[(size_t)n * Dd + d]);
        s2 += bp[d] * (g_s.U2[(size_t)n * Dd + d] + g_s.GW[(size_t)n * Dd + d]);
    }
    __shared__ float r1[256], r2[256];
    r1[tid] = s1; r2[tid] = s2; __syncthreads();
    for (int st = 128; st > 0; st >>= 1) {
        if (tid < st) { r1[tid] += r1[tid + st]; r2[tid] += r2[tid + st]; }
        __syncthreads();
    }
    if (tid == 0) { S1[n] = 0.5f * r1[0]; S2[n] = 0.5f * r2[0]; }
}

__global__ void logitsk(const int* __restrict__ sbj, const int* __restrict__ obj,
                        int E, int Nn, float scale)
{
    int e = blockIdx.x * 256 + threadIdx.x;
    if (e >= E) return;
    const float* qp = g_s.quadP + (size_t)e * 8;
    float q = qp[0] + qp[1] + qp[2] + qp[3] + qp[4] + qp[5] + qp[6] + qp[7];
    int s = sbj[e], o = obj[e];
    size_t po = (size_t)s * Nn + o;
    g_s.logits[e] = (q + g_s.Pa[po] + g_s.Pb[po] + g_s.Pc[po] + g_s.S1[s] + g_s.S2[o]) * scale;
}

// single-pass online-softmax segment stats for BOTH segmentations (deterministic)
__global__ void segstats(const int* __restrict__ sbj, const int* __restrict__ obj, int E)
{
    int n = blockIdx.x, tid = threadIdx.x;
    float ms = -1e30f, ss = 0.f, mo = -1e30f, so = 0.f;
    for (int e = tid; e < E; e += 256) {
        float l = g_s.logits[e];
        if (sbj[e] == n) {
            if (l > ms) { ss = ss * expf(ms - l) + 1.f; ms = l; }
            else        { ss += expf(l - ms); }
        }
        if (obj[e] == n) {
            if (l > mo) { so = so * expf(mo - l) + 1.f; mo = l; }
            else        { so += expf(l - mo); }
        }
    }
    __shared__ float rm1[256], rs1[256], rm2[256], rs2[256];
    rm1[tid] = ms; rs1[tid] = ss; rm2[tid] = mo; rs2[tid] = so;
    __syncthreads();
    for (int st = 128; st > 0; st >>= 1) {
        if (tid < st) {
            float m1 = rm1[tid], s1 = rs1[tid], m2 = rm1[tid + st], s2 = rs1[tid + st];
            float M = fmaxf(m1, m2);
            rs1[tid] = s1 * expf(m1 - M) + s2 * expf(m2 - M);
            rm1[tid] = M;
            m1 = rm2[tid]; s1 = rs2[tid]; m2 = rm2[tid + st]; s2 = rs2[tid + st];
            M = fmaxf(m1, m2);
            rs2[tid] = s1 * expf(m1 - M) + s2 * expf(m2 - M);
            rm2[tid] = M;
        }
        __syncthreads();
    }
    if (tid == 0) {
        g_s.maxs[n] = rm1[0]; g_s.sums[n] = rs1[0];
        g_s.maxo[n] = rm2[0]; g_s.sumo[n] = rs2[0];
    }
}

__global__ void wmatk(const int* __restrict__ sbj, const int* __restrict__ obj,
                      int E, int Nn)
{
    int e = blockIdx.x * 256 + threadIdx.x;
    if (e >= E) return;
    float l = g_s.logits[e];
    int s = sbj[e], o = obj[e];
    float ws = expf(l - g_s.maxs[s]) / g_s.sums[s];
    float wo = expf(l - g_s.maxo[o]) / g_s.sumo[o];
    atomicAdd(&g_s.Wmat[(size_t)s * Nn + o], ws);
    atomicAdd(&g_s.Wmat[(size_t)o * Nn + s], wo);
}

// ================= host orchestration =================
static GemmDesc mkdesc(const __half* Ah, int lda, const __half* Bh, int ldb,
                       float* C, int ldc, const float* addsrc, const float* bias,
                       __half* Chi, int M, int N, int K, float cscale = 1.0f)
{
    GemmDesc d{};
    d.Ah = Ah; d.Bh = Bh;
    d.addsrc = addsrc; d.bias = bias; d.C = C; d.Chi = Chi;
    d.lda = lda; d.ldb = ldb; d.ldc = ldc; d.K = K;
    d.mb = M / 128; d.nb = N / 128; d.cscale = cscale;
    d.emit = Chi ? 1 : 0;
    return d;
}

static void launch_batch(GemmDesc* ds, int nd)
{
    GemmBatch b{};
    int mx = 0, nx = 0;
    for (int i = 0; i < nd; i++) { b.d[i] = ds[i]; if (ds[i].mb > mx) mx = ds[i].mb; if (ds[i].nb > nx) nx = ds[i].nb; }
    for (int i = nd; i < 6; i++) { b.d[i] = ds[0]; }
    dim3 grid(nx, mx, nd);
    mgemm3<<<grid, 256, SMEM_TOT>>>(b);
}

extern "C" void kernel_launch(void* const* d_in, const int* in_sizes, int n_in,
                              void* d_out, int out_size)
{
    const float* vf   = (const float*)d_in[0];
    const float* rvf  = (const float*)d_in[1];
    const float* Wrel = (const float*)d_in[2];
    const float* brel = (const float*)d_in[3];
    const float* Wsbj = (const float*)d_in[4];
    const float* bsbj = (const float*)d_in[5];
    const float* Wobj = (const float*)d_in[6];
    const float* bobj = (const float*)d_in[7];
    const float* Wctx = (const float*)d_in[8];
    const float* bctx = (const float*)d_in[9];
    const int*   sbj  = (const int*)d_in[10];
    const int*   obj  = (const int*)d_in[11];

    const int Nn = in_sizes[0] / Dd;    // 768
    const int E  = in_sizes[10];        // 24576
    float* out = (float*)d_out;

    cudaFuncSetAttribute(mgemm3, cudaFuncAttributeMaxDynamicSharedMemorySize, SMEM_TOT);

    Scratch* S = nullptr;
    cudaGetSymbolAddress((void**)&S, g_s);
    __half *rvfh, *vfh, *WcatTh, *WctxTh, *Wrrh, *Wsrh, *Worh, *WorTh, *WsrTh;
    __half *X4h, *Msh, *T1h, *Kqh, *W2h, *W3h, *VWTh, *U1h, *U2h, *GWh, *Wmh;
    cudaGetSymbolAddress((void**)&rvfh, g_rvfh);
    cudaGetSymbolAddress((void**)&vfh, g_vfh);
    cudaGetSymbolAddress((void**)&WcatTh, g_WcatTh);
    cudaGetSymbolAddress((void**)&WctxTh, g_WctxTh);
    cudaGetSymbolAddress((void**)&Wrrh, g_Wrrh);
    cudaGetSymbolAddress((void**)&Wsrh, g_Wsrh);
    cudaGetSymbolAddress((void**)&Worh, g_Worh);
    cudaGetSymbolAddress((void**)&WorTh, g_WorTh);
    cudaGetSymbolAddress((void**)&WsrTh, g_WsrTh);
    cudaGetSymbolAddress((void**)&X4h, g_X4h);
    cudaGetSymbolAddress((void**)&Msh, g_Msymh);
    cudaGetSymbolAddress((void**)&T1h, g_T1h);
    cudaGetSymbolAddress((void**)&Kqh, g_Kqh);
    cudaGetSymbolAddress((void**)&W2h, g_W2h);
    cudaGetSymbolAddress((void**)&W3h, g_W3h);
    cudaGetSymbolAddress((void**)&VWTh, g_VWTh);
    cudaGetSymbolAddress((void**)&U1h, g_U1h);
    cudaGetSymbolAddress((void**)&U2h, g_U2h);
    cudaGetSymbolAddress((void**)&GWh, g_GWh);
    cudaGetSymbolAddress((void**)&Wmh, g_Wmath);

    const float* Wr_r = Wrel + 2 * Dd * Dd;
    const float* Ws_r = Wsbj + Dd * Dd;
    const float* Wo_r = Wobj + Dd * Dd;

    // P0: rvf copy + fp16 hi + Wmat zero + biascat
    long long n4 = (long long)E * Dd / 4;
    rvfprep<<<4096, 256>>>((const float4*)rvf, (float4*)out,
                           (__half2*)rvfh, n4,
                           S->Wmat, Nn * Nn, brel, bsbj, bobj, S->biascat);

    // P1: flat fp16 conversions (vf, Wrr, Wsr, Wor)
    {
        ToHalfBatch sb{};
        sb.d[0] = { vf,   vfh,  (long long)Nn * Dd };
        sb.d[1] = { Wr_r, Wrrh, (long long)Dd * Dd };
        sb.d[2] = { Ws_r, Wsrh, (long long)Dd * Dd };
        sb.d[3] = { Wo_r, Worh, (long long)Dd * Dd };
        tohalfmulti<<<dim3(256, 1, 4), 256>>>(sb);
    }
    // P2: transposed fp16 conversions (WctxT, WcatT x4, WorT, WsrT)
    {
        THalfBatch tb{};
        tb.d[0] = { Wctx,           WctxTh,               Dd };
        tb.d[1] = { Wrel,           WcatTh + 0 * Dd * Dd, Dd };
        tb.d[2] = { Wrel + Dd * Dd, WcatTh + 1 * Dd * Dd, Dd };
        tb.d[3] = { Wsbj,           WcatTh + 2 * Dd * Dd, Dd };
        tb.d[4] = { Wobj,           WcatTh + 3 * Dd * Dd, Dd };
        tb.d[5] = { Wo_r,           WorTh,                Dd };
        tb.d[6] = { Ws_r,           WsrTh,                Dd };
        thalfmulti<<<dim3(32, 32, 7), dim3(32, 8)>>>(tb);
    }

    // B1: X4, M, W2'=Wrr@Wor, W3'=Wrr@Wsr, VWT=Wctx^T·vf^T
    {
        GemmDesc ds[5] = {
            mkdesc(vfh, Dd, WcatTh, Dd, S->X4, 4096, nullptr, S->biascat, X4h, Nn, 4096, Dd),
            mkdesc(Wsrh, Dd, Worh, Dd, S->M, Dd, nullptr, nullptr, nullptr, Dd, Dd, Dd),
            mkdesc(Wrrh, Dd, WorTh, Dd, S->W2, Dd, nullptr, nullptr, W2h, Dd, Dd, Dd),
            mkdesc(Wrrh, Dd, WsrTh, Dd, S->W3, Dd, nullptr, nullptr, W3h, Dd, Dd, Dd),
            mkdesc(WctxTh, Dd, vfh, Dd, S->VWT, Nn, nullptr, nullptr, VWTh, Dd, Nn, Dd)
        };
        launch_batch(ds, 5);
    }
    msymk<<<(Dd * Dd + 255) / 256, 256>>>();

    // B2: T1=Wrr@Msym, CW, GW, Pa=C@G^T, V1a=C@W2'^T, V2a=G@W3'^T
    {
        GemmDesc ds[6] = {
            mkdesc(Wrrh, Dd, Msh, Dd, S->T1, Dd, nullptr, nullptr, T1h, Dd, Dd, Dd),
            mkdesc(X4h + 2048, 4096, Worh, Dd, S->CW, Dd, nullptr, nullptr, nullptr, Nn, Dd, Dd),
            mkdesc(X4h + 3072, 4096, Wsrh, Dd, S->GW, Dd, nullptr, nullptr, GWh, Nn, Dd, Dd),
            mkdesc(X4h + 2048, 4096, X4h + 3072, 4096, S->Pa, Nn, nullptr, nullptr, nullptr, Nn, Nn, Dd),
            mkdesc(X4h + 2048, 4096, W2h, Dd, S->V1, Dd, nullptr, nullptr, nullptr, Nn, Dd, Dd),
            mkdesc(X4h + 3072, 4096, W3h, Dd, S->V2, Dd, nullptr, nullptr, nullptr, Nn, Dd, Dd)
        };
        launch_batch(ds, 6);
    }

    // B3: U1=A@Msym+CW, U2=B'@Msym+GW, Kq=0.5*T1@Wrr^T, V1=A@T1^T+V1a, V2=B'@T1^T+V2a
    {
        GemmDesc ds[5] = {
            mkdesc(X4h, 4096, Msh, Dd, S->U1, Dd, S->CW, nullptr, U1h, Nn, Dd, Dd),
            mkdesc(X4h + 1024, 4096, Msh, Dd, S->U2, Dd, S->GW, nullptr, U2h, Nn, Dd, Dd),
            mkdesc(T1h, Dd, Wrrh, Dd, S->Kq, Dd, nullptr, nullptr, Kqh, Dd, Dd, Dd, 0.5f),
            mkdesc(X4h, 4096, T1h, Dd, S->V1, Dd, S->V1, nullptr, nullptr, Nn, Dd, Dd),
            mkdesc(X4h + 1024, 4096, T1h, Dd, S->V2, Dd, S->V2, nullptr, nullptr, Nn, Dd, Dd)
        };
        launch_batch(ds, 5);
    }
    rowdots<<<Nn, 256>>>(S->S1, S->S2);

    // B4: quad GEMM (xh @ Kq, symmetric-quad epilogue), Pb=U1@B'^T, Pc=A@GW^T
    {
        GemmDesc ds[3];
        ds[0] = mkdesc(rvfh, Dd, Kqh, Dd, nullptr, Dd, nullptr, nullptr,
                       nullptr, E, Dd, Dd);
        ds[0].emit = 0;
        ds[0].xptr = rvf; ds[0].sbjp = sbj; ds[0].objp = obj;
        ds[0].v1p = S->V1; ds[0].v2p = S->V2; ds[0].qp = S->quadP;
        ds[1] = mkdesc(U1h, Dd, X4h + 1024, 4096, S->Pb, Nn, nullptr, nullptr, nullptr, Nn, Nn, Dd);
        ds[2] = mkdesc(X4h, 4096, GWh, Dd, S->Pc, Nn, nullptr, nullptr, nullptr, Nn, Nn, Dd);
        launch_batch(ds, 3);
    }

    // logits, softmax stats, mixing matrix
    logitsk<<<(E + 255) / 256, 256>>>(sbj, obj, E, Nn, 1.0f / sqrtf((float)Dd));
    segstats<<<Nn, 256>>>(sbj, obj, E);
    wmatk<<<(E + 255) / 256, 256>>>(sbj, obj, E, Nn);
    tohalfk<<<256, 256>>>(S->Wmat, Wmh, (long long)Nn * Nn);

    // B5: ctxW = Wmat @ VWT^T + bctx, fused final-mask epilogue -> out
    {
        GemmDesc d = mkdesc(Wmh, Nn, VWTh, Nn, out + (size_t)E * Dd, Dd,
                            nullptr, bctx, nullptr, Nn, Dd, Nn);
        d.emit = 3;
        d.xptr = vf; d.v1p = S->sums; d.v2p = S->sumo;
        launch_batch(&d, 1);
    }
}